// round 5
// baseline (speedup 1.0000x reference)
#include <cuda_runtime.h>
#include <cuda_fp16.h>
#include <math.h>
#include <stdint.h>

// ---------------- model constants ----------------
#define BV   32000
#define DD   1024
#define DFF  4096
#define LT   2
#define HT   16
#define CC   4
#define DC   256
#define DFFC 1024
#define LC   4
#define HC   4
#define NM   2
#define BB   2
#define TT   1024
#define BT   (BB*TT)     // 2048
#define CBT  (CC*BT)     // 8192

// ---------------- weight offsets ([N][K] fp16; QKV interleaved per layer) ----------------
constexpr long OT_QKV = 0;
constexpr long OT_WO  = OT_QKV + (long)LT*3*DD*DD;
constexpr long OT_W1  = OT_WO  + (long)LT*DD*DD;
constexpr long OT_W2  = OT_W1  + (long)LT*DD*DFF;
constexpr long OC_IN  = OT_W2  + (long)LT*DFF*DD;
constexpr long OC_QKV = OC_IN  + (long)CC*DD*DC;
constexpr long OC_WO  = OC_QKV + (long)CC*LC*3*DC*DC;
constexpr long OC_W1  = OC_WO  + (long)CC*LC*DC*DC;
constexpr long OC_W2  = OC_W1  + (long)CC*LC*DC*DFFC;
constexpr long OM_QKV = OC_W2  + (long)CC*LC*DFFC*DC;
constexpr long OM_WO  = OM_QKV + (long)NM*3*DC*DC;
constexpr long O_OP   = OM_WO  + (long)NM*DC*DC;
constexpr long O_EMB  = O_OP   + (long)DD*DD;
constexpr long WTOT   = O_EMB  + (long)BV*DD;

// ---------------- scratch (device globals) ----------------
__device__ float  g_X [BT*DD];
__device__ float  g_Q [BT*DD];
__device__ float  g_CS[CC*BT*DC];
__device__ __half g_Hh[BT*DD];
__device__ __half g_Hl[BT*DD];
__device__ __half g_M1h[BT*DFF];
__device__ __half g_M1l[BT*DFF];
__device__ __half g_Oh[BT*DD];
__device__ __half g_Ol[BT*DD];
__device__ __half g_QKVh[BT*3*DD];
__device__ __half g_QKVl[BT*3*DD];
__device__ __half g_Wh[WTOT];
__device__ __half g_Wl[WTOT];

// ---------------- asm helpers ----------------
__device__ __forceinline__ void lm4(const __half* p, uint32_t* r)
{
    uint32_t a = (uint32_t)__cvta_generic_to_shared(p);
    asm volatile("ldmatrix.sync.aligned.m8n8.x4.shared.b16 {%0,%1,%2,%3}, [%4];"
        : "=r"(r[0]), "=r"(r[1]), "=r"(r[2]), "=r"(r[3]) : "r"(a));
}
__device__ __forceinline__ void lm4t(const __half* p, uint32_t* r)
{
    uint32_t a = (uint32_t)__cvta_generic_to_shared(p);
    asm volatile("ldmatrix.sync.aligned.m8n8.x4.trans.shared.b16 {%0,%1,%2,%3}, [%4];"
        : "=r"(r[0]), "=r"(r[1]), "=r"(r[2]), "=r"(r[3]) : "r"(a));
}
__device__ __forceinline__ void mma16816(float* c, const uint32_t* a, const uint32_t* b)
{
    asm volatile("mma.sync.aligned.m16n8k16.row.col.f32.f16.f16.f32 "
        "{%0,%1,%2,%3},{%4,%5,%6,%7},{%8,%9},{%0,%1,%2,%3};"
        : "+f"(c[0]), "+f"(c[1]), "+f"(c[2]), "+f"(c[3])
        : "r"(a[0]), "r"(a[1]), "r"(a[2]), "r"(a[3]), "r"(b[0]), "r"(b[1]));
}
__device__ __forceinline__ void cpasync16(const __half* dst, const __half* src)
{
    uint32_t d = (uint32_t)__cvta_generic_to_shared(dst);
    asm volatile("cp.async.cg.shared.global [%0], [%1], 16;" :: "r"(d), "l"(src));
}
__device__ __forceinline__ void cp_commit() { asm volatile("cp.async.commit_group;"); }
template<int N> __device__ __forceinline__ void cp_wait()
{ asm volatile("cp.async.wait_group %0;" :: "n"(N)); }

__device__ __forceinline__ float gelu1(float v)
{
    return 0.5f * v * (1.f + tanhf(0.7978845608028654f * (v + 0.044715f*v*v*v)));
}
__device__ __forceinline__ void split_store(__half* oh, __half* ol, long idx, float v)
{
    __half h = __float2half(v);
    oh[idx] = h;
    ol[idx] = __float2half(v - __half2float(h));
}
__device__ __forceinline__ float rec2(__half h, __half l)
{
    return __half2float(h) + __half2float(l);
}

// ---------------- HGEMM (cp.async double-buffered, R3 mainloop) ----------------
// A: [M][K] rm, B: [N][K] rm.  NT=2: hi/lo split, NT=1: plain.
// MODE 0: C fp32 (+accum)   MODE 1: split hi/lo out   MODE 2: gelu + split out
#define BM 128
#define BN 128
#define BKH 32
#define SSTR 40
#define GPER (BM*SSTR)

template<int NT, int MODE>
__global__ void __launch_bounds__(256) hgemm_kernel(
    const __half* __restrict__ Ah, const __half* __restrict__ Al,
    const __half* __restrict__ Bh, const __half* __restrict__ Bl,
    const float* __restrict__ bias, float* __restrict__ C,
    __half* __restrict__ Coh, __half* __restrict__ Col,
    int M, int N, int K, int accum,
    long aBS, long bBS, long cBS, long biasBS)
{
    extern __shared__ __half smp[];
    const int NARR = (NT == 2) ? 4 : 2;

    Ah += blockIdx.z * aBS;
    Bh += blockIdx.z * bBS;
    if (MODE == 0) C += blockIdx.z * cBS;
    else { Coh += blockIdx.z * cBS; Col += blockIdx.z * cBS; }
    if (NT == 2) { Al += blockIdx.z * aBS; Bl += blockIdx.z * bBS; }
    if (bias) bias += blockIdx.z * biasBS;

    int row0 = blockIdx.y * BM;
    int col0 = blockIdx.x * BN;
    int tid  = threadIdx.x;
    int lane = tid & 31;
    int wid  = tid >> 5;
    int wm0  = (wid >> 2) * 64;
    int wn0  = (wid & 3) * 32;

    float acc[4][4][4];
#pragma unroll
    for (int mt = 0; mt < 4; mt++)
#pragma unroll
        for (int nt = 0; nt < 4; nt++)
#pragma unroll
            for (int q = 0; q < 4; q++) acc[mt][nt][q] = 0.f;

    int a_r  = lane & 15;
    int a_ko = (lane >> 4) << 3;
    int b_n  = ((lane >> 4) << 3) + (lane & 7);
    int b_ko = ((lane >> 3) & 1) << 3;

    int nk = K / BKH;

    auto loadStage = [&](int st, int k0) {
        __half* dAh = smp + st * NARR * GPER;
        __half* dBh = dAh + GPER;
        __half* dAl = dAh + 2 * GPER;
        __half* dBl = dAh + 3 * GPER;
#pragma unroll
        for (int c = tid; c < 512; c += 256) {
            int r = c >> 2, o = (c & 3) << 3;
            cpasync16(&dAh[r*SSTR + o], &Ah[(long)(row0 + r)*K + k0 + o]);
            cpasync16(&dBh[r*SSTR + o], &Bh[(long)(col0 + r)*K + k0 + o]);
            if (NT == 2) {
                cpasync16(&dAl[r*SSTR + o], &Al[(long)(row0 + r)*K + k0 + o]);
                cpasync16(&dBl[r*SSTR + o], &Bl[(long)(col0 + r)*K + k0 + o]);
            }
        }
    };

    loadStage(0, 0);
    cp_commit();

    for (int kt = 0; kt < nk; kt++) {
        int cur = kt & 1;
        if (kt + 1 < nk) {
            loadStage(cur ^ 1, (kt + 1) * BKH);
            cp_commit();
            cp_wait<1>();
        } else {
            cp_wait<0>();
        }
        __syncthreads();

        const __half* pAh = smp + cur * NARR * GPER;
        const __half* pBh = pAh + GPER;
        const __half* pAl = pAh + 2 * GPER;
        const __half* pBl = pAh + 3 * GPER;

#pragma unroll
        for (int ks = 0; ks < BKH; ks += 16) {
            uint32_t a_hi[4][4], b_hi[2][4];
#pragma unroll
            for (int mt = 0; mt < 4; mt++)
                lm4(&pAh[(wm0 + mt*16 + a_r)*SSTR + ks + a_ko], a_hi[mt]);
#pragma unroll
            for (int np = 0; np < 2; np++)
                lm4(&pBh[(wn0 + np*16 + b_n)*SSTR + ks + b_ko], b_hi[np]);
#pragma unroll
            for (int mt = 0; mt < 4; mt++)
#pragma unroll
                for (int nt = 0; nt < 4; nt++)
                    mma16816(acc[mt][nt], a_hi[mt], &b_hi[nt >> 1][(nt & 1)*2]);

            if (NT == 2) {
                uint32_t b_lo[2][4];
#pragma unroll
                for (int np = 0; np < 2; np++)
                    lm4(&pBl[(wn0 + np*16 + b_n)*SSTR + ks + b_ko], b_lo[np]);
#pragma unroll
                for (int mt = 0; mt < 4; mt++)
#pragma unroll
                    for (int nt = 0; nt < 4; nt++)
                        mma16816(acc[mt][nt], a_hi[mt], &b_lo[nt >> 1][(nt & 1)*2]);
                uint32_t a_lo[4][4];
#pragma unroll
                for (int mt = 0; mt < 4; mt++)
                    lm4(&pAl[(wm0 + mt*16 + a_r)*SSTR + ks + a_ko], a_lo[mt]);
#pragma unroll
                for (int mt = 0; mt < 4; mt++)
#pragma unroll
                    for (int nt = 0; nt < 4; nt++)
                        mma16816(acc[mt][nt], a_lo[mt], &b_hi[nt >> 1][(nt & 1)*2]);
            }
        }
        __syncthreads();
    }

    int g = lane >> 2, t = lane & 3;
#pragma unroll
    for (int mt = 0; mt < 4; mt++) {
#pragma unroll
        for (int nt = 0; nt < 4; nt++) {
            int r1  = row0 + wm0 + mt*16 + g;
            int cix = col0 + wn0 + nt*8 + 2*t;
            float bv0 = 0.f, bv1 = 0.f;
            if (bias) { bv0 = bias[cix]; bv1 = bias[cix + 1]; }
            float v00 = acc[mt][nt][0] + bv0, v01 = acc[mt][nt][1] + bv1;
            float v10 = acc[mt][nt][2] + bv0, v11 = acc[mt][nt][3] + bv1;
            long o0 = (long)r1*N + cix;
            long o1 = (long)(r1 + 8)*N + cix;
            if (MODE == 0) {
                if (accum) {
                    float2 p0 = *(float2*)&C[o0];
                    float2 p1 = *(float2*)&C[o1];
                    v00 += p0.x; v01 += p0.y;
                    v10 += p1.x; v11 += p1.y;
                }
                *(float2*)&C[o0] = make_float2(v00, v01);
                *(float2*)&C[o1] = make_float2(v10, v11);
            } else {
                if (MODE == 2) {
                    v00 = gelu1(v00); v01 = gelu1(v01);
                    v10 = gelu1(v10); v11 = gelu1(v11);
                }
                __half h00 = __float2half(v00), h01 = __float2half(v01);
                __half h10 = __float2half(v10), h11 = __float2half(v11);
                *(__half2*)&Coh[o0] = __halves2half2(h00, h01);
                *(__half2*)&Coh[o1] = __halves2half2(h10, h11);
                *(__half2*)&Col[o0] = __halves2half2(
                    __float2half(v00 - __half2float(h00)),
                    __float2half(v01 - __half2float(h01)));
                *(__half2*)&Col[o1] = __halves2half2(
                    __float2half(v10 - __half2float(h10)),
                    __float2half(v11 - __half2float(h11)));
            }
        }
    }
}

// ---------------- tensor-core flash attention (causal, hd=64) ----------------
#define ASTR 72
#define FATTN_SMEM (6*64*ASTR*2)

__global__ void __launch_bounds__(128) fattn_kernel(
    const __half* __restrict__ Qh, const __half* __restrict__ Ql,
    const __half* __restrict__ Kh, const __half* __restrict__ Kl,
    const __half* __restrict__ Vh, const __half* __restrict__ Vl,
    __half* __restrict__ Oh, __half* __restrict__ Ol,
    int T, int nh, int rstride, long colstride, int orstride, long ocolstride)
{
    extern __shared__ __half sm[];
    __half* sQh = sm;
    __half* sQl = sQh + 64*ASTR;
    __half* sKh = sQl + 64*ASTR;
    __half* sKl = sKh + 64*ASTR;
    __half* sVh = sKl + 64*ASTR;
    __half* sVl = sVh + 64*ASTR;

    int qt = blockIdx.x;
    int b  = blockIdx.y / nh;
    int h  = blockIdx.y % nh;
    long base  = (long)blockIdx.z * colstride + (long)h * 64;
    long obase = (long)blockIdx.z * ocolstride + (long)h * 64;
    int q0  = qt * 64;
    int tid = threadIdx.x;
    int lane = tid & 31;
    int wid  = tid >> 5;
    int wrow = wid * 16;
    int g = lane >> 2, t4 = lane & 3;

#pragma unroll
    for (int c = tid; c < 512; c += 128) {
        int r = c >> 3, o = (c & 7) << 3;
        long src = base + (long)(b*T + q0 + r)*rstride + o;
        *(uint4*)&sQh[r*ASTR + o] = *(const uint4*)&Qh[src];
        *(uint4*)&sQl[r*ASTR + o] = *(const uint4*)&Ql[src];
    }
    __syncthreads();

    int a_r  = lane & 15;
    int a_ko = (lane >> 4) << 3;
    int b_n  = ((lane >> 4) << 3) + (lane & 7);
    int b_ko = ((lane >> 3) & 1) << 3;
    int v_r  = (((lane >> 3) & 1) << 3) + (lane & 7);
    int v_c  = (lane >> 4) << 3;

    uint32_t qfh[4][4], qfl[4][4];
#pragma unroll
    for (int ks = 0; ks < 4; ks++) {
        lm4(&sQh[(wrow + a_r)*ASTR + ks*16 + a_ko], qfh[ks]);
        lm4(&sQl[(wrow + a_r)*ASTR + ks*16 + a_ko], qfl[ks]);
    }

    float mrow[2] = {-1e30f, -1e30f};
    float lrow[2] = {0.f, 0.f};
    float oacc[8][4];
#pragma unroll
    for (int nt = 0; nt < 8; nt++)
#pragma unroll
        for (int e = 0; e < 4; e++) oacc[nt][e] = 0.f;

    for (int kt = 0; kt <= qt; kt++) {
        int k0 = kt * 64;
        __syncthreads();
#pragma unroll
        for (int c = tid; c < 512; c += 128) {
            int r = c >> 3, o = (c & 7) << 3;
            long src = base + (long)(b*T + k0 + r)*rstride + o;
            *(uint4*)&sKh[r*ASTR + o] = *(const uint4*)&Kh[src];
            *(uint4*)&sKl[r*ASTR + o] = *(const uint4*)&Kl[src];
            *(uint4*)&sVh[r*ASTR + o] = *(const uint4*)&Vh[src];
            *(uint4*)&sVl[r*ASTR + o] = *(const uint4*)&Vl[src];
        }
        __syncthreads();

        float S[8][4];
#pragma unroll
        for (int nt = 0; nt < 8; nt++)
#pragma unroll
            for (int e = 0; e < 4; e++) S[nt][e] = 0.f;

#pragma unroll
        for (int ks = 0; ks < 4; ks++) {
            uint32_t bh[4][4], bl[4][4];
#pragma unroll
            for (int np = 0; np < 4; np++) {
                lm4(&sKh[(np*16 + b_n)*ASTR + ks*16 + b_ko], bh[np]);
                lm4(&sKl[(np*16 + b_n)*ASTR + ks*16 + b_ko], bl[np]);
            }
#pragma unroll
            for (int np = 0; np < 4; np++)
#pragma unroll
                for (int j = 0; j < 2; j++) {
                    int nt = np*2 + j;
                    mma16816(S[nt], qfh[ks], &bh[np][j*2]);
                    mma16816(S[nt], qfh[ks], &bl[np][j*2]);
                    mma16816(S[nt], qfl[ks], &bh[np][j*2]);
                }
        }

#pragma unroll
        for (int nt = 0; nt < 8; nt++)
#pragma unroll
            for (int e = 0; e < 4; e++) {
                S[nt][e] *= 0.125f;
                if (kt == qt) {
                    int col = k0 + nt*8 + t4*2 + (e & 1);
                    int row = q0 + wrow + g + ((e >> 1) << 3);
                    if (col > row) S[nt][e] = -1e30f;
                }
            }

        float P[8][4];
#pragma unroll
        for (int r = 0; r < 2; r++) {
            float mx = -1e30f;
#pragma unroll
            for (int nt = 0; nt < 8; nt++) {
                mx = fmaxf(mx, S[nt][2*r + 0]);
                mx = fmaxf(mx, S[nt][2*r + 1]);
            }
            mx = fmaxf(mx, __shfl_xor_sync(0xffffffffu, mx, 1));
            mx = fmaxf(mx, __shfl_xor_sync(0xffffffffu, mx, 2));
            float mnew  = fmaxf(mrow[r], mx);
            float alpha = __expf(mrow[r] - mnew);
            float rsum = 0.f;
#pragma unroll
            for (int nt = 0; nt < 8; nt++) {
                float p0 = __expf(S[nt][2*r + 0] - mnew);
                float p1 = __expf(S[nt][2*r + 1] - mnew);
                P[nt][2*r + 0] = p0; P[nt][2*r + 1] = p1;
                rsum += p0 + p1;
            }
            rsum += __shfl_xor_sync(0xffffffffu, rsum, 1);
            rsum += __shfl_xor_sync(0xffffffffu, rsum, 2);
            lrow[r] = lrow[r]*alpha + rsum;
            mrow[r] = mnew;
#pragma unroll
            for (int nt = 0; nt < 8; nt++) {
                oacc[nt][2*r + 0] *= alpha;
                oacc[nt][2*r + 1] *= alpha;
            }
        }

        uint32_t pah[4][4], pal[4][4];
#pragma unroll
        for (int ks = 0; ks < 4; ks++) {
            int j0 = 2*ks, j1 = 2*ks + 1;
#pragma unroll
            for (int q = 0; q < 4; q++) {
                int jj = (q < 2) ? j0 : j1;
                int e0 = (q & 1) ? 2 : 0;
                float f0 = P[jj][e0], f1 = P[jj][e0 + 1];
                __half h0 = __float2half(f0), h1 = __float2half(f1);
                __half l0 = __float2half(f0 - __half2float(h0));
                __half l1 = __float2half(f1 - __half2float(h1));
                pah[ks][q] = (uint32_t)__half_as_ushort(h0) |
                             ((uint32_t)__half_as_ushort(h1) << 16);
                pal[ks][q] = (uint32_t)__half_as_ushort(l0) |
                             ((uint32_t)__half_as_ushort(l1) << 16);
            }
        }

#pragma unroll
        for (int ks = 0; ks < 4; ks++) {
            uint32_t vh[4][4], vl[4][4];
#pragma unroll
            for (int np = 0; np < 4; np++) {
                lm4t(&sVh[(ks*16 + v_r)*ASTR + np*16 + v_c], vh[np]);
                lm4t(&sVl[(ks*16 + v_r)*ASTR + np*16 + v_c], vl[np]);
            }
#pragma unroll
            for (int np = 0; np < 4; np++)
#pragma unroll
                for (int j = 0; j < 2; j++) {
                    int nt = np*2 + j;
                    mma16816(oacc[nt], pah[ks], &vh[np][j*2]);
                    mma16816(oacc[nt], pah[ks], &vl[np][j*2]);
                    mma16816(oacc[nt], pal[ks], &vh[np][j*2]);
                }
        }
    }

#pragma unroll
    for (int r = 0; r < 2; r++) {
        float inv = 1.f / lrow[r];
        int row = q0 + wrow + g + r*8;
        long ob = obase + (long)(b*T + row)*orstride;
#pragma unroll
        for (int nt = 0; nt < 8; nt++) {
            float v0 = oacc[nt][2*r + 0] * inv;
            float v1 = oacc[nt][2*r + 1] * inv;
            __half h0 = __float2half(v0), h1 = __float2half(v1);
            __half l0 = __float2half(v0 - __half2float(h0));
            __half l1 = __float2half(v1 - __half2float(h1));
            int col = nt*8 + t4*2;
            *(__half2*)&Oh[ob + col] = __halves2half2(h0, h1);
            *(__half2*)&Ol[ob + col] = __halves2half2(l0, l1);
        }
    }
}

// ---------------- weight transpose + fp16 split (up to 4 sources, optional interleave) ----------------
__global__ void splitT4_kernel(const float* p0, const float* p1,
                               const float* p2, const float* p3,
                               __half* __restrict__ oh, __half* __restrict__ ol,
                               int K, int N, int perBatch, int ngroups, int interleave)
{
    __shared__ float tile[32][33];
    const float* ps[4] = {p0, p1, p2, p3};
    int gsel = blockIdx.z / perBatch;
    int bz   = blockIdx.z % perBatch;
    const float* in = ps[gsel] + (long)bz * K * N;
    long ob = (interleave ? (long)(bz*ngroups + gsel) : (long)blockIdx.z) * K * N;
    int n0 = blockIdx.x * 32, k0 = blockIdx.y * 32;
    int tx = threadIdx.x & 31, ty = threadIdx.x >> 5;
#pragma unroll
    for (int j = 0; j < 4; j++) {
        int r = ty*4 + j;
        tile[r][tx] = in[(long)(k0 + r)*N + n0 + tx];
    }
    __syncthreads();
#pragma unroll
    for (int j = 0; j < 4; j++) {
        int nn = ty*4 + j;
        float v = tile[tx][nn];
        __half h = __float2half(v);
        long o = ob + (long)(n0 + nn)*K + k0 + tx;
        oh[o] = h;
        ol[o] = __float2half(v - __half2float(h));
    }
}

__global__ void split1_kernel(const float* __restrict__ in, __half* __restrict__ oh, int n4)
{
    int i = blockIdx.x * blockDim.x + threadIdx.x;
    if (i >= n4) return;
    float4 v = ((const float4*)in)[i];
    oh[4*i + 0] = __float2half(v.x);
    oh[4*i + 1] = __float2half(v.y);
    oh[4*i + 2] = __float2half(v.z);
    oh[4*i + 3] = __float2half(v.w);
}

__global__ void split2_kernel(const float* __restrict__ in, __half* __restrict__ oh,
                              __half* __restrict__ ol, int n4)
{
    int i = blockIdx.x * blockDim.x + threadIdx.x;
    if (i >= n4) return;
    float4 v = ((const float4*)in)[i];
    split_store(oh, ol, 4L*i + 0, v.x);
    split_store(oh, ol, 4L*i + 1, v.y);
    split_store(oh, ol, 4L*i + 2, v.z);
    split_store(oh, ol, 4L*i + 3, v.w);
}

// ---------------- rmsnorm -> fp16 hi/lo ----------------
__global__ void rms_kernel(const float* __restrict__ x, const float* __restrict__ w,
                           __half* __restrict__ oh, __half* __restrict__ ol,
                           int W, int rowsPerChunk, long wStride)
{
    int row = blockIdx.x;
    const float* xr = x + (long)row * W;
    const float* wr = w + (long)(row / rowsPerChunk) * wStride;
    float ss = 0.f;
    for (int i = threadIdx.x; i < W; i += 256) {
        float v = xr[i];
        ss += v * v;
    }
    __shared__ float red[8];
#pragma unroll
    for (int off = 16; off > 0; off >>= 1)
        ss += __shfl_xor_sync(0xffffffffu, ss, off);
    if ((threadIdx.x & 31) == 0) red[threadIdx.x >> 5] = ss;
    __syncthreads();
    float tot = red[0]+red[1]+red[2]+red[3]+red[4]+red[5]+red[6]+red[7];
    float inv = rsqrtf(tot / (float)W + 1e-6f);
    long rb = (long)row * W;
    for (int i = threadIdx.x; i < W; i += 256)
        split_store(oh, ol, rb + i, xr[i] * inv * wr[i]);
}

// ---------------- rope: rotate fp16 hi/lo QKV buffer in place ----------------
__global__ void rope_kernel(__half* __restrict__ bh, __half* __restrict__ bl,
                            int T, int nh, int roww, int koff, int nrows)
{
    int idx = blockIdx.x * blockDim.x + threadIdx.x;
    if (idx >= nrows * nh * 32) return;
    int i   = idx & 31;
    int h   = (idx >> 5) % nh;
    int row = idx / (32 * nh);
    int t   = row % T;
    float inv = __expf(-(float)(2*i) * (1.f/64.f) * 9.210340371976184f);
    float f = (float)t * inv;
    float s, c;
    sincosf(f, &s, &c);
    long bo = (long)row * roww + h*64 + i;
    // Q
    float q1 = rec2(bh[bo], bl[bo]);
    float q2 = rec2(bh[bo + 32], bl[bo + 32]);
    split_store(bh, bl, bo,      q1*c - q2*s);
    split_store(bh, bl, bo + 32, q2*c + q1*s);
    // K
    long ko = bo + koff;
    float k1 = rec2(bh[ko], bl[ko]);
    float k2 = rec2(bh[ko + 32], bl[ko + 32]);
    split_store(bh, bl, ko,      k1*c - k2*s);
    split_store(bh, bl, ko + 32, k2*c + k1*s);
}

// ---------------- embedding gather ----------------
__global__ void embed_kernel(float* __restrict__ X, const float* __restrict__ emb,
                             const int* __restrict__ ids)
{
    int row = blockIdx.x;
    int id  = ids[row];
    const float4* src = (const float4*)(emb + (long)id * DD);
    float4* dst = (float4*)(X + (long)row * DD);
    dst[threadIdx.x] = src[threadIdx.x];
}

// ---------------- cross-column merge attention (reads fp16 hi/lo QKV, width 3*DC) ----------------
__global__ void merge_attn_kernel(const __half* __restrict__ QKVh,
                                  const __half* __restrict__ QKVl,
                                  __half* __restrict__ Oh, __half* __restrict__ Ol)
{
    int gid = blockIdx.x * blockDim.x + threadIdx.x;  // CC*BT*HC
    int h   = gid & 3;
    int row = (gid >> 2) & (BT - 1);
    int i   = gid >> 13;
    if (i >= CC) return;
    const int W = 3*DC;

    long qb = (long)(i*BT + row)*W + h*64;
    float q[64];
#pragma unroll
    for (int t = 0; t < 64; t++) q[t] = rec2(QKVh[qb + t], QKVl[qb + t]);

    float s[CC];
#pragma unroll
    for (int j = 0; j < CC; j++) {
        long kb = (long)(j*BT + row)*W + DC + h*64;
        float acc = 0.f;
#pragma unroll
        for (int t = 0; t < 64; t++)
            acc += q[t] * rec2(QKVh[kb + t], QKVl[kb + t]);
        s[j] = acc * 0.125f;
    }
    float mm = fmaxf(fmaxf(s[0], s[1]), fmaxf(s[2], s[3]));
    float a[CC], sum = 0.f;
#pragma unroll
    for (int j = 0; j < CC; j++) { a[j] = __expf(s[j] - mm); sum += a[j]; }
    float isum = 1.f / sum;
#pragma unroll
    for (int j = 0; j < CC; j++) a[j] *= isum;

    float o[64];
#pragma unroll
    for (int t = 0; t < 64; t++) o[t] = 0.f;
#pragma unroll
    for (int j = 0; j < CC; j++) {
        long vb = (long)(j*BT + row)*W + 2*DC + h*64;
        float aj = a[j];
#pragma unroll
        for (int t = 0; t < 64; t++)
            o[t] = fmaf(aj, rec2(QKVh[vb + t], QKVl[vb + t]), o[t]);
    }
    long ob = (long)(i*BT + row)*DC + h*64;
#pragma unroll
    for (int t = 0; t < 64; t++) split_store(Oh, Ol, ob + t, o[t]);
}

// ---------------- concat ----------------
__global__ void comb_kernel(const float* __restrict__ cs, __half* __restrict__ oh,
                            __half* __restrict__ ol)
{
    int gid = blockIdx.x * blockDim.x + threadIdx.x;
    int d4  = gid & (DD/4 - 1);
    int row = gid / (DD/4);
    int d = d4 * 4;
    int c = d >> 8;
    int e = d & 255;
    float4 v = *(const float4*)(cs + (long)c*BT*DC + (long)row*DC + e);
    split_store(oh, ol, 4L*gid + 0, v.x);
    split_store(oh, ol, 4L*gid + 1, v.y);
    split_store(oh, ol, 4L*gid + 2, v.z);
    split_store(oh, ol, 4L*gid + 3, v.w);
}

// ---------------- host side ----------------
static __half *Wh_p, *Wl_p;
#define HG2_SMEM (2*4*GPER*2)
#define HG1_SMEM (2*2*GPER*2)

static inline void hgemm(int mode, int nt, const __half* Ah, const __half* Al, long boff,
                         float* C, __half* Coh, __half* Col,
                         int M, int N, int K, int accum, const float* bias, int batch,
                         long aBS, long bBS, long cBS, long biasBS)
{
    dim3 grid(N/BN, M/BM, batch);
    if (nt == 2) {
        if (mode == 0)
            hgemm_kernel<2,0><<<grid, 256, HG2_SMEM>>>(Ah, Al, Wh_p + boff, Wl_p + boff,
                bias, C, nullptr, nullptr, M, N, K, accum, aBS, bBS, cBS, biasBS);
        else if (mode == 1)
            hgemm_kernel<2,1><<<grid, 256, HG2_SMEM>>>(Ah, Al, Wh_p + boff, Wl_p + boff,
                bias, nullptr, Coh, Col, M, N, K, accum, aBS, bBS, cBS, biasBS);
        else
            hgemm_kernel<2,2><<<grid, 256, HG2_SMEM>>>(Ah, Al, Wh_p + boff, Wl_p + boff,
                bias, nullptr, Coh, Col, M, N, K, accum, aBS, bBS, cBS, biasBS);
    } else {
        hgemm_kernel<1,0><<<grid, 256, HG1_SMEM>>>(Ah, nullptr, Wh_p + boff, nullptr,
            bias, C, nullptr, nullptr, M, N, K, accum, aBS, bBS, cBS, biasBS);
    }
}

static inline void splitT4(const float* a, const float* b, const float* c, const float* d,
                           long off, int K, int N, int perBatch, int ngroups, int interleave)
{
    splitT4_kernel<<<dim3(N/32, K/32, ngroups*perBatch), 256>>>(
        a, b, c, d, Wh_p + off, Wl_p + off, K, N, perBatch, ngroups, interleave);
}

extern "C" void kernel_launch(void* const* d_in, const int* in_sizes, int n_in,
                              void* d_out, int out_size)
{
    const int*   ids   = (const int*)d_in[0];
    const float* emb   = (const float*)d_in[1];
    const float* t_wq  = (const float*)d_in[2];
    const float* t_wk  = (const float*)d_in[3];
    const float* t_wv  = (const float*)d_in[4];
    const float* t_wo  = (const float*)d_in[5];
    const float* t_w1  = (const float*)d_in[6];
    const float* t_w2  = (const float*)d_in[7];
    const float* t_n1  = (const float*)d_in[8];
    const float* t_n2  = (const float*)d_in[9];
    const float* cin_w = (const float*)d_in[10];
    const float* cin_b = (const float*)d_in[11];
    const float* c_wq  = (const float*)d_in[12];
    const float* c_wk  = (const float*)d_in[13];
    const float* c_wv  = (const float*)d_in[14];
    const float* c_wo  = (const float*)d_in[15];
    const float* c_w1  = (const float*)d_in[16];
    const float* c_w2  = (const float*)d_in[17];
    const float* c_n1  = (const float*)d_in[18];
    const float* c_n2  = (const float*)d_in[19];
    const float* m_wq  = (const float*)d_in[20];
    const float* m_wk  = (const float*)d_in[21];
    const float* m_wv  = (const float*)d_in[22];
    const float* m_wo  = (const float*)d_in[23];
    const float* m_n   = (const float*)d_in[24];
    const float* oproj = (const float*)d_in[25];
    const float* fnorm = (const float*)d_in[26];
    float* out = (float*)d_out;

    void* p;
    cudaGetSymbolAddress(&p, g_X);    float*  X    = (float*)p;
    cudaGetSymbolAddress(&p, g_Q);    float*  Q    = (float*)p;
    cudaGetSymbolAddress(&p, g_CS);   float*  CS   = (float*)p;
    cudaGetSymbolAddress(&p, g_Hh);   __half* Hh   = (__half*)p;
    cudaGetSymbolAddress(&p, g_Hl);   __half* Hl   = (__half*)p;
    cudaGetSymbolAddress(&p, g_M1h);  __half* M1h  = (__half*)p;
    cudaGetSymbolAddress(&p, g_M1l);  __half* M1l  = (__half*)p;
    cudaGetSymbolAddress(&p, g_Oh);   __half* Oh   = (__half*)p;
    cudaGetSymbolAddress(&p, g_Ol);   __half* Ol   = (__half*)p;
    cudaGetSymbolAddress(&p, g_QKVh); __half* QKVh = (__half*)p;
    cudaGetSymbolAddress(&p, g_QKVl); __half* QKVl = (__half*)p;
    cudaGetSymbolAddress(&p, g_Wh);   Wh_p = (__half*)p;
    cudaGetSymbolAddress(&p, g_Wl);   Wl_p = (__half*)p;

    cudaFuncSetAttribute(hgemm_kernel<2,0>, cudaFuncAttributeMaxDynamicSharedMemorySize, HG2_SMEM);
    cudaFuncSetAttribute(hgemm_kernel<2,1>, cudaFuncAttributeMaxDynamicSharedMemorySize, HG2_SMEM);
    cudaFuncSetAttribute(hgemm_kernel<2,2>, cudaFuncAttributeMaxDynamicSharedMemorySize, HG2_SMEM);
    cudaFuncSetAttribute(hgemm_kernel<1,0>, cudaFuncAttributeMaxDynamicSharedMemorySize, HG1_SMEM);
    cudaFuncSetAttribute(fattn_kernel, cudaFuncAttributeMaxDynamicSharedMemorySize, FATTN_SMEM);

    // ---- weight conversion ----
    splitT4(t_wq, t_wk, t_wv, nullptr, OT_QKV, DD, DD, LT, 3, 1);
    splitT4(t_wo, nullptr, nullptr, nullptr, OT_WO, DD, DD, LT, 1, 0);
    splitT4(t_w1, nullptr, nullptr, nullptr, OT_W1, DD, DFF, LT, 1, 0);
    splitT4(t_w2, nullptr, nullptr, nullptr, OT_W2, DFF, DD, LT, 1, 0);
    splitT4(cin_w, nullptr, nullptr, nullptr, OC_IN, DD, DC, CC, 1, 0);
    splitT4(c_wq, c_wk, c_wv, nullptr, OC_QKV, DC, DC, CC*LC, 3, 1);
    splitT4(c_wo, nullptr, nullptr, nullptr, OC_WO, DC, DC, CC*LC, 1, 0);
    splitT4(c_w1, nullptr, nullptr, nullptr, OC_W1, DC, DFFC, CC*LC, 1, 0);
    splitT4(c_w2, nullptr, nullptr, nullptr, OC_W2, DFFC, DC, CC*LC, 1, 0);
    splitT4(m_wq, m_wk, m_wv, nullptr, OM_QKV, DC, DC, NM, 3, 1);
    splitT4(m_wo, nullptr, nullptr, nullptr, OM_WO, DC, DC, NM, 1, 0);
    splitT4(oproj, nullptr, nullptr, nullptr, O_OP, DD, DD, 1, 1, 0);
    split1_kernel<<<(BV*DD/4 + 255)/256, 256>>>(emb, Wh_p + O_EMB, BV*DD/4);

    embed_kernel<<<BT, 256>>>(X, emb, ids);

    // ---- trunk ----
    for (int l = 0; l < LT; l++) {
        rms_kernel<<<BT, 256>>>(X, t_n1 + (long)l*DD, Hh, Hl, DD, BT, 0);
        hgemm(1, 2, Hh, Hl, OT_QKV + (long)l*3*DD*DD, 0, QKVh, QKVl,
              BT, 3*DD, DD, 0, nullptr, 1, 0,0,0,0);
        rope_kernel<<<(BT*HT*32)/256, 256>>>(QKVh, QKVl, TT, HT, 3*DD, DD, BT);
        fattn_kernel<<<dim3(TT/64, BB*HT, 1), 128, FATTN_SMEM>>>(
            QKVh, QKVl, QKVh + DD, QKVl + DD, QKVh + 2*DD, QKVl + 2*DD,
            Oh, Ol, TT, HT, 3*DD, 0, DD, 0);
        hgemm(0, 2, Oh, Ol, OT_WO + (long)l*DD*DD, X, 0, 0, BT, DD, DD, 1, nullptr, 1, 0,0,0,0);
        rms_kernel<<<BT, 256>>>(X, t_n2 + (long)l*DD, Hh, Hl, DD, BT, 0);
        hgemm(2, 2, Hh, Hl, OT_W1 + (long)l*DD*DFF, 0, M1h, M1l, BT, DFF, DD, 0, nullptr, 1, 0,0,0,0);
        hgemm(0, 2, M1h, M1l, OT_W2 + (long)l*DFF*DD, X, 0, 0, BT, DD, DFF, 1, nullptr, 1, 0,0,0,0);
    }

    // ---- column projection ----
    split2_kernel<<<(BT*DD/4)/256, 256>>>(X, Hh, Hl, BT*DD/4);
    hgemm(0, 2, Hh, Hl, OC_IN, CS, 0, 0, BT, DC, DD, 0, cin_b, CC, 0, (long)DD*DC, (long)BT*DC, DC);

    // ---- column layers ----
    for (int l = 0; l < LC; l++) {
        rms_kernel<<<CBT, 256>>>(CS, c_n1 + (long)l*DC, Hh, Hl, DC, BT, (long)LC*DC);
        hgemm(1, 2, Hh, Hl, OC_QKV + (long)l*3*DC*DC, 0, QKVh, QKVl,
              BT, 3*DC, DC, 0, nullptr, CC,
              (long)BT*DC, (long)LC*3*DC*DC, (long)BT*3*DC, 0);
        rope_kernel<<<(CBT*HC*32)/256, 256>>>(QKVh, QKVl, TT, HC, 3*DC, DC, CBT);
        fattn_kernel<<<dim3(TT/64, BB*HC, CC), 128, FATTN_SMEM>>>(
            QKVh, QKVl, QKVh + DC, QKVl + DC, QKVh + 2*DC, QKVl + 2*DC,
            Oh, Ol, TT, HC, 3*DC, (long)BT*3*DC, DC, (long)BT*DC);
        hgemm(0, 2, Oh, Ol, OC_WO + (long)l*DC*DC, CS, 0, 0, BT, DC, DC, 1, nullptr, CC,
              (long)BT*DC, (long)LC*DC*DC, (long)BT*DC, 0);
        rms_kernel<<<CBT, 256>>>(CS, c_n2 + (long)l*DC, Hh, Hl, DC, BT, (long)LC*DC);
        hgemm(2, 2, Hh, Hl, OC_W1 + (long)l*DC*DFFC, 0, M1h, M1l, BT, DFFC, DC, 0, nullptr, CC,
              (long)BT*DC, (long)LC*DC*DFFC, (long)BT*DFFC, 0);
        hgemm(0, 2, M1h, M1l, OC_W2 + (long)l*DFFC*DC, CS, 0, 0, BT, DC, DFFC, 1, nullptr, CC,
              (long)BT*DFFC, (long)LC*DFFC*DC, (long)BT*DC, 0);

        if (((l + 1) & 1) == 0) {
            int m = (l + 1)/2 - 1;
            rms_kernel<<<CBT, 256>>>(CS, m_n + (long)m*DC, Hh, Hl, DC, CBT, 0);
            hgemm(1, 2, Hh, Hl, OM_QKV + (long)m*3*DC*DC, 0, QKVh, QKVl,
                  CBT, 3*DC, DC, 0, nullptr, 1, 0,0,0,0);
            merge_attn_kernel<<<(CC*BT*HC)/256, 256>>>(QKVh, QKVl, Oh, Ol);
            hgemm(0, 2, Oh, Ol, OM_WO + (long)m*DC*DC, CS, 0, 0, CBT, DC, DC, 1, nullptr, 1, 0,0,0,0);
        }
    }

    // ---- output head ----
    comb_kernel<<<(BT*DD/4)/256, 256>>>(CS, Hh, Hl);
    hgemm(0, 2, Hh, Hl, O_OP, Q, 0, 0, BT, DD, DD, 0, nullptr, 1, 0,0,0,0);
    rms_kernel<<<BT, 256>>>(Q, fnorm, Hh, Hl, DD, BT, 0);
    hgemm(0, 1, Hh, nullptr, O_EMB, out, 0, 0, BT, BV, DD, 0, nullptr, 1, 0,0,0,0);
}

// round 6
// speedup vs baseline: 1.0330x; 1.0330x over previous
#include <cuda_runtime.h>
#include <cuda_fp16.h>
#include <math.h>
#include <stdint.h>

// ---------------- model constants ----------------
#define BV   32000
#define DD   1024
#define DFF  4096
#define LT   2
#define HT   16
#define CC   4
#define DC   256
#define DFFC 1024
#define LC   4
#define HC   4
#define NM   2
#define BB   2
#define TT   1024
#define BT   (BB*TT)     // 2048
#define CBT  (CC*BT)     // 8192

// ---------------- weight offsets (transposed [N][K] fp16 store) ----------------
constexpr long OT_WQ = 0;
constexpr long OT_WK = OT_WQ + (long)LT*DD*DD;
constexpr long OT_WV = OT_WK + (long)LT*DD*DD;
constexpr long OT_WO = OT_WV + (long)LT*DD*DD;
constexpr long OT_W1 = OT_WO + (long)LT*DD*DD;
constexpr long OT_W2 = OT_W1 + (long)LT*DD*DFF;
constexpr long OC_IN = OT_W2 + (long)LT*DFF*DD;
constexpr long OC_WQ = OC_IN + (long)CC*DD*DC;
constexpr long OC_WK = OC_WQ + (long)CC*LC*DC*DC;
constexpr long OC_WV = OC_WK + (long)CC*LC*DC*DC;
constexpr long OC_WO = OC_WV + (long)CC*LC*DC*DC;
constexpr long OC_W1 = OC_WO + (long)CC*LC*DC*DC;
constexpr long OC_W2 = OC_W1 + (long)CC*LC*DC*DFFC;
constexpr long OM_WQ = OC_W2 + (long)CC*LC*DFFC*DC;
constexpr long OM_WK = OM_WQ + (long)NM*DC*DC;
constexpr long OM_WV = OM_WK + (long)NM*DC*DC;
constexpr long OM_WO = OM_WV + (long)NM*DC*DC;
constexpr long O_OP  = OM_WO + (long)NM*DC*DC;
constexpr long O_EMB = O_OP  + (long)DD*DD;
constexpr long WTOT  = O_EMB + (long)BV*DD;

// ---------------- scratch (device globals) ----------------
__device__ float  g_X [BT*DD];
__device__ float  g_Q [BT*DD];
__device__ float  g_K [BT*DD];
__device__ float  g_V [BT*DD];
__device__ float  g_M1[BT*DFF];
__device__ float  g_CS[CC*BT*DC];
__device__ __half g_Hh[BT*DD];
__device__ __half g_Hl[BT*DD];
__device__ __half g_M1h[BT*DFF];
__device__ __half g_M1l[BT*DFF];
__device__ __half g_Oh[BT*DD];
__device__ __half g_Ol[BT*DD];
__device__ __half g_Qh[BT*DD];
__device__ __half g_Ql[BT*DD];
__device__ __half g_Kh[BT*DD];
__device__ __half g_Kl[BT*DD];
__device__ __half g_Vh[BT*DD];
__device__ __half g_Vl[BT*DD];
__device__ __half g_Wh[WTOT];
__device__ __half g_Wl[WTOT];

// ---------------- asm helpers ----------------
__device__ __forceinline__ void lm4(const __half* p, uint32_t* r)
{
    uint32_t a = (uint32_t)__cvta_generic_to_shared(p);
    asm volatile("ldmatrix.sync.aligned.m8n8.x4.shared.b16 {%0,%1,%2,%3}, [%4];"
        : "=r"(r[0]), "=r"(r[1]), "=r"(r[2]), "=r"(r[3]) : "r"(a));
}
__device__ __forceinline__ void lm4t(const __half* p, uint32_t* r)
{
    uint32_t a = (uint32_t)__cvta_generic_to_shared(p);
    asm volatile("ldmatrix.sync.aligned.m8n8.x4.trans.shared.b16 {%0,%1,%2,%3}, [%4];"
        : "=r"(r[0]), "=r"(r[1]), "=r"(r[2]), "=r"(r[3]) : "r"(a));
}
// non-volatile: pure register op, original load placement preserved
__device__ __forceinline__ void mma16816(float* c, const uint32_t* a, const uint32_t* b)
{
    asm("mma.sync.aligned.m16n8k16.row.col.f32.f16.f16.f32 "
        "{%0,%1,%2,%3},{%4,%5,%6,%7},{%8,%9},{%0,%1,%2,%3};"
        : "+f"(c[0]), "+f"(c[1]), "+f"(c[2]), "+f"(c[3])
        : "r"(a[0]), "r"(a[1]), "r"(a[2]), "r"(a[3]), "r"(b[0]), "r"(b[1]));
}
__device__ __forceinline__ void cpasync16(const __half* dst, const __half* src)
{
    uint32_t d = (uint32_t)__cvta_generic_to_shared(dst);
    asm volatile("cp.async.cg.shared.global [%0], [%1], 16;" :: "r"(d), "l"(src));
}
__device__ __forceinline__ void cp_commit() { asm volatile("cp.async.commit_group;"); }
template<int N> __device__ __forceinline__ void cp_wait()
{ asm volatile("cp.async.wait_group %0;" :: "n"(N)); }

__device__ __forceinline__ float gelu1(float v)
{
    return 0.5f * v * (1.f + tanhf(0.7978845608028654f * (v + 0.044715f*v*v*v)));
}
__device__ __forceinline__ void split_store(__half* oh, __half* ol, long idx, float v)
{
    __half h = __float2half(v);
    oh[idx] = h;
    ol[idx] = __float2half(v - __half2float(h));
}

// ---------------- HGEMM (cp.async double-buffered) ----------------
// A: [M][K] rm, B: [N][K] rm, C: [M][N] fp32.  NT=2: hi/lo split, NT=1: plain.
#define BM 128
#define BN 128
#define BKH 32
#define SSTR 40
#define GPER (BM*SSTR)

template<int NT>
__global__ void __launch_bounds__(256) hgemm_kernel(
    const __half* __restrict__ Ah, const __half* __restrict__ Al,
    const __half* __restrict__ Bh, const __half* __restrict__ Bl,
    const float* __restrict__ bias, float* __restrict__ C,
    int M, int N, int K, int accum,
    long aBS, long bBS, long cBS, long biasBS)
{
    extern __shared__ __half smp[];
    const int NARR = (NT == 2) ? 4 : 2;

    Ah += blockIdx.z * aBS;
    Bh += blockIdx.z * bBS;
    C  += blockIdx.z * cBS;
    if (NT == 2) { Al += blockIdx.z * aBS; Bl += blockIdx.z * bBS; }
    if (bias) bias += blockIdx.z * biasBS;

    int row0 = blockIdx.y * BM;
    int col0 = blockIdx.x * BN;
    int tid  = threadIdx.x;
    int lane = tid & 31;
    int wid  = tid >> 5;
    int wm0  = (wid >> 2) * 64;
    int wn0  = (wid & 3) * 32;

    float acc[4][4][4];
#pragma unroll
    for (int mt = 0; mt < 4; mt++)
#pragma unroll
        for (int nt = 0; nt < 4; nt++)
#pragma unroll
            for (int q = 0; q < 4; q++) acc[mt][nt][q] = 0.f;

    int a_r  = lane & 15;
    int a_ko = (lane >> 4) << 3;
    int b_n  = ((lane >> 4) << 3) + (lane & 7);
    int b_ko = ((lane >> 3) & 1) << 3;

    int nk = K / BKH;

    auto loadStage = [&](int st, int k0) {
        __half* dAh = smp + st * NARR * GPER;
        __half* dBh = dAh + GPER;
        __half* dAl = dAh + 2 * GPER;
        __half* dBl = dAh + 3 * GPER;
#pragma unroll
        for (int c = tid; c < 512; c += 256) {
            int r = c >> 2, o = (c & 3) << 3;
            cpasync16(&dAh[r*SSTR + o], &Ah[(long)(row0 + r)*K + k0 + o]);
            cpasync16(&dBh[r*SSTR + o], &Bh[(long)(col0 + r)*K + k0 + o]);
            if (NT == 2) {
                cpasync16(&dAl[r*SSTR + o], &Al[(long)(row0 + r)*K + k0 + o]);
                cpasync16(&dBl[r*SSTR + o], &Bl[(long)(col0 + r)*K + k0 + o]);
            }
        }
    };

    loadStage(0, 0);
    cp_commit();

    for (int kt = 0; kt < nk; kt++) {
        int cur = kt & 1;
        if (kt + 1 < nk) {
            loadStage(cur ^ 1, (kt + 1) * BKH);
            cp_commit();
            cp_wait<1>();
        } else {
            cp_wait<0>();
        }
        __syncthreads();

        const __half* pAh = smp + cur * NARR * GPER;
        const __half* pBh = pAh + GPER;
        const __half* pAl = pAh + 2 * GPER;
        const __half* pBl = pAh + 3 * GPER;

#pragma unroll
        for (int ks = 0; ks < BKH; ks += 16) {
            uint32_t a_hi[4][4], b_hi[2][4];
#pragma unroll
            for (int mt = 0; mt < 4; mt++)
                lm4(&pAh[(wm0 + mt*16 + a_r)*SSTR + ks + a_ko], a_hi[mt]);
#pragma unroll
            for (int np = 0; np < 2; np++)
                lm4(&pBh[(wn0 + np*16 + b_n)*SSTR + ks + b_ko], b_hi[np]);
#pragma unroll
            for (int mt = 0; mt < 4; mt++)
#pragma unroll
                for (int nt = 0; nt < 4; nt++)
                    mma16816(acc[mt][nt], a_hi[mt], &b_hi[nt >> 1][(nt & 1)*2]);

            if (NT == 2) {
                uint32_t b_lo[2][4];
#pragma unroll
                for (int np = 0; np < 2; np++)
                    lm4(&pBl[(wn0 + np*16 + b_n)*SSTR + ks + b_ko], b_lo[np]);
#pragma unroll
                for (int mt = 0; mt < 4; mt++)
#pragma unroll
                    for (int nt = 0; nt < 4; nt++)
                        mma16816(acc[mt][nt], a_hi[mt], &b_lo[nt >> 1][(nt & 1)*2]);
                uint32_t a_lo[4][4];
#pragma unroll
                for (int mt = 0; mt < 4; mt++)
                    lm4(&pAl[(wm0 + mt*16 + a_r)*SSTR + ks + a_ko], a_lo[mt]);
#pragma unroll
                for (int mt = 0; mt < 4; mt++)
#pragma unroll
                    for (int nt = 0; nt < 4; nt++)
                        mma16816(acc[mt][nt], a_lo[mt], &b_hi[nt >> 1][(nt & 1)*2]);
            }
        }
        __syncthreads();
    }

    int g = lane >> 2, t = lane & 3;
#pragma unroll
    for (int mt = 0; mt < 4; mt++) {
#pragma unroll
        for (int nt = 0; nt < 4; nt++) {
            int r1  = row0 + wm0 + mt*16 + g;
            int cix = col0 + wn0 + nt*8 + 2*t;
            float bv0 = 0.f, bv1 = 0.f;
            if (bias) { bv0 = bias[cix]; bv1 = bias[cix + 1]; }
            float2 v0 = make_float2(acc[mt][nt][0] + bv0, acc[mt][nt][1] + bv1);
            float2 v1 = make_float2(acc[mt][nt][2] + bv0, acc[mt][nt][3] + bv1);
            long o0 = (long)r1*N + cix;
            long o1 = (long)(r1 + 8)*N + cix;
            if (accum) {
                float2 p0 = *(float2*)&C[o0];
                float2 p1 = *(float2*)&C[o1];
                v0.x += p0.x; v0.y += p0.y;
                v1.x += p1.x; v1.y += p1.y;
            }
            *(float2*)&C[o0] = v0;
            *(float2*)&C[o1] = v1;
        }
    }
}

// ---------------- tensor-core flash attention (causal, hd=64) ----------------
#define ASTR 72
#define FATTN_SMEM (6*64*ASTR*2)

__global__ void __launch_bounds__(128) fattn_kernel(
    const __half* __restrict__ Qh, const __half* __restrict__ Ql,
    const __half* __restrict__ Kh, const __half* __restrict__ Kl,
    const __half* __restrict__ Vh, const __half* __restrict__ Vl,
    __half* __restrict__ Oh, __half* __restrict__ Ol,
    int T, int nh, int rstride, long colstride)
{
    extern __shared__ __half sm[];
    __half* sQh = sm;
    __half* sQl = sQh + 64*ASTR;
    __half* sKh = sQl + 64*ASTR;
    __half* sKl = sKh + 64*ASTR;
    __half* sVh = sKl + 64*ASTR;
    __half* sVl = sVh + 64*ASTR;

    int qt = blockIdx.x;
    int b  = blockIdx.y / nh;
    int h  = blockIdx.y % nh;
    long base = (long)blockIdx.z * colstride + (long)h * 64;
    int q0  = qt * 64;
    int tid = threadIdx.x;
    int lane = tid & 31;
    int wid  = tid >> 5;
    int wrow = wid * 16;
    int g = lane >> 2, t4 = lane & 3;

#pragma unroll
    for (int c = tid; c < 512; c += 128) {
        int r = c >> 3, o = (c & 7) << 3;
        long src = base + (long)(b*T + q0 + r)*rstride + o;
        *(uint4*)&sQh[r*ASTR + o] = *(const uint4*)&Qh[src];
        *(uint4*)&sQl[r*ASTR + o] = *(const uint4*)&Ql[src];
    }
    __syncthreads();

    int a_r  = lane & 15;
    int a_ko = (lane >> 4) << 3;
    int b_n  = ((lane >> 4) << 3) + (lane & 7);
    int b_ko = ((lane >> 3) & 1) << 3;
    int v_r  = (((lane >> 3) & 1) << 3) + (lane & 7);
    int v_c  = (lane >> 4) << 3;

    uint32_t qfh[4][4], qfl[4][4];
#pragma unroll
    for (int ks = 0; ks < 4; ks++) {
        lm4(&sQh[(wrow + a_r)*ASTR + ks*16 + a_ko], qfh[ks]);
        lm4(&sQl[(wrow + a_r)*ASTR + ks*16 + a_ko], qfl[ks]);
    }

    float mrow[2] = {-1e30f, -1e30f};
    float lrow[2] = {0.f, 0.f};
    float oacc[8][4];
#pragma unroll
    for (int nt = 0; nt < 8; nt++)
#pragma unroll
        for (int e = 0; e < 4; e++) oacc[nt][e] = 0.f;

    for (int kt = 0; kt <= qt; kt++) {
        int k0 = kt * 64;
        __syncthreads();
#pragma unroll
        for (int c = tid; c < 512; c += 128) {
            int r = c >> 3, o = (c & 7) << 3;
            long src = base + (long)(b*T + k0 + r)*rstride + o;
            *(uint4*)&sKh[r*ASTR + o] = *(const uint4*)&Kh[src];
            *(uint4*)&sKl[r*ASTR + o] = *(const uint4*)&Kl[src];
            *(uint4*)&sVh[r*ASTR + o] = *(const uint4*)&Vh[src];
            *(uint4*)&sVl[r*ASTR + o] = *(const uint4*)&Vl[src];
        }
        __syncthreads();

        float S[8][4];
#pragma unroll
        for (int nt = 0; nt < 8; nt++)
#pragma unroll
            for (int e = 0; e < 4; e++) S[nt][e] = 0.f;

#pragma unroll
        for (int ks = 0; ks < 4; ks++) {
            uint32_t bh[4][4], bl[4][4];
#pragma unroll
            for (int np = 0; np < 4; np++) {
                lm4(&sKh[(np*16 + b_n)*ASTR + ks*16 + b_ko], bh[np]);
                lm4(&sKl[(np*16 + b_n)*ASTR + ks*16 + b_ko], bl[np]);
            }
#pragma unroll
            for (int np = 0; np < 4; np++)
#pragma unroll
                for (int j = 0; j < 2; j++) {
                    int nt = np*2 + j;
                    mma16816(S[nt], qfh[ks], &bh[np][j*2]);
                    mma16816(S[nt], qfh[ks], &bl[np][j*2]);
                    mma16816(S[nt], qfl[ks], &bh[np][j*2]);
                }
        }

#pragma unroll
        for (int nt = 0; nt < 8; nt++)
#pragma unroll
            for (int e = 0; e < 4; e++) {
                S[nt][e] *= 0.125f;
                if (kt == qt) {
                    int col = k0 + nt*8 + t4*2 + (e & 1);
                    int row = q0 + wrow + g + ((e >> 1) << 3);
                    if (col > row) S[nt][e] = -1e30f;
                }
            }

        float P[8][4];
#pragma unroll
        for (int r = 0; r < 2; r++) {
            float mx = -1e30f;
#pragma unroll
            for (int nt = 0; nt < 8; nt++) {
                mx = fmaxf(mx, S[nt][2*r + 0]);
                mx = fmaxf(mx, S[nt][2*r + 1]);
            }
            mx = fmaxf(mx, __shfl_xor_sync(0xffffffffu, mx, 1));
            mx = fmaxf(mx, __shfl_xor_sync(0xffffffffu, mx, 2));
            float mnew  = fmaxf(mrow[r], mx);
            float alpha = __expf(mrow[r] - mnew);
            float rsum = 0.f;
#pragma unroll
            for (int nt = 0; nt < 8; nt++) {
                float p0 = __expf(S[nt][2*r + 0] - mnew);
                float p1 = __expf(S[nt][2*r + 1] - mnew);
                P[nt][2*r + 0] = p0; P[nt][2*r + 1] = p1;
                rsum += p0 + p1;
            }
            rsum += __shfl_xor_sync(0xffffffffu, rsum, 1);
            rsum += __shfl_xor_sync(0xffffffffu, rsum, 2);
            lrow[r] = lrow[r]*alpha + rsum;
            mrow[r] = mnew;
#pragma unroll
            for (int nt = 0; nt < 8; nt++) {
                oacc[nt][2*r + 0] *= alpha;
                oacc[nt][2*r + 1] *= alpha;
            }
        }

        uint32_t pah[4][4], pal[4][4];
#pragma unroll
        for (int ks = 0; ks < 4; ks++) {
            int j0 = 2*ks, j1 = 2*ks + 1;
#pragma unroll
            for (int q = 0; q < 4; q++) {
                int jj = (q < 2) ? j0 : j1;
                int e0 = (q & 1) ? 2 : 0;
                float f0 = P[jj][e0], f1 = P[jj][e0 + 1];
                __half h0 = __float2half(f0), h1 = __float2half(f1);
                __half l0 = __float2half(f0 - __half2float(h0));
                __half l1 = __float2half(f1 - __half2float(h1));
                pah[ks][q] = (uint32_t)__half_as_ushort(h0) |
                             ((uint32_t)__half_as_ushort(h1) << 16);
                pal[ks][q] = (uint32_t)__half_as_ushort(l0) |
                             ((uint32_t)__half_as_ushort(l1) << 16);
            }
        }

#pragma unroll
        for (int ks = 0; ks < 4; ks++) {
            uint32_t vh[4][4], vl[4][4];
#pragma unroll
            for (int np = 0; np < 4; np++) {
                lm4t(&sVh[(ks*16 + v_r)*ASTR + np*16 + v_c], vh[np]);
                lm4t(&sVl[(ks*16 + v_r)*ASTR + np*16 + v_c], vl[np]);
            }
#pragma unroll
            for (int np = 0; np < 4; np++)
#pragma unroll
                for (int j = 0; j < 2; j++) {
                    int nt = np*2 + j;
                    mma16816(oacc[nt], pah[ks], &vh[np][j*2]);
                    mma16816(oacc[nt], pah[ks], &vl[np][j*2]);
                    mma16816(oacc[nt], pal[ks], &vh[np][j*2]);
                }
        }
    }

#pragma unroll
    for (int r = 0; r < 2; r++) {
        float inv = 1.f / lrow[r];
        int row = q0 + wrow + g + r*8;
        long ob = base + (long)(b*T + row)*rstride;
#pragma unroll
        for (int nt = 0; nt < 8; nt++) {
            float v0 = oacc[nt][2*r + 0] * inv;
            float v1 = oacc[nt][2*r + 1] * inv;
            __half h0 = __float2half(v0), h1 = __float2half(v1);
            __half l0 = __float2half(v0 - __half2float(h0));
            __half l1 = __float2half(v1 - __half2float(h1));
            int col = nt*8 + t4*2;
            *(__half2*)&Oh[ob + col] = __halves2half2(h0, h1);
            *(__half2*)&Ol[ob + col] = __halves2half2(l0, l1);
        }
    }
}

// ---------------- weight transpose + fp16 split (up to 4 sources per launch) ----------------
__global__ void splitT4_kernel(const float* p0, const float* p1,
                               const float* p2, const float* p3,
                               __half* __restrict__ oh, __half* __restrict__ ol,
                               int K, int N, int perBatch)
{
    __shared__ float tile[32][33];
    const float* ps[4] = {p0, p1, p2, p3};
    int gsel = blockIdx.z / perBatch;
    int bz   = blockIdx.z % perBatch;
    const float* in = ps[gsel] + (long)bz * K * N;
    long ob = (long)blockIdx.z * K * N;
    int n0 = blockIdx.x * 32, k0 = blockIdx.y * 32;
    int tx = threadIdx.x & 31, ty = threadIdx.x >> 5;
#pragma unroll
    for (int j = 0; j < 4; j++) {
        int r = ty*4 + j;
        tile[r][tx] = in[(long)(k0 + r)*N + n0 + tx];
    }
    __syncthreads();
#pragma unroll
    for (int j = 0; j < 4; j++) {
        int nn = ty*4 + j;
        float v = tile[tx][nn];
        __half h = __float2half(v);
        long o = ob + (long)(n0 + nn)*K + k0 + tx;
        oh[o] = h;
        ol[o] = __float2half(v - __half2float(h));
    }
}

__global__ void split1_kernel(const float* __restrict__ in, __half* __restrict__ oh, int n4)
{
    int i = blockIdx.x * blockDim.x + threadIdx.x;
    if (i >= n4) return;
    float4 v = ((const float4*)in)[i];
    oh[4*i + 0] = __float2half(v.x);
    oh[4*i + 1] = __float2half(v.y);
    oh[4*i + 2] = __float2half(v.z);
    oh[4*i + 3] = __float2half(v.w);
}

__global__ void split2_kernel(const float* __restrict__ in, __half* __restrict__ oh,
                              __half* __restrict__ ol, int n4)
{
    int i = blockIdx.x * blockDim.x + threadIdx.x;
    if (i >= n4) return;
    float4 v = ((const float4*)in)[i];
    split_store(oh, ol, 4L*i + 0, v.x);
    split_store(oh, ol, 4L*i + 1, v.y);
    split_store(oh, ol, 4L*i + 2, v.z);
    split_store(oh, ol, 4L*i + 3, v.w);
}

// ---------------- rmsnorm -> fp16 hi/lo ----------------
__global__ void rms_kernel(const float* __restrict__ x, const float* __restrict__ w,
                           __half* __restrict__ oh, __half* __restrict__ ol,
                           int W, int rowsPerChunk, long wStride)
{
    int row = blockIdx.x;
    const float* xr = x + (long)row * W;
    const float* wr = w + (long)(row / rowsPerChunk) * wStride;
    float ss = 0.f;
    for (int i = threadIdx.x; i < W; i += 256) {
        float v = xr[i];
        ss += v * v;
    }
    __shared__ float red[8];
#pragma unroll
    for (int off = 16; off > 0; off >>= 1)
        ss += __shfl_xor_sync(0xffffffffu, ss, off);
    if ((threadIdx.x & 31) == 0) red[threadIdx.x >> 5] = ss;
    __syncthreads();
    float tot = red[0]+red[1]+red[2]+red[3]+red[4]+red[5]+red[6]+red[7];
    float inv = rsqrtf(tot / (float)W + 1e-6f);
    long rb = (long)row * W;
    for (int i = threadIdx.x; i < W; i += 256)
        split_store(oh, ol, rb + i, xr[i] * inv * wr[i]);
}

// ---------------- rope: fp32 q,k -> rotated fp16 hi/lo ----------------
__global__ void rope_kernel(const float* __restrict__ q, const float* __restrict__ k,
                            __half* __restrict__ qh, __half* __restrict__ ql,
                            __half* __restrict__ kh, __half* __restrict__ kl,
                            int T, int nh, int rstride, int nrows)
{
    int idx = blockIdx.x * blockDim.x + threadIdx.x;
    if (idx >= nrows * nh * 32) return;
    int i   = idx & 31;
    int h   = (idx >> 5) % nh;
    int row = idx / (32 * nh);
    int t   = row % T;
    float inv = __expf(-(float)(2*i) * (1.f/64.f) * 9.210340371976184f);
    float f = (float)t * inv;
    float s, c;
    sincosf(f, &s, &c);
    long bo = (long)row * rstride + h*64 + i;
    float q1 = q[bo], q2 = q[bo + 32];
    split_store(qh, ql, bo,      q1*c - q2*s);
    split_store(qh, ql, bo + 32, q2*c + q1*s);
    float k1 = k[bo], k2 = k[bo + 32];
    split_store(kh, kl, bo,      k1*c - k2*s);
    split_store(kh, kl, bo + 32, k2*c + k1*s);
}

// ---------------- gelu ----------------
__global__ void gelu_kernel(const float* __restrict__ x, __half* __restrict__ oh,
                            __half* __restrict__ ol, int n4)
{
    int i = blockIdx.x * blockDim.x + threadIdx.x;
    if (i >= n4) return;
    float4 v = ((const float4*)x)[i];
    split_store(oh, ol, 4L*i + 0, gelu1(v.x));
    split_store(oh, ol, 4L*i + 1, gelu1(v.y));
    split_store(oh, ol, 4L*i + 2, gelu1(v.z));
    split_store(oh, ol, 4L*i + 3, gelu1(v.w));
}

// ---------------- embedding gather ----------------
__global__ void embed_kernel(float* __restrict__ X, const float* __restrict__ emb,
                             const int* __restrict__ ids)
{
    int row = blockIdx.x;
    int id  = ids[row];
    const float4* src = (const float4*)(emb + (long)id * DD);
    float4* dst = (float4*)(X + (long)row * DD);
    dst[threadIdx.x] = src[threadIdx.x];
}

// ---------------- cross-column merge attention ----------------
__global__ void merge_attn_kernel(const float* __restrict__ Qm, const float* __restrict__ Km,
                                  const float* __restrict__ Vm,
                                  __half* __restrict__ Oh, __half* __restrict__ Ol)
{
    int gid = blockIdx.x * blockDim.x + threadIdx.x;
    int h   = gid & 3;
    int row = (gid >> 2) & (BT - 1);
    int i   = gid >> 13;
    if (i >= CC) return;
    long base  = (long)row * DC + h*64;
    long cstep = (long)BT * DC;

    float4 q[16];
    const float4* qp = (const float4*)(Qm + i*cstep + base);
#pragma unroll
    for (int t = 0; t < 16; t++) q[t] = qp[t];

    float s[CC];
#pragma unroll
    for (int j = 0; j < CC; j++) {
        const float4* kp = (const float4*)(Km + j*cstep + base);
        float acc = 0.f;
#pragma unroll
        for (int t = 0; t < 16; t++) {
            float4 kv = kp[t];
            acc += q[t].x*kv.x + q[t].y*kv.y + q[t].z*kv.z + q[t].w*kv.w;
        }
        s[j] = acc * 0.125f;
    }
    float mm = fmaxf(fmaxf(s[0], s[1]), fmaxf(s[2], s[3]));
    float a[CC], sum = 0.f;
#pragma unroll
    for (int j = 0; j < CC; j++) { a[j] = __expf(s[j] - mm); sum += a[j]; }
    float isum = 1.f / sum;
#pragma unroll
    for (int j = 0; j < CC; j++) a[j] *= isum;

    float o[64];
#pragma unroll
    for (int t = 0; t < 64; t++) o[t] = 0.f;
#pragma unroll
    for (int j = 0; j < CC; j++) {
        const float4* vp = (const float4*)(Vm + j*cstep + base);
        float aj = a[j];
#pragma unroll
        for (int t = 0; t < 16; t++) {
            float4 vv = vp[t];
            o[4*t+0] = fmaf(aj, vv.x, o[4*t+0]);
            o[4*t+1] = fmaf(aj, vv.y, o[4*t+1]);
            o[4*t+2] = fmaf(aj, vv.z, o[4*t+2]);
            o[4*t+3] = fmaf(aj, vv.w, o[4*t+3]);
        }
    }
    long ob = i*cstep + base;
#pragma unroll
    for (int t = 0; t < 64; t++) split_store(Oh, Ol, ob + t, o[t]);
}

// ---------------- concat ----------------
__global__ void comb_kernel(const float* __restrict__ cs, __half* __restrict__ oh,
                            __half* __restrict__ ol)
{
    int gid = blockIdx.x * blockDim.x + threadIdx.x;
    int d4  = gid & (DD/4 - 1);
    int row = gid / (DD/4);
    int d = d4 * 4;
    int c = d >> 8;
    int e = d & 255;
    float4 v = *(const float4*)(cs + (long)c*BT*DC + (long)row*DC + e);
    split_store(oh, ol, 4L*gid + 0, v.x);
    split_store(oh, ol, 4L*gid + 1, v.y);
    split_store(oh, ol, 4L*gid + 2, v.z);
    split_store(oh, ol, 4L*gid + 3, v.w);
}

// ---------------- host side ----------------
static __half *Wh_p, *Wl_p;
#define HG2_SMEM (2*4*GPER*2)
#define HG1_SMEM (2*2*GPER*2)

static inline void hgemm(const __half* Ah, const __half* Al, long boff, float* C,
                         int M, int N, int K, int accum, const float* bias, int batch,
                         long aBS, long bBS, long cBS, long biasBS, int nt)
{
    dim3 grid(N/BN, M/BM, batch);
    if (nt == 2)
        hgemm_kernel<2><<<grid, 256, HG2_SMEM>>>(Ah, Al, Wh_p + boff, Wl_p + boff, bias, C,
                                                 M, N, K, accum, aBS, bBS, cBS, biasBS);
    else
        hgemm_kernel<1><<<grid, 256, HG1_SMEM>>>(Ah, nullptr, Wh_p + boff, nullptr, bias, C,
                                                 M, N, K, accum, aBS, bBS, cBS, biasBS);
}

static inline void splitT4(const float* a, const float* b, const float* c, const float* d,
                           long off, int K, int N, int perBatch, int ngroups)
{
    splitT4_kernel<<<dim3(N/32, K/32, ngroups*perBatch), 256>>>(
        a, b, c, d, Wh_p + off, Wl_p + off, K, N, perBatch);
}

extern "C" void kernel_launch(void* const* d_in, const int* in_sizes, int n_in,
                              void* d_out, int out_size)
{
    const int*   ids   = (const int*)d_in[0];
    const float* emb   = (const float*)d_in[1];
    const float* t_wq  = (const float*)d_in[2];
    const float* t_wk  = (const float*)d_in[3];
    const float* t_wv  = (const float*)d_in[4];
    const float* t_wo  = (const float*)d_in[5];
    const float* t_w1  = (const float*)d_in[6];
    const float* t_w2  = (const float*)d_in[7];
    const float* t_n1  = (const float*)d_in[8];
    const float* t_n2  = (const float*)d_in[9];
    const float* cin_w = (const float*)d_in[10];
    const float* cin_b = (const float*)d_in[11];
    const float* c_wq  = (const float*)d_in[12];
    const float* c_wk  = (const float*)d_in[13];
    const float* c_wv  = (const float*)d_in[14];
    const float* c_wo  = (const float*)d_in[15];
    const float* c_w1  = (const float*)d_in[16];
    const float* c_w2  = (const float*)d_in[17];
    const float* c_n1  = (const float*)d_in[18];
    const float* c_n2  = (const float*)d_in[19];
    const float* m_wq  = (const float*)d_in[20];
    const float* m_wk  = (const float*)d_in[21];
    const float* m_wv  = (const float*)d_in[22];
    const float* m_wo  = (const float*)d_in[23];
    const float* m_n   = (const float*)d_in[24];
    const float* oproj = (const float*)d_in[25];
    const float* fnorm = (const float*)d_in[26];
    float* out = (float*)d_out;

    void* p;
    cudaGetSymbolAddress(&p, g_X);   float*  X   = (float*)p;
    cudaGetSymbolAddress(&p, g_Q);   float*  Q   = (float*)p;
    cudaGetSymbolAddress(&p, g_K);   float*  Kb  = (float*)p;
    cudaGetSymbolAddress(&p, g_V);   float*  Vb  = (float*)p;
    cudaGetSymbolAddress(&p, g_M1);  float*  M1  = (float*)p;
    cudaGetSymbolAddress(&p, g_CS);  float*  CS  = (float*)p;
    cudaGetSymbolAddress(&p, g_Hh);  __half* Hh  = (__half*)p;
    cudaGetSymbolAddress(&p, g_Hl);  __half* Hl  = (__half*)p;
    cudaGetSymbolAddress(&p, g_M1h); __half* M1h = (__half*)p;
    cudaGetSymbolAddress(&p, g_M1l); __half* M1l = (__half*)p;
    cudaGetSymbolAddress(&p, g_Oh);  __half* Oh  = (__half*)p;
    cudaGetSymbolAddress(&p, g_Ol);  __half* Ol  = (__half*)p;
    cudaGetSymbolAddress(&p, g_Qh);  __half* Qh  = (__half*)p;
    cudaGetSymbolAddress(&p, g_Ql);  __half* Ql  = (__half*)p;
    cudaGetSymbolAddress(&p, g_Kh);  __half* Kh  = (__half*)p;
    cudaGetSymbolAddress(&p, g_Kl);  __half* Kl  = (__half*)p;
    cudaGetSymbolAddress(&p, g_Vh);  __half* Vh  = (__half*)p;
    cudaGetSymbolAddress(&p, g_Vl);  __half* Vl  = (__half*)p;
    cudaGetSymbolAddress(&p, g_Wh);  Wh_p = (__half*)p;
    cudaGetSymbolAddress(&p, g_Wl);  Wl_p = (__half*)p;

    cudaFuncSetAttribute(hgemm_kernel<2>, cudaFuncAttributeMaxDynamicSharedMemorySize, HG2_SMEM);
    cudaFuncSetAttribute(hgemm_kernel<1>, cudaFuncAttributeMaxDynamicSharedMemorySize, HG1_SMEM);
    cudaFuncSetAttribute(fattn_kernel, cudaFuncAttributeMaxDynamicSharedMemorySize, FATTN_SMEM);

    // ---- weight conversion (batched) ----
    splitT4(t_wq, t_wk, t_wv, t_wo, OT_WQ, DD, DD, LT, 4);
    splitT4(t_w1, nullptr, nullptr, nullptr, OT_W1, DD, DFF, LT, 1);
    splitT4(t_w2, nullptr, nullptr, nullptr, OT_W2, DFF, DD, LT, 1);
    splitT4(cin_w, nullptr, nullptr, nullptr, OC_IN, DD, DC, CC, 1);
    splitT4(c_wq, c_wk, c_wv, c_wo, OC_WQ, DC, DC, CC*LC, 4);
    splitT4(c_w1, nullptr, nullptr, nullptr, OC_W1, DC, DFFC, CC*LC, 1);
    splitT4(c_w2, nullptr, nullptr, nullptr, OC_W2, DFFC, DC, CC*LC, 1);
    splitT4(m_wq, m_wk, m_wv, m_wo, OM_WQ, DC, DC, NM, 4);
    splitT4(oproj, nullptr, nullptr, nullptr, O_OP, DD, DD, 1, 1);
    split1_kernel<<<(BV*DD/4 + 255)/256, 256>>>(emb, Wh_p + O_EMB, BV*DD/4);

    embed_kernel<<<BT, 256>>>(X, emb, ids);

    // ---- trunk ----
    for (int l = 0; l < LT; l++) {
        rms_kernel<<<BT, 256>>>(X, t_n1 + (long)l*DD, Hh, Hl, DD, BT, 0);
        hgemm(Hh, Hl, OT_WQ + (long)l*DD*DD, Q,  BT, DD, DD, 0, nullptr, 1, 0,0,0,0, 2);
        hgemm(Hh, Hl, OT_WK + (long)l*DD*DD, Kb, BT, DD, DD, 0, nullptr, 1, 0,0,0,0, 2);
        hgemm(Hh, Hl, OT_WV + (long)l*DD*DD, Vb, BT, DD, DD, 0, nullptr, 1, 0,0,0,0, 2);
        rope_kernel<<<(BT*HT*32)/256, 256>>>(Q, Kb, Qh, Ql, Kh, Kl, TT, HT, DD, BT);
        split2_kernel<<<(BT*DD/4)/256, 256>>>(Vb, Vh, Vl, BT*DD/4);
        fattn_kernel<<<dim3(TT/64, BB*HT, 1), 128, FATTN_SMEM>>>(
            Qh, Ql, Kh, Kl, Vh, Vl, Oh, Ol, TT, HT, DD, 0);
        hgemm(Oh, Ol, OT_WO + (long)l*DD*DD, X, BT, DD, DD, 1, nullptr, 1, 0,0,0,0, 2);
        rms_kernel<<<BT, 256>>>(X, t_n2 + (long)l*DD, Hh, Hl, DD, BT, 0);
        hgemm(Hh, Hl, OT_W1 + (long)l*DD*DFF, M1, BT, DFF, DD, 0, nullptr, 1, 0,0,0,0, 2);
        gelu_kernel<<<(BT*DFF/4)/256, 256>>>(M1, M1h, M1l, BT*DFF/4);
        hgemm(M1h, M1l, OT_W2 + (long)l*DFF*DD, X, BT, DD, DFF, 1, nullptr, 1, 0,0,0,0, 2);
    }

    // ---- column projection ----
    split2_kernel<<<(BT*DD/4)/256, 256>>>(X, Hh, Hl, BT*DD/4);
    hgemm(Hh, Hl, OC_IN, CS, BT, DC, DD, 0, cin_b, CC, 0, (long)DD*DC, (long)BT*DC, DC, 2);

    // ---- column layers ----
    for (int l = 0; l < LC; l++) {
        rms_kernel<<<CBT, 256>>>(CS, c_n1 + (long)l*DC, Hh, Hl, DC, BT, (long)LC*DC);
        hgemm(Hh, Hl, OC_WQ + (long)l*DC*DC, Q,  BT, DC, DC, 0, nullptr, CC,
              (long)BT*DC, (long)LC*DC*DC, (long)BT*DC, 0, 2);
        hgemm(Hh, Hl, OC_WK + (long)l*DC*DC, Kb, BT, DC, DC, 0, nullptr, CC,
              (long)BT*DC, (long)LC*DC*DC, (long)BT*DC, 0, 2);
        hgemm(Hh, Hl, OC_WV + (long)l*DC*DC, Vb, BT, DC, DC, 0, nullptr, CC,
              (long)BT*DC, (long)LC*DC*DC, (long)BT*DC, 0, 2);
        rope_kernel<<<(CBT*HC*32)/256, 256>>>(Q, Kb, Qh, Ql, Kh, Kl, TT, HC, DC, CBT);
        split2_kernel<<<(CBT*DC/4)/256, 256>>>(Vb, Vh, Vl, CBT*DC/4);
        fattn_kernel<<<dim3(TT/64, BB*HC, CC), 128, FATTN_SMEM>>>(
            Qh, Ql, Kh, Kl, Vh, Vl, Oh, Ol, TT, HC, DC, (long)BT*DC);
        hgemm(Oh, Ol, OC_WO + (long)l*DC*DC, CS, BT, DC, DC, 1, nullptr, CC,
              (long)BT*DC, (long)LC*DC*DC, (long)BT*DC, 0, 2);
        rms_kernel<<<CBT, 256>>>(CS, c_n2 + (long)l*DC, Hh, Hl, DC, BT, (long)LC*DC);
        hgemm(Hh, Hl, OC_W1 + (long)l*DC*DFFC, M1, BT, DFFC, DC, 0, nullptr, CC,
              (long)BT*DC, (long)LC*DC*DFFC, (long)BT*DFFC, 0, 2);
        gelu_kernel<<<(CBT*DFFC/4)/256, 256>>>(M1, M1h, M1l, CBT*DFFC/4);
        hgemm(M1h, M1l, OC_W2 + (long)l*DFFC*DC, CS, BT, DC, DFFC, 1, nullptr, CC,
              (long)BT*DFFC, (long)LC*DFFC*DC, (long)BT*DC, 0, 2);

        if (((l + 1) & 1) == 0) {
            int m = (l + 1)/2 - 1;
            rms_kernel<<<CBT, 256>>>(CS, m_n + (long)m*DC, Hh, Hl, DC, CBT, 0);
            hgemm(Hh, Hl, OM_WQ + (long)m*DC*DC, Q,  CBT, DC, DC, 0, nullptr, 1, 0,0,0,0, 2);
            hgemm(Hh, Hl, OM_WK + (long)m*DC*DC, Kb, CBT, DC, DC, 0, nullptr, 1, 0,0,0,0, 2);
            hgemm(Hh, Hl, OM_WV + (long)m*DC*DC, Vb, CBT, DC, DC, 0, nullptr, 1, 0,0,0,0, 2);
            merge_attn_kernel<<<(CC*BT*HC)/256, 256>>>(Q, Kb, Vb, Oh, Ol);
            hgemm(Oh, Ol, OM_WO + (long)m*DC*DC, CS, CBT, DC, DC, 1, nullptr, 1, 0,0,0,0, 2);
        }
    }

    // ---- output head ----
    comb_kernel<<<(BT*DD/4)/256, 256>>>(CS, Hh, Hl);
    hgemm(Hh, Hl, O_OP, Q, BT, DD, DD, 0, nullptr, 1, 0,0,0,0, 2);
    rms_kernel<<<BT, 256>>>(Q, fnorm, Hh, Hl, DD, BT, 0);
    hgemm(Hh, nullptr, O_EMB, out, BT, BV, DD, 0, nullptr, 1, 0,0,0,0, 1);
}

// round 7
// speedup vs baseline: 1.0608x; 1.0268x over previous
#include <cuda_runtime.h>
#include <cuda_fp16.h>
#include <math.h>
#include <stdint.h>

// ---------------- model constants ----------------
#define BV   32000
#define DD   1024
#define DFF  4096
#define LT   2
#define HT   16
#define CC   4
#define DC   256
#define DFFC 1024
#define LC   4
#define HC   4
#define NM   2
#define BB   2
#define TT   1024
#define BT   (BB*TT)     // 2048
#define CBT  (CC*BT)     // 8192

// ---------------- weight offsets (transposed [N][K] fp16 store) ----------------
constexpr long OT_WQ = 0;
constexpr long OT_WK = OT_WQ + (long)LT*DD*DD;
constexpr long OT_WV = OT_WK + (long)LT*DD*DD;
constexpr long OT_WO = OT_WV + (long)LT*DD*DD;
constexpr long OT_W1 = OT_WO + (long)LT*DD*DD;
constexpr long OT_W2 = OT_W1 + (long)LT*DD*DFF;
constexpr long OC_IN = OT_W2 + (long)LT*DFF*DD;
constexpr long OC_WQ = OC_IN + (long)CC*DD*DC;
constexpr long OC_WK = OC_WQ + (long)CC*LC*DC*DC;
constexpr long OC_WV = OC_WK + (long)CC*LC*DC*DC;
constexpr long OC_WO = OC_WV + (long)CC*LC*DC*DC;
constexpr long OC_W1 = OC_WO + (long)CC*LC*DC*DC;
constexpr long OC_W2 = OC_W1 + (long)CC*LC*DC*DFFC;
constexpr long OM_WQ = OC_W2 + (long)CC*LC*DFFC*DC;
constexpr long OM_WK = OM_WQ + (long)NM*DC*DC;
constexpr long OM_WV = OM_WK + (long)NM*DC*DC;
constexpr long OM_WO = OM_WV + (long)NM*DC*DC;
constexpr long O_OP  = OM_WO + (long)NM*DC*DC;
constexpr long O_EMB = O_OP  + (long)DD*DD;
constexpr long WTOT  = O_EMB + (long)BV*DD;

// ---------------- scratch (device globals) ----------------
__device__ float  g_X [BT*DD];
__device__ float  g_Q [BT*DD];
__device__ float  g_K [BT*DD];
__device__ float  g_V [BT*DD];
__device__ float  g_CS[CC*BT*DC];
__device__ __half g_Hh[BT*DD];
__device__ __half g_Hl[BT*DD];
__device__ __half g_M1h[BT*DFF];
__device__ __half g_M1l[BT*DFF];
__device__ __half g_Oh[BT*DD];
__device__ __half g_Ol[BT*DD];
__device__ __half g_Qh[BT*DD];
__device__ __half g_Ql[BT*DD];
__device__ __half g_Kh[BT*DD];
__device__ __half g_Kl[BT*DD];
__device__ __half g_Vh[BT*DD];
__device__ __half g_Vl[BT*DD];
__device__ __half g_Wh[WTOT];
__device__ __half g_Wl[WTOT];

// ---------------- asm helpers ----------------
__device__ __forceinline__ void lm4(const __half* p, uint32_t* r)
{
    uint32_t a = (uint32_t)__cvta_generic_to_shared(p);
    asm volatile("ldmatrix.sync.aligned.m8n8.x4.shared.b16 {%0,%1,%2,%3}, [%4];"
        : "=r"(r[0]), "=r"(r[1]), "=r"(r[2]), "=r"(r[3]) : "r"(a));
}
__device__ __forceinline__ void lm4t(const __half* p, uint32_t* r)
{
    uint32_t a = (uint32_t)__cvta_generic_to_shared(p);
    asm volatile("ldmatrix.sync.aligned.m8n8.x4.trans.shared.b16 {%0,%1,%2,%3}, [%4];"
        : "=r"(r[0]), "=r"(r[1]), "=r"(r[2]), "=r"(r[3]) : "r"(a));
}
// volatile, as in the R3 champion — do not change ordering freedom
__device__ __forceinline__ void mma16816(float* c, const uint32_t* a, const uint32_t* b)
{
    asm volatile("mma.sync.aligned.m16n8k16.row.col.f32.f16.f16.f32 "
        "{%0,%1,%2,%3},{%4,%5,%6,%7},{%8,%9},{%0,%1,%2,%3};"
        : "+f"(c[0]), "+f"(c[1]), "+f"(c[2]), "+f"(c[3])
        : "r"(a[0]), "r"(a[1]), "r"(a[2]), "r"(a[3]), "r"(b[0]), "r"(b[1]));
}
__device__ __forceinline__ void cpasync16(const __half* dst, const __half* src)
{
    uint32_t d = (uint32_t)__cvta_generic_to_shared(dst);
    asm volatile("cp.async.cg.shared.global [%0], [%1], 16;" :: "r"(d), "l"(src));
}
__device__ __forceinline__ void cp_commit() { asm volatile("cp.async.commit_group;"); }
template<int N> __device__ __forceinline__ void cp_wait()
{ asm volatile("cp.async.wait_group %0;" :: "n"(N)); }

__device__ __forceinline__ float gelu1(float v)
{
    return 0.5f * v * (1.f + tanhf(0.7978845608028654f * (v + 0.044715f*v*v*v)));
}
__device__ __forceinline__ void split_store(__half* oh, __half* ol, long idx, float v)
{
    __half h = __float2half(v);
    oh[idx] = h;
    ol[idx] = __float2half(v - __half2float(h));
}

// ---------------- HGEMM (cp.async double-buffered, R3 mainloop verbatim) ----------------
// A: [M][K] rm, B: [N][K] rm.  NT=2: hi/lo split, NT=1: plain.
// MODE 0: C fp32 (+accum)   MODE 1: split hi/lo out   MODE 2: gelu + split out
#define BM 128
#define BN 128
#define BKH 32
#define SSTR 40
#define GPER (BM*SSTR)

template<int NT, int MODE>
__global__ void __launch_bounds__(256) hgemm_kernel(
    const __half* __restrict__ Ah, const __half* __restrict__ Al,
    const __half* __restrict__ Bh, const __half* __restrict__ Bl,
    const float* __restrict__ bias, float* __restrict__ C,
    __half* __restrict__ Coh, __half* __restrict__ Col,
    int M, int N, int K, int accum,
    long aBS, long bBS, long cBS, long biasBS)
{
    extern __shared__ __half smp[];
    const int NARR = (NT == 2) ? 4 : 2;

    Ah += blockIdx.z * aBS;
    Bh += blockIdx.z * bBS;
    if (MODE == 0) C += blockIdx.z * cBS;
    else { Coh += blockIdx.z * cBS; Col += blockIdx.z * cBS; }
    if (NT == 2) { Al += blockIdx.z * aBS; Bl += blockIdx.z * bBS; }
    if (bias) bias += blockIdx.z * biasBS;

    int row0 = blockIdx.y * BM;
    int col0 = blockIdx.x * BN;
    int tid  = threadIdx.x;
    int lane = tid & 31;
    int wid  = tid >> 5;
    int wm0  = (wid >> 2) * 64;
    int wn0  = (wid & 3) * 32;

    float acc[4][4][4];
#pragma unroll
    for (int mt = 0; mt < 4; mt++)
#pragma unroll
        for (int nt = 0; nt < 4; nt++)
#pragma unroll
            for (int q = 0; q < 4; q++) acc[mt][nt][q] = 0.f;

    int a_r  = lane & 15;
    int a_ko = (lane >> 4) << 3;
    int b_n  = ((lane >> 4) << 3) + (lane & 7);
    int b_ko = ((lane >> 3) & 1) << 3;

    int nk = K / BKH;

    auto loadStage = [&](int st, int k0) {
        __half* dAh = smp + st * NARR * GPER;
        __half* dBh = dAh + GPER;
        __half* dAl = dAh + 2 * GPER;
        __half* dBl = dAh + 3 * GPER;
#pragma unroll
        for (int c = tid; c < 512; c += 256) {
            int r = c >> 2, o = (c & 3) << 3;
            cpasync16(&dAh[r*SSTR + o], &Ah[(long)(row0 + r)*K + k0 + o]);
            cpasync16(&dBh[r*SSTR + o], &Bh[(long)(col0 + r)*K + k0 + o]);
            if (NT == 2) {
                cpasync16(&dAl[r*SSTR + o], &Al[(long)(row0 + r)*K + k0 + o]);
                cpasync16(&dBl[r*SSTR + o], &Bl[(long)(col0 + r)*K + k0 + o]);
            }
        }
    };

    loadStage(0, 0);
    cp_commit();

    for (int kt = 0; kt < nk; kt++) {
        int cur = kt & 1;
        if (kt + 1 < nk) {
            loadStage(cur ^ 1, (kt + 1) * BKH);
            cp_commit();
            cp_wait<1>();
        } else {
            cp_wait<0>();
        }
        __syncthreads();

        const __half* pAh = smp + cur * NARR * GPER;
        const __half* pBh = pAh + GPER;
        const __half* pAl = pAh + 2 * GPER;
        const __half* pBl = pAh + 3 * GPER;

#pragma unroll
        for (int ks = 0; ks < BKH; ks += 16) {
            uint32_t a_hi[4][4], b_hi[2][4];
#pragma unroll
            for (int mt = 0; mt < 4; mt++)
                lm4(&pAh[(wm0 + mt*16 + a_r)*SSTR + ks + a_ko], a_hi[mt]);
#pragma unroll
            for (int np = 0; np < 2; np++)
                lm4(&pBh[(wn0 + np*16 + b_n)*SSTR + ks + b_ko], b_hi[np]);
#pragma unroll
            for (int mt = 0; mt < 4; mt++)
#pragma unroll
                for (int nt = 0; nt < 4; nt++)
                    mma16816(acc[mt][nt], a_hi[mt], &b_hi[nt >> 1][(nt & 1)*2]);

            if (NT == 2) {
                uint32_t b_lo[2][4];
#pragma unroll
                for (int np = 0; np < 2; np++)
                    lm4(&pBl[(wn0 + np*16 + b_n)*SSTR + ks + b_ko], b_lo[np]);
#pragma unroll
                for (int mt = 0; mt < 4; mt++)
#pragma unroll
                    for (int nt = 0; nt < 4; nt++)
                        mma16816(acc[mt][nt], a_hi[mt], &b_lo[nt >> 1][(nt & 1)*2]);
                uint32_t a_lo[4][4];
#pragma unroll
                for (int mt = 0; mt < 4; mt++)
                    lm4(&pAl[(wm0 + mt*16 + a_r)*SSTR + ks + a_ko], a_lo[mt]);
#pragma unroll
                for (int mt = 0; mt < 4; mt++)
#pragma unroll
                    for (int nt = 0; nt < 4; nt++)
                        mma16816(acc[mt][nt], a_lo[mt], &b_hi[nt >> 1][(nt & 1)*2]);
            }
        }
        __syncthreads();
    }

    int g = lane >> 2, t = lane & 3;
#pragma unroll
    for (int mt = 0; mt < 4; mt++) {
#pragma unroll
        for (int nt = 0; nt < 4; nt++) {
            int r1  = row0 + wm0 + mt*16 + g;
            int cix = col0 + wn0 + nt*8 + 2*t;
            float bv0 = 0.f, bv1 = 0.f;
            if (bias) { bv0 = bias[cix]; bv1 = bias[cix + 1]; }
            float v00 = acc[mt][nt][0] + bv0, v01 = acc[mt][nt][1] + bv1;
            float v10 = acc[mt][nt][2] + bv0, v11 = acc[mt][nt][3] + bv1;
            long o0 = (long)r1*N + cix;
            long o1 = (long)(r1 + 8)*N + cix;
            if (MODE == 0) {
                if (accum) {
                    float2 p0 = *(float2*)&C[o0];
                    float2 p1 = *(float2*)&C[o1];
                    v00 += p0.x; v01 += p0.y;
                    v10 += p1.x; v11 += p1.y;
                }
                *(float2*)&C[o0] = make_float2(v00, v01);
                *(float2*)&C[o1] = make_float2(v10, v11);
            } else {
                if (MODE == 2) {
                    v00 = gelu1(v00); v01 = gelu1(v01);
                    v10 = gelu1(v10); v11 = gelu1(v11);
                }
                __half h00 = __float2half(v00), h01 = __float2half(v01);
                __half h10 = __float2half(v10), h11 = __float2half(v11);
                *(__half2*)&Coh[o0] = __halves2half2(h00, h01);
                *(__half2*)&Coh[o1] = __halves2half2(h10, h11);
                *(__half2*)&Col[o0] = __halves2half2(
                    __float2half(v00 - __half2float(h00)),
                    __float2half(v01 - __half2float(h01)));
                *(__half2*)&Col[o1] = __halves2half2(
                    __float2half(v10 - __half2float(h10)),
                    __float2half(v11 - __half2float(h11)));
            }
        }
    }
}

// ---------------- tensor-core flash attention (causal, hd=64) ----------------
#define ASTR 72
#define FATTN_SMEM (6*64*ASTR*2)

__global__ void __launch_bounds__(128) fattn_kernel(
    const __half* __restrict__ Qh, const __half* __restrict__ Ql,
    const __half* __restrict__ Kh, const __half* __restrict__ Kl,
    const __half* __restrict__ Vh, const __half* __restrict__ Vl,
    __half* __restrict__ Oh, __half* __restrict__ Ol,
    int T, int nh, int rstride, long colstride)
{
    extern __shared__ __half sm[];
    __half* sQh = sm;
    __half* sQl = sQh + 64*ASTR;
    __half* sKh = sQl + 64*ASTR;
    __half* sKl = sKh + 64*ASTR;
    __half* sVh = sKl + 64*ASTR;
    __half* sVl = sVh + 64*ASTR;

    int qt = blockIdx.x;
    int b  = blockIdx.y / nh;
    int h  = blockIdx.y % nh;
    long base = (long)blockIdx.z * colstride + (long)h * 64;
    int q0  = qt * 64;
    int tid = threadIdx.x;
    int lane = tid & 31;
    int wid  = tid >> 5;
    int wrow = wid * 16;
    int g = lane >> 2, t4 = lane & 3;

#pragma unroll
    for (int c = tid; c < 512; c += 128) {
        int r = c >> 3, o = (c & 7) << 3;
        long src = base + (long)(b*T + q0 + r)*rstride + o;
        *(uint4*)&sQh[r*ASTR + o] = *(const uint4*)&Qh[src];
        *(uint4*)&sQl[r*ASTR + o] = *(const uint4*)&Ql[src];
    }
    __syncthreads();

    int a_r  = lane & 15;
    int a_ko = (lane >> 4) << 3;
    int b_n  = ((lane >> 4) << 3) + (lane & 7);
    int b_ko = ((lane >> 3) & 1) << 3;
    int v_r  = (((lane >> 3) & 1) << 3) + (lane & 7);
    int v_c  = (lane >> 4) << 3;

    uint32_t qfh[4][4], qfl[4][4];
#pragma unroll
    for (int ks = 0; ks < 4; ks++) {
        lm4(&sQh[(wrow + a_r)*ASTR + ks*16 + a_ko], qfh[ks]);
        lm4(&sQl[(wrow + a_r)*ASTR + ks*16 + a_ko], qfl[ks]);
    }

    float mrow[2] = {-1e30f, -1e30f};
    float lrow[2] = {0.f, 0.f};
    float oacc[8][4];
#pragma unroll
    for (int nt = 0; nt < 8; nt++)
#pragma unroll
        for (int e = 0; e < 4; e++) oacc[nt][e] = 0.f;

    for (int kt = 0; kt <= qt; kt++) {
        int k0 = kt * 64;
        __syncthreads();
#pragma unroll
        for (int c = tid; c < 512; c += 128) {
            int r = c >> 3, o = (c & 7) << 3;
            long src = base + (long)(b*T + k0 + r)*rstride + o;
            *(uint4*)&sKh[r*ASTR + o] = *(const uint4*)&Kh[src];
            *(uint4*)&sKl[r*ASTR + o] = *(const uint4*)&Kl[src];
            *(uint4*)&sVh[r*ASTR + o] = *(const uint4*)&Vh[src];
            *(uint4*)&sVl[r*ASTR + o] = *(const uint4*)&Vl[src];
        }
        __syncthreads();

        float S[8][4];
#pragma unroll
        for (int nt = 0; nt < 8; nt++)
#pragma unroll
            for (int e = 0; e < 4; e++) S[nt][e] = 0.f;

#pragma unroll
        for (int ks = 0; ks < 4; ks++) {
            uint32_t bh[4][4], bl[4][4];
#pragma unroll
            for (int np = 0; np < 4; np++) {
                lm4(&sKh[(np*16 + b_n)*ASTR + ks*16 + b_ko], bh[np]);
                lm4(&sKl[(np*16 + b_n)*ASTR + ks*16 + b_ko], bl[np]);
            }
#pragma unroll
            for (int np = 0; np < 4; np++)
#pragma unroll
                for (int j = 0; j < 2; j++) {
                    int nt = np*2 + j;
                    mma16816(S[nt], qfh[ks], &bh[np][j*2]);
                    mma16816(S[nt], qfh[ks], &bl[np][j*2]);
                    mma16816(S[nt], qfl[ks], &bh[np][j*2]);
                }
        }

#pragma unroll
        for (int nt = 0; nt < 8; nt++)
#pragma unroll
            for (int e = 0; e < 4; e++) {
                S[nt][e] *= 0.125f;
                if (kt == qt) {
                    int col = k0 + nt*8 + t4*2 + (e & 1);
                    int row = q0 + wrow + g + ((e >> 1) << 3);
                    if (col > row) S[nt][e] = -1e30f;
                }
            }

        float P[8][4];
#pragma unroll
        for (int r = 0; r < 2; r++) {
            float mx = -1e30f;
#pragma unroll
            for (int nt = 0; nt < 8; nt++) {
                mx = fmaxf(mx, S[nt][2*r + 0]);
                mx = fmaxf(mx, S[nt][2*r + 1]);
            }
            mx = fmaxf(mx, __shfl_xor_sync(0xffffffffu, mx, 1));
            mx = fmaxf(mx, __shfl_xor_sync(0xffffffffu, mx, 2));
            float mnew  = fmaxf(mrow[r], mx);
            float alpha = __expf(mrow[r] - mnew);
            float rsum = 0.f;
#pragma unroll
            for (int nt = 0; nt < 8; nt++) {
                float p0 = __expf(S[nt][2*r + 0] - mnew);
                float p1 = __expf(S[nt][2*r + 1] - mnew);
                P[nt][2*r + 0] = p0; P[nt][2*r + 1] = p1;
                rsum += p0 + p1;
            }
            rsum += __shfl_xor_sync(0xffffffffu, rsum, 1);
            rsum += __shfl_xor_sync(0xffffffffu, rsum, 2);
            lrow[r] = lrow[r]*alpha + rsum;
            mrow[r] = mnew;
#pragma unroll
            for (int nt = 0; nt < 8; nt++) {
                oacc[nt][2*r + 0] *= alpha;
                oacc[nt][2*r + 1] *= alpha;
            }
        }

        uint32_t pah[4][4], pal[4][4];
#pragma unroll
        for (int ks = 0; ks < 4; ks++) {
            int j0 = 2*ks, j1 = 2*ks + 1;
#pragma unroll
            for (int q = 0; q < 4; q++) {
                int jj = (q < 2) ? j0 : j1;
                int e0 = (q & 1) ? 2 : 0;
                float f0 = P[jj][e0], f1 = P[jj][e0 + 1];
                __half h0 = __float2half(f0), h1 = __float2half(f1);
                __half l0 = __float2half(f0 - __half2float(h0));
                __half l1 = __float2half(f1 - __half2float(h1));
                pah[ks][q] = (uint32_t)__half_as_ushort(h0) |
                             ((uint32_t)__half_as_ushort(h1) << 16);
                pal[ks][q] = (uint32_t)__half_as_ushort(l0) |
                             ((uint32_t)__half_as_ushort(l1) << 16);
            }
        }

#pragma unroll
        for (int ks = 0; ks < 4; ks++) {
            uint32_t vh[4][4], vl[4][4];
#pragma unroll
            for (int np = 0; np < 4; np++) {
                lm4t(&sVh[(ks*16 + v_r)*ASTR + np*16 + v_c], vh[np]);
                lm4t(&sVl[(ks*16 + v_r)*ASTR + np*16 + v_c], vl[np]);
            }
#pragma unroll
            for (int np = 0; np < 4; np++)
#pragma unroll
                for (int j = 0; j < 2; j++) {
                    int nt = np*2 + j;
                    mma16816(oacc[nt], pah[ks], &vh[np][j*2]);
                    mma16816(oacc[nt], pah[ks], &vl[np][j*2]);
                    mma16816(oacc[nt], pal[ks], &vh[np][j*2]);
                }
        }
    }

#pragma unroll
    for (int r = 0; r < 2; r++) {
        float inv = 1.f / lrow[r];
        int row = q0 + wrow + g + r*8;
        long ob = base + (long)(b*T + row)*rstride;
#pragma unroll
        for (int nt = 0; nt < 8; nt++) {
            float v0 = oacc[nt][2*r + 0] * inv;
            float v1 = oacc[nt][2*r + 1] * inv;
            __half h0 = __float2half(v0), h1 = __float2half(v1);
            __half l0 = __float2half(v0 - __half2float(h0));
            __half l1 = __float2half(v1 - __half2float(h1));
            int col = nt*8 + t4*2;
            *(__half2*)&Oh[ob + col] = __halves2half2(h0, h1);
            *(__half2*)&Ol[ob + col] = __halves2half2(l0, l1);
        }
    }
}

// ---------------- weight transpose + fp16 split (up to 4 sources per launch) ----------------
__global__ void splitT4_kernel(const float* p0, const float* p1,
                               const float* p2, const float* p3,
                               __half* __restrict__ oh, __half* __restrict__ ol,
                               int K, int N, int perBatch)
{
    __shared__ float tile[32][33];
    const float* ps[4] = {p0, p1, p2, p3};
    int gsel = blockIdx.z / perBatch;
    int bz   = blockIdx.z % perBatch;
    const float* in = ps[gsel] + (long)bz * K * N;
    long ob = (long)blockIdx.z * K * N;
    int n0 = blockIdx.x * 32, k0 = blockIdx.y * 32;
    int tx = threadIdx.x & 31, ty = threadIdx.x >> 5;
#pragma unroll
    for (int j = 0; j < 4; j++) {
        int r = ty*4 + j;
        tile[r][tx] = in[(long)(k0 + r)*N + n0 + tx];
    }
    __syncthreads();
#pragma unroll
    for (int j = 0; j < 4; j++) {
        int nn = ty*4 + j;
        float v = tile[tx][nn];
        __half h = __float2half(v);
        long o = ob + (long)(n0 + nn)*K + k0 + tx;
        oh[o] = h;
        ol[o] = __float2half(v - __half2float(h));
    }
}

__global__ void split1_kernel(const float* __restrict__ in, __half* __restrict__ oh, int n4)
{
    int i = blockIdx.x * blockDim.x + threadIdx.x;
    if (i >= n4) return;
    float4 v = ((const float4*)in)[i];
    oh[4*i + 0] = __float2half(v.x);
    oh[4*i + 1] = __float2half(v.y);
    oh[4*i + 2] = __float2half(v.z);
    oh[4*i + 3] = __float2half(v.w);
}

__global__ void split2_kernel(const float* __restrict__ in, __half* __restrict__ oh,
                              __half* __restrict__ ol, int n4)
{
    int i = blockIdx.x * blockDim.x + threadIdx.x;
    if (i >= n4) return;
    float4 v = ((const float4*)in)[i];
    split_store(oh, ol, 4L*i + 0, v.x);
    split_store(oh, ol, 4L*i + 1, v.y);
    split_store(oh, ol, 4L*i + 2, v.z);
    split_store(oh, ol, 4L*i + 3, v.w);
}

// ---------------- rmsnorm -> fp16 hi/lo ----------------
__global__ void rms_kernel(const float* __restrict__ x, const float* __restrict__ w,
                           __half* __restrict__ oh, __half* __restrict__ ol,
                           int W, int rowsPerChunk, long wStride)
{
    int row = blockIdx.x;
    const float* xr = x + (long)row * W;
    const float* wr = w + (long)(row / rowsPerChunk) * wStride;
    float ss = 0.f;
    for (int i = threadIdx.x; i < W; i += 256) {
        float v = xr[i];
        ss += v * v;
    }
    __shared__ float red[8];
#pragma unroll
    for (int off = 16; off > 0; off >>= 1)
        ss += __shfl_xor_sync(0xffffffffu, ss, off);
    if ((threadIdx.x & 31) == 0) red[threadIdx.x >> 5] = ss;
    __syncthreads();
    float tot = red[0]+red[1]+red[2]+red[3]+red[4]+red[5]+red[6]+red[7];
    float inv = rsqrtf(tot / (float)W + 1e-6f);
    long rb = (long)row * W;
    for (int i = threadIdx.x; i < W; i += 256)
        split_store(oh, ol, rb + i, xr[i] * inv * wr[i]);
}

// ---------------- rope: fp32 q,k -> rotated fp16 hi/lo ----------------
__global__ void rope_kernel(const float* __restrict__ q, const float* __restrict__ k,
                            __half* __restrict__ qh, __half* __restrict__ ql,
                            __half* __restrict__ kh, __half* __restrict__ kl,
                            int T, int nh, int rstride, int nrows)
{
    int idx = blockIdx.x * blockDim.x + threadIdx.x;
    if (idx >= nrows * nh * 32) return;
    int i   = idx & 31;
    int h   = (idx >> 5) % nh;
    int row = idx / (32 * nh);
    int t   = row % T;
    float inv = __expf(-(float)(2*i) * (1.f/64.f) * 9.210340371976184f);
    float f = (float)t * inv;
    float s, c;
    sincosf(f, &s, &c);
    long bo = (long)row * rstride + h*64 + i;
    float q1 = q[bo], q2 = q[bo + 32];
    split_store(qh, ql, bo,      q1*c - q2*s);
    split_store(qh, ql, bo + 32, q2*c + q1*s);
    float k1 = k[bo], k2 = k[bo + 32];
    split_store(kh, kl, bo,      k1*c - k2*s);
    split_store(kh, kl, bo + 32, k2*c + k1*s);
}

// ---------------- embedding gather ----------------
__global__ void embed_kernel(float* __restrict__ X, const float* __restrict__ emb,
                             const int* __restrict__ ids)
{
    int row = blockIdx.x;
    int id  = ids[row];
    const float4* src = (const float4*)(emb + (long)id * DD);
    float4* dst = (float4*)(X + (long)row * DD);
    dst[threadIdx.x] = src[threadIdx.x];
}

// ---------------- cross-column merge attention ----------------
__global__ void merge_attn_kernel(const float* __restrict__ Qm, const float* __restrict__ Km,
                                  const float* __restrict__ Vm,
                                  __half* __restrict__ Oh, __half* __restrict__ Ol)
{
    int gid = blockIdx.x * blockDim.x + threadIdx.x;
    int h   = gid & 3;
    int row = (gid >> 2) & (BT - 1);
    int i   = gid >> 13;
    if (i >= CC) return;
    long base  = (long)row * DC + h*64;
    long cstep = (long)BT * DC;

    float4 q[16];
    const float4* qp = (const float4*)(Qm + i*cstep + base);
#pragma unroll
    for (int t = 0; t < 16; t++) q[t] = qp[t];

    float s[CC];
#pragma unroll
    for (int j = 0; j < CC; j++) {
        const float4* kp = (const float4*)(Km + j*cstep + base);
        float acc = 0.f;
#pragma unroll
        for (int t = 0; t < 16; t++) {
            float4 kv = kp[t];
            acc += q[t].x*kv.x + q[t].y*kv.y + q[t].z*kv.z + q[t].w*kv.w;
        }
        s[j] = acc * 0.125f;
    }
    float mm = fmaxf(fmaxf(s[0], s[1]), fmaxf(s[2], s[3]));
    float a[CC], sum = 0.f;
#pragma unroll
    for (int j = 0; j < CC; j++) { a[j] = __expf(s[j] - mm); sum += a[j]; }
    float isum = 1.f / sum;
#pragma unroll
    for (int j = 0; j < CC; j++) a[j] *= isum;

    float o[64];
#pragma unroll
    for (int t = 0; t < 64; t++) o[t] = 0.f;
#pragma unroll
    for (int j = 0; j < CC; j++) {
        const float4* vp = (const float4*)(Vm + j*cstep + base);
        float aj = a[j];
#pragma unroll
        for (int t = 0; t < 16; t++) {
            float4 vv = vp[t];
            o[4*t+0] = fmaf(aj, vv.x, o[4*t+0]);
            o[4*t+1] = fmaf(aj, vv.y, o[4*t+1]);
            o[4*t+2] = fmaf(aj, vv.z, o[4*t+2]);
            o[4*t+3] = fmaf(aj, vv.w, o[4*t+3]);
        }
    }
    long ob = i*cstep + base;
#pragma unroll
    for (int t = 0; t < 64; t++) split_store(Oh, Ol, ob + t, o[t]);
}

// ---------------- concat ----------------
__global__ void comb_kernel(const float* __restrict__ cs, __half* __restrict__ oh,
                            __half* __restrict__ ol)
{
    int gid = blockIdx.x * blockDim.x + threadIdx.x;
    int d4  = gid & (DD/4 - 1);
    int row = gid / (DD/4);
    int d = d4 * 4;
    int c = d >> 8;
    int e = d & 255;
    float4 v = *(const float4*)(cs + (long)c*BT*DC + (long)row*DC + e);
    split_store(oh, ol, 4L*gid + 0, v.x);
    split_store(oh, ol, 4L*gid + 1, v.y);
    split_store(oh, ol, 4L*gid + 2, v.z);
    split_store(oh, ol, 4L*gid + 3, v.w);
}

// ---------------- host side ----------------
static __half *Wh_p, *Wl_p;
#define HG2_SMEM (2*4*GPER*2)
#define HG1_SMEM (2*2*GPER*2)

// mode: 0 f32 out, 1 split out, 2 gelu+split out
static inline void hgemm(int mode, int nt, const __half* Ah, const __half* Al, long boff,
                         float* C, __half* Coh, __half* Col,
                         int M, int N, int K, int accum, const float* bias, int batch,
                         long aBS, long bBS, long cBS, long biasBS)
{
    dim3 grid(N/BN, M/BM, batch);
    if (nt == 2) {
        if (mode == 0)
            hgemm_kernel<2,0><<<grid, 256, HG2_SMEM>>>(Ah, Al, Wh_p + boff, Wl_p + boff,
                bias, C, nullptr, nullptr, M, N, K, accum, aBS, bBS, cBS, biasBS);
        else if (mode == 1)
            hgemm_kernel<2,1><<<grid, 256, HG2_SMEM>>>(Ah, Al, Wh_p + boff, Wl_p + boff,
                bias, nullptr, Coh, Col, M, N, K, accum, aBS, bBS, cBS, biasBS);
        else
            hgemm_kernel<2,2><<<grid, 256, HG2_SMEM>>>(Ah, Al, Wh_p + boff, Wl_p + boff,
                bias, nullptr, Coh, Col, M, N, K, accum, aBS, bBS, cBS, biasBS);
    } else {
        hgemm_kernel<1,0><<<grid, 256, HG1_SMEM>>>(Ah, nullptr, Wh_p + boff, nullptr,
            bias, C, nullptr, nullptr, M, N, K, accum, aBS, bBS, cBS, biasBS);
    }
}

static inline void splitT4(const float* a, const float* b, const float* c, const float* d,
                           long off, int K, int N, int perBatch, int ngroups)
{
    splitT4_kernel<<<dim3(N/32, K/32, ngroups*perBatch), 256>>>(
        a, b, c, d, Wh_p + off, Wl_p + off, K, N, perBatch);
}

extern "C" void kernel_launch(void* const* d_in, const int* in_sizes, int n_in,
                              void* d_out, int out_size)
{
    const int*   ids   = (const int*)d_in[0];
    const float* emb   = (const float*)d_in[1];
    const float* t_wq  = (const float*)d_in[2];
    const float* t_wk  = (const float*)d_in[3];
    const float* t_wv  = (const float*)d_in[4];
    const float* t_wo  = (const float*)d_in[5];
    const float* t_w1  = (const float*)d_in[6];
    const float* t_w2  = (const float*)d_in[7];
    const float* t_n1  = (const float*)d_in[8];
    const float* t_n2  = (const float*)d_in[9];
    const float* cin_w = (const float*)d_in[10];
    const float* cin_b = (const float*)d_in[11];
    const float* c_wq  = (const float*)d_in[12];
    const float* c_wk  = (const float*)d_in[13];
    const float* c_wv  = (const float*)d_in[14];
    const float* c_wo  = (const float*)d_in[15];
    const float* c_w1  = (const float*)d_in[16];
    const float* c_w2  = (const float*)d_in[17];
    const float* c_n1  = (const float*)d_in[18];
    const float* c_n2  = (const float*)d_in[19];
    const float* m_wq  = (const float*)d_in[20];
    const float* m_wk  = (const float*)d_in[21];
    const float* m_wv  = (const float*)d_in[22];
    const float* m_wo  = (const float*)d_in[23];
    const float* m_n   = (const float*)d_in[24];
    const float* oproj = (const float*)d_in[25];
    const float* fnorm = (const float*)d_in[26];
    float* out = (float*)d_out;

    void* p;
    cudaGetSymbolAddress(&p, g_X);   float*  X   = (float*)p;
    cudaGetSymbolAddress(&p, g_Q);   float*  Q   = (float*)p;
    cudaGetSymbolAddress(&p, g_K);   float*  Kb  = (float*)p;
    cudaGetSymbolAddress(&p, g_V);   float*  Vb  = (float*)p;
    cudaGetSymbolAddress(&p, g_CS);  float*  CS  = (float*)p;
    cudaGetSymbolAddress(&p, g_Hh);  __half* Hh  = (__half*)p;
    cudaGetSymbolAddress(&p, g_Hl);  __half* Hl  = (__half*)p;
    cudaGetSymbolAddress(&p, g_M1h); __half* M1h = (__half*)p;
    cudaGetSymbolAddress(&p, g_M1l); __half* M1l = (__half*)p;
    cudaGetSymbolAddress(&p, g_Oh);  __half* Oh  = (__half*)p;
    cudaGetSymbolAddress(&p, g_Ol);  __half* Ol  = (__half*)p;
    cudaGetSymbolAddress(&p, g_Qh);  __half* Qh  = (__half*)p;
    cudaGetSymbolAddress(&p, g_Ql);  __half* Ql  = (__half*)p;
    cudaGetSymbolAddress(&p, g_Kh);  __half* Kh  = (__half*)p;
    cudaGetSymbolAddress(&p, g_Kl);  __half* Kl  = (__half*)p;
    cudaGetSymbolAddress(&p, g_Vh);  __half* Vh  = (__half*)p;
    cudaGetSymbolAddress(&p, g_Vl);  __half* Vl  = (__half*)p;
    cudaGetSymbolAddress(&p, g_Wh);  Wh_p = (__half*)p;
    cudaGetSymbolAddress(&p, g_Wl);  Wl_p = (__half*)p;

    cudaFuncSetAttribute(hgemm_kernel<2,0>, cudaFuncAttributeMaxDynamicSharedMemorySize, HG2_SMEM);
    cudaFuncSetAttribute(hgemm_kernel<2,1>, cudaFuncAttributeMaxDynamicSharedMemorySize, HG2_SMEM);
    cudaFuncSetAttribute(hgemm_kernel<2,2>, cudaFuncAttributeMaxDynamicSharedMemorySize, HG2_SMEM);
    cudaFuncSetAttribute(hgemm_kernel<1,0>, cudaFuncAttributeMaxDynamicSharedMemorySize, HG1_SMEM);
    cudaFuncSetAttribute(fattn_kernel, cudaFuncAttributeMaxDynamicSharedMemorySize, FATTN_SMEM);

    // ---- weight conversion (batched) ----
    splitT4(t_wq, t_wk, t_wv, t_wo, OT_WQ, DD, DD, LT, 4);
    splitT4(t_w1, nullptr, nullptr, nullptr, OT_W1, DD, DFF, LT, 1);
    splitT4(t_w2, nullptr, nullptr, nullptr, OT_W2, DFF, DD, LT, 1);
    splitT4(cin_w, nullptr, nullptr, nullptr, OC_IN, DD, DC, CC, 1);
    splitT4(c_wq, c_wk, c_wv, c_wo, OC_WQ, DC, DC, CC*LC, 4);
    splitT4(c_w1, nullptr, nullptr, nullptr, OC_W1, DC, DFFC, CC*LC, 1);
    splitT4(c_w2, nullptr, nullptr, nullptr, OC_W2, DFFC, DC, CC*LC, 1);
    splitT4(m_wq, m_wk, m_wv, m_wo, OM_WQ, DC, DC, NM, 4);
    splitT4(oproj, nullptr, nullptr, nullptr, O_OP, DD, DD, 1, 1);
    split1_kernel<<<(BV*DD/4 + 255)/256, 256>>>(emb, Wh_p + O_EMB, BV*DD/4);

    embed_kernel<<<BT, 256>>>(X, emb, ids);

    // ---- trunk ----
    for (int l = 0; l < LT; l++) {
        rms_kernel<<<BT, 256>>>(X, t_n1 + (long)l*DD, Hh, Hl, DD, BT, 0);
        hgemm(0, 2, Hh, Hl, OT_WQ + (long)l*DD*DD, Q, 0, 0, BT, DD, DD, 0, nullptr, 1, 0,0,0,0);
        hgemm(0, 2, Hh, Hl, OT_WK + (long)l*DD*DD, Kb, 0, 0, BT, DD, DD, 0, nullptr, 1, 0,0,0,0);
        hgemm(1, 2, Hh, Hl, OT_WV + (long)l*DD*DD, 0, Vh, Vl, BT, DD, DD, 0, nullptr, 1, 0,0,0,0);
        rope_kernel<<<(BT*HT*32)/256, 256>>>(Q, Kb, Qh, Ql, Kh, Kl, TT, HT, DD, BT);
        fattn_kernel<<<dim3(TT/64, BB*HT, 1), 128, FATTN_SMEM>>>(
            Qh, Ql, Kh, Kl, Vh, Vl, Oh, Ol, TT, HT, DD, 0);
        hgemm(0, 2, Oh, Ol, OT_WO + (long)l*DD*DD, X, 0, 0, BT, DD, DD, 1, nullptr, 1, 0,0,0,0);
        rms_kernel<<<BT, 256>>>(X, t_n2 + (long)l*DD, Hh, Hl, DD, BT, 0);
        hgemm(2, 2, Hh, Hl, OT_W1 + (long)l*DD*DFF, 0, M1h, M1l, BT, DFF, DD, 0, nullptr, 1, 0,0,0,0);
        hgemm(0, 2, M1h, M1l, OT_W2 + (long)l*DFF*DD, X, 0, 0, BT, DD, DFF, 1, nullptr, 1, 0,0,0,0);
    }

    // ---- column projection ----
    split2_kernel<<<(BT*DD/4)/256, 256>>>(X, Hh, Hl, BT*DD/4);
    hgemm(0, 2, Hh, Hl, OC_IN, CS, 0, 0, BT, DC, DD, 0, cin_b, CC, 0, (long)DD*DC, (long)BT*DC, DC);

    // ---- column layers ----
    for (int l = 0; l < LC; l++) {
        rms_kernel<<<CBT, 256>>>(CS, c_n1 + (long)l*DC, Hh, Hl, DC, BT, (long)LC*DC);
        hgemm(0, 2, Hh, Hl, OC_WQ + (long)l*DC*DC, Q, 0, 0, BT, DC, DC, 0, nullptr, CC,
              (long)BT*DC, (long)LC*DC*DC, (long)BT*DC, 0);
        hgemm(0, 2, Hh, Hl, OC_WK + (long)l*DC*DC, Kb, 0, 0, BT, DC, DC, 0, nullptr, CC,
              (long)BT*DC, (long)LC*DC*DC, (long)BT*DC, 0);
        hgemm(1, 2, Hh, Hl, OC_WV + (long)l*DC*DC, 0, Vh, Vl, BT, DC, DC, 0, nullptr, CC,
              (long)BT*DC, (long)LC*DC*DC, (long)BT*DC, 0);
        rope_kernel<<<(CBT*HC*32)/256, 256>>>(Q, Kb, Qh, Ql, Kh, Kl, TT, HC, DC, CBT);
        fattn_kernel<<<dim3(TT/64, BB*HC, CC), 128, FATTN_SMEM>>>(
            Qh, Ql, Kh, Kl, Vh, Vl, Oh, Ol, TT, HC, DC, (long)BT*DC);
        hgemm(0, 2, Oh, Ol, OC_WO + (long)l*DC*DC, CS, 0, 0, BT, DC, DC, 1, nullptr, CC,
              (long)BT*DC, (long)LC*DC*DC, (long)BT*DC, 0);
        rms_kernel<<<CBT, 256>>>(CS, c_n2 + (long)l*DC, Hh, Hl, DC, BT, (long)LC*DC);
        hgemm(2, 2, Hh, Hl, OC_W1 + (long)l*DC*DFFC, 0, M1h, M1l, BT, DFFC, DC, 0, nullptr, CC,
              (long)BT*DC, (long)LC*DC*DFFC, (long)BT*DFFC, 0);
        hgemm(0, 2, M1h, M1l, OC_W2 + (long)l*DFFC*DC, CS, 0, 0, BT, DC, DFFC, 1, nullptr, CC,
              (long)BT*DFFC, (long)LC*DFFC*DC, (long)BT*DC, 0);

        if (((l + 1) & 1) == 0) {
            int m = (l + 1)/2 - 1;
            rms_kernel<<<CBT, 256>>>(CS, m_n + (long)m*DC, Hh, Hl, DC, CBT, 0);
            hgemm(0, 2, Hh, Hl, OM_WQ + (long)m*DC*DC, Q, 0, 0, CBT, DC, DC, 0, nullptr, 1, 0,0,0,0);
            hgemm(0, 2, Hh, Hl, OM_WK + (long)m*DC*DC, Kb, 0, 0, CBT, DC, DC, 0, nullptr, 1, 0,0,0,0);
            hgemm(0, 2, Hh, Hl, OM_WV + (long)m*DC*DC, Vb, 0, 0, CBT, DC, DC, 0, nullptr, 1, 0,0,0,0);
            merge_attn_kernel<<<(CC*BT*HC)/256, 256>>>(Q, Kb, Vb, Oh, Ol);
            hgemm(0, 2, Oh, Ol, OM_WO + (long)m*DC*DC, CS, 0, 0, CBT, DC, DC, 1, nullptr, 1, 0,0,0,0);
        }
    }

    // ---- output head ----
    comb_kernel<<<(BT*DD/4)/256, 256>>>(CS, Hh, Hl);
    hgemm(0, 2, Hh, Hl, O_OP, Q, 0, 0, BT, DD, DD, 0, nullptr, 1, 0,0,0,0);
    rms_kernel<<<BT, 256>>>(Q, fnorm, Hh, Hl, DD, BT, 0);
    hgemm(0, 1, Hh, nullptr, O_EMB, out, 0, 0, BT, BV, DD, 0, nullptr, 1, 0,0,0,0);
}

// round 10
// speedup vs baseline: 1.0624x; 1.0016x over previous
#include <cuda_runtime.h>
#include <cuda_fp16.h>
#include <math.h>
#include <stdint.h>

// ---------------- model constants ----------------
#define BV   32000
#define DD   1024
#define DFF  4096
#define LT   2
#define HT   16
#define CC   4
#define DC   256
#define DFFC 1024
#define LC   4
#define HC   4
#define NM   2
#define BB   2
#define TT   1024
#define BT   (BB*TT)     // 2048
#define CBT  (CC*BT)     // 8192

// ---------------- weight offsets ([N][K] fp16; QKV interleaved per layer) ----------------
constexpr long OT_QKV = 0;
constexpr long OT_WO  = OT_QKV + (long)LT*3*DD*DD;
constexpr long OT_W1  = OT_WO  + (long)LT*DD*DD;
constexpr long OT_W2  = OT_W1  + (long)LT*DD*DFF;
constexpr long OC_IN  = OT_W2  + (long)LT*DFF*DD;
constexpr long OC_QKV = OC_IN  + (long)CC*DD*DC;
constexpr long OC_WO  = OC_QKV + (long)CC*LC*3*DC*DC;
constexpr long OC_W1  = OC_WO  + (long)CC*LC*DC*DC;
constexpr long OC_W2  = OC_W1  + (long)CC*LC*DC*DFFC;
constexpr long OM_QKV = OC_W2  + (long)CC*LC*DFFC*DC;
constexpr long OM_WO  = OM_QKV + (long)NM*3*DC*DC;
constexpr long O_OP   = OM_WO  + (long)NM*DC*DC;
constexpr long O_EMB  = O_OP   + (long)DD*DD;
constexpr long WTOT   = O_EMB  + (long)BV*DD;

// ---------------- scratch (device globals) ----------------
__device__ float  g_X [BT*DD];
__device__ float  g_Q [BT*DD];
__device__ float  g_K [BT*DD];
__device__ float  g_V [BT*DD];
__device__ float  g_CS[CC*BT*DC];
__device__ __half g_Hh[BT*DD];
__device__ __half g_Hl[BT*DD];
__device__ __half g_M1h[BT*DFF];
__device__ __half g_M1l[BT*DFF];
__device__ __half g_Oh[BT*DD];
__device__ __half g_Ol[BT*DD];
__device__ __half g_Qh[BT*DD];
__device__ __half g_Ql[BT*DD];
__device__ __half g_Kh[BT*DD];
__device__ __half g_Kl[BT*DD];
__device__ __half g_Vh[BT*DD];
__device__ __half g_Vl[BT*DD];
__device__ __half g_Wh[WTOT];
__device__ __half g_Wl[WTOT];

// ---------------- asm helpers ----------------
__device__ __forceinline__ void lm4(const __half* p, uint32_t* r)
{
    uint32_t a = (uint32_t)__cvta_generic_to_shared(p);
    asm volatile("ldmatrix.sync.aligned.m8n8.x4.shared.b16 {%0,%1,%2,%3}, [%4];"
        : "=r"(r[0]), "=r"(r[1]), "=r"(r[2]), "=r"(r[3]) : "r"(a));
}
__device__ __forceinline__ void lm4t(const __half* p, uint32_t* r)
{
    uint32_t a = (uint32_t)__cvta_generic_to_shared(p);
    asm volatile("ldmatrix.sync.aligned.m8n8.x4.trans.shared.b16 {%0,%1,%2,%3}, [%4];"
        : "=r"(r[0]), "=r"(r[1]), "=r"(r[2]), "=r"(r[3]) : "r"(a));
}
__device__ __forceinline__ void mma16816(float* c, const uint32_t* a, const uint32_t* b)
{
    asm volatile("mma.sync.aligned.m16n8k16.row.col.f32.f16.f16.f32 "
        "{%0,%1,%2,%3},{%4,%5,%6,%7},{%8,%9},{%0,%1,%2,%3};"
        : "+f"(c[0]), "+f"(c[1]), "+f"(c[2]), "+f"(c[3])
        : "r"(a[0]), "r"(a[1]), "r"(a[2]), "r"(a[3]), "r"(b[0]), "r"(b[1]));
}
__device__ __forceinline__ void cpasync16(const __half* dst, const __half* src)
{
    uint32_t d = (uint32_t)__cvta_generic_to_shared(dst);
    asm volatile("cp.async.cg.shared.global [%0], [%1], 16;" :: "r"(d), "l"(src));
}
__device__ __forceinline__ void cp_commit() { asm volatile("cp.async.commit_group;"); }
template<int N> __device__ __forceinline__ void cp_wait()
{ asm volatile("cp.async.wait_group %0;" :: "n"(N)); }

__device__ __forceinline__ float gelu1(float v)
{
    return 0.5f * v * (1.f + tanhf(0.7978845608028654f * (v + 0.044715f*v*v*v)));
}
__device__ __forceinline__ void split_store(__half* oh, __half* ol, long idx, float v)
{
    __half h = __float2half(v);
    oh[idx] = h;
    ol[idx] = __float2half(v - __half2float(h));
}

// ---------------- HGEMM (cp.async double-buffered, champion mainloop) ----------------
#define BM 128
#define BN 128
#define BKH 32
#define SSTR 40
#define GPER (BM*SSTR)

template<int NT, int MODE>
__global__ void __launch_bounds__(256) hgemm_kernel(
    const __half* __restrict__ Ah, const __half* __restrict__ Al,
    const __half* __restrict__ Bh, const __half* __restrict__ Bl,
    const float* __restrict__ bias, float* __restrict__ C,
    __half* __restrict__ Coh, __half* __restrict__ Col,
    int M, int N, int K, int accum,
    long aBS, long bBS, long cBS, long biasBS,
    float* __restrict__ Ck, float* __restrict__ Cv)
{
    extern __shared__ __half smp[];
    const int NARR = (NT == 2) ? 4 : 2;

    Ah += blockIdx.z * aBS;
    Bh += blockIdx.z * bBS;
    if (MODE == 0) C += blockIdx.z * cBS;
    else if (MODE == 3) {
        C += blockIdx.z * cBS;
        if (Ck)  Ck  += blockIdx.z * cBS;
        if (Cv)  Cv  += blockIdx.z * cBS;
        if (Coh) { Coh += blockIdx.z * cBS; Col += blockIdx.z * cBS; }
    } else { Coh += blockIdx.z * cBS; Col += blockIdx.z * cBS; }
    if (NT == 2) { Al += blockIdx.z * aBS; Bl += blockIdx.z * bBS; }
    if (bias) bias += blockIdx.z * biasBS;

    int row0 = blockIdx.y * BM;
    int col0 = blockIdx.x * BN;
    int tid  = threadIdx.x;
    int lane = tid & 31;
    int wid  = tid >> 5;
    int wm0  = (wid >> 2) * 64;
    int wn0  = (wid & 3) * 32;

    float acc[4][4][4];
#pragma unroll
    for (int mt = 0; mt < 4; mt++)
#pragma unroll
        for (int nt = 0; nt < 4; nt++)
#pragma unroll
            for (int q = 0; q < 4; q++) acc[mt][nt][q] = 0.f;

    int a_r  = lane & 15;
    int a_ko = (lane >> 4) << 3;
    int b_n  = ((lane >> 4) << 3) + (lane & 7);
    int b_ko = ((lane >> 3) & 1) << 3;

    int nk = K / BKH;

    auto loadStage = [&](int st, int k0) {
        __half* dAh = smp + st * NARR * GPER;
        __half* dBh = dAh + GPER;
        __half* dAl = dAh + 2 * GPER;
        __half* dBl = dAh + 3 * GPER;
#pragma unroll
        for (int c = tid; c < 512; c += 256) {
            int r = c >> 2, o = (c & 3) << 3;
            cpasync16(&dAh[r*SSTR + o], &Ah[(long)(row0 + r)*K + k0 + o]);
            cpasync16(&dBh[r*SSTR + o], &Bh[(long)(col0 + r)*K + k0 + o]);
            if (NT == 2) {
                cpasync16(&dAl[r*SSTR + o], &Al[(long)(row0 + r)*K + k0 + o]);
                cpasync16(&dBl[r*SSTR + o], &Bl[(long)(col0 + r)*K + k0 + o]);
            }
        }
    };

    loadStage(0, 0);
    cp_commit();

    for (int kt = 0; kt < nk; kt++) {
        int cur = kt & 1;
        if (kt + 1 < nk) {
            loadStage(cur ^ 1, (kt + 1) * BKH);
            cp_commit();
            cp_wait<1>();
        } else {
            cp_wait<0>();
        }
        __syncthreads();

        const __half* pAh = smp + cur * NARR * GPER;
        const __half* pBh = pAh + GPER;
        const __half* pAl = pAh + 2 * GPER;
        const __half* pBl = pAh + 3 * GPER;

#pragma unroll
        for (int ks = 0; ks < BKH; ks += 16) {
            uint32_t a_hi[4][4], b_hi[2][4];
#pragma unroll
            for (int mt = 0; mt < 4; mt++)
                lm4(&pAh[(wm0 + mt*16 + a_r)*SSTR + ks + a_ko], a_hi[mt]);
#pragma unroll
            for (int np = 0; np < 2; np++)
                lm4(&pBh[(wn0 + np*16 + b_n)*SSTR + ks + b_ko], b_hi[np]);
#pragma unroll
            for (int mt = 0; mt < 4; mt++)
#pragma unroll
                for (int nt = 0; nt < 4; nt++)
                    mma16816(acc[mt][nt], a_hi[mt], &b_hi[nt >> 1][(nt & 1)*2]);

            if (NT == 2) {
                uint32_t b_lo[2][4];
#pragma unroll
                for (int np = 0; np < 2; np++)
                    lm4(&pBl[(wn0 + np*16 + b_n)*SSTR + ks + b_ko], b_lo[np]);
#pragma unroll
                for (int mt = 0; mt < 4; mt++)
#pragma unroll
                    for (int nt = 0; nt < 4; nt++)
                        mma16816(acc[mt][nt], a_hi[mt], &b_lo[nt >> 1][(nt & 1)*2]);
                uint32_t a_lo[4][4];
#pragma unroll
                for (int mt = 0; mt < 4; mt++)
                    lm4(&pAl[(wm0 + mt*16 + a_r)*SSTR + ks + a_ko], a_lo[mt]);
#pragma unroll
                for (int mt = 0; mt < 4; mt++)
#pragma unroll
                    for (int nt = 0; nt < 4; nt++)
                        mma16816(acc[mt][nt], a_lo[mt], &b_hi[nt >> 1][(nt & 1)*2]);
            }
        }
        __syncthreads();
    }

    int g = lane >> 2, t = lane & 3;

    if (MODE == 3) {
        const int NW = N / 3;
        int sel = col0 / NW;
        int colb = col0 - sel*NW;
        float* Cf = (sel == 0) ? C : (sel == 1) ? Ck : Cv;
        bool dosplit = (sel == 2) && (Coh != nullptr);
#pragma unroll
        for (int mt = 0; mt < 4; mt++) {
#pragma unroll
            for (int nt = 0; nt < 4; nt++) {
                int r1  = row0 + wm0 + mt*16 + g;
                int cix = colb + wn0 + nt*8 + 2*t;
                float v00 = acc[mt][nt][0], v01 = acc[mt][nt][1];
                float v10 = acc[mt][nt][2], v11 = acc[mt][nt][3];
                long o0 = (long)r1*NW + cix;
                long o1 = (long)(r1 + 8)*NW + cix;
                if (dosplit) {
                    __half h00 = __float2half(v00), h01 = __float2half(v01);
                    __half h10 = __float2half(v10), h11 = __float2half(v11);
                    *(__half2*)&Coh[o0] = __halves2half2(h00, h01);
                    *(__half2*)&Coh[o1] = __halves2half2(h10, h11);
                    *(__half2*)&Col[o0] = __halves2half2(
                        __float2half(v00 - __half2float(h00)),
                        __float2half(v01 - __half2float(h01)));
                    *(__half2*)&Col[o1] = __halves2half2(
                        __float2half(v10 - __half2float(h10)),
                        __float2half(v11 - __half2float(h11)));
                } else {
                    *(float2*)&Cf[o0] = make_float2(v00, v01);
                    *(float2*)&Cf[o1] = make_float2(v10, v11);
                }
            }
        }
        return;
    }

#pragma unroll
    for (int mt = 0; mt < 4; mt++) {
#pragma unroll
        for (int nt = 0; nt < 4; nt++) {
            int r1  = row0 + wm0 + mt*16 + g;
            int cix = col0 + wn0 + nt*8 + 2*t;
            float bv0 = 0.f, bv1 = 0.f;
            if (bias) { bv0 = bias[cix]; bv1 = bias[cix + 1]; }
            float v00 = acc[mt][nt][0] + bv0, v01 = acc[mt][nt][1] + bv1;
            float v10 = acc[mt][nt][2] + bv0, v11 = acc[mt][nt][3] + bv1;
            long o0 = (long)r1*N + cix;
            long o1 = (long)(r1 + 8)*N + cix;
            if (MODE == 0) {
                if (accum) {
                    float2 p0 = *(float2*)&C[o0];
                    float2 p1 = *(float2*)&C[o1];
                    v00 += p0.x; v01 += p0.y;
                    v10 += p1.x; v11 += p1.y;
                }
                *(float2*)&C[o0] = make_float2(v00, v01);
                *(float2*)&C[o1] = make_float2(v10, v11);
            } else {
                if (MODE == 2) {
                    v00 = gelu1(v00); v01 = gelu1(v01);
                    v10 = gelu1(v10); v11 = gelu1(v11);
                }
                __half h00 = __float2half(v00), h01 = __float2half(v01);
                __half h10 = __float2half(v10), h11 = __float2half(v11);
                *(__half2*)&Coh[o0] = __halves2half2(h00, h01);
                *(__half2*)&Coh[o1] = __halves2half2(h10, h11);
                *(__half2*)&Col[o0] = __halves2half2(
                    __float2half(v00 - __half2float(h00)),
                    __float2half(v01 - __half2float(h01)));
                *(__half2*)&Col[o1] = __halves2half2(
                    __float2half(v10 - __half2float(h10)),
                    __float2half(v11 - __half2float(h11)));
            }
        }
    }
}

// ---------------- tensor-core flash attention (causal, hd=64) ----------------
#define ASTR 72
#define FATTN_SMEM (6*64*ASTR*2)

__global__ void __launch_bounds__(128) fattn_kernel(
    const __half* __restrict__ Qh, const __half* __restrict__ Ql,
    const __half* __restrict__ Kh, const __half* __restrict__ Kl,
    const __half* __restrict__ Vh, const __half* __restrict__ Vl,
    __half* __restrict__ Oh, __half* __restrict__ Ol,
    int T, int nh, int rstride, long colstride)
{
    extern __shared__ __half sm[];
    __half* sQh = sm;
    __half* sQl = sQh + 64*ASTR;
    __half* sKh = sQl + 64*ASTR;
    __half* sKl = sKh + 64*ASTR;
    __half* sVh = sKl + 64*ASTR;
    __half* sVl = sVh + 64*ASTR;

    int qt = blockIdx.x;
    int b  = blockIdx.y / nh;
    int h  = blockIdx.y % nh;
    long base = (long)blockIdx.z * colstride + (long)h * 64;
    int q0  = qt * 64;
    int tid = threadIdx.x;
    int lane = tid & 31;
    int wid  = tid >> 5;
    int wrow = wid * 16;
    int g = lane >> 2, t4 = lane & 3;

#pragma unroll
    for (int c = tid; c < 512; c += 128) {
        int r = c >> 3, o = (c & 7) << 3;
        long src = base + (long)(b*T + q0 + r)*rstride + o;
        *(uint4*)&sQh[r*ASTR + o] = *(const uint4*)&Qh[src];
        *(uint4*)&sQl[r*ASTR + o] = *(const uint4*)&Ql[src];
    }
    __syncthreads();

    int a_r  = lane & 15;
    int a_ko = (lane >> 4) << 3;
    int b_n  = ((lane >> 4) << 3) + (lane & 7);
    int b_ko = ((lane >> 3) & 1) << 3;
    int v_r  = (((lane >> 3) & 1) << 3) + (lane & 7);
    int v_c  = (lane >> 4) << 3;

    uint32_t qfh[4][4], qfl[4][4];
#pragma unroll
    for (int ks = 0; ks < 4; ks++) {
        lm4(&sQh[(wrow + a_r)*ASTR + ks*16 + a_ko], qfh[ks]);
        lm4(&sQl[(wrow + a_r)*ASTR + ks*16 + a_ko], qfl[ks]);
    }

    float mrow[2] = {-1e30f, -1e30f};
    float lrow[2] = {0.f, 0.f};
    float oacc[8][4];
#pragma unroll
    for (int nt = 0; nt < 8; nt++)
#pragma unroll
        for (int e = 0; e < 4; e++) oacc[nt][e] = 0.f;

    for (int kt = 0; kt <= qt; kt++) {
        int k0 = kt * 64;
        __syncthreads();
#pragma unroll
        for (int c = tid; c < 512; c += 128) {
            int r = c >> 3, o = (c & 7) << 3;
            long src = base + (long)(b*T + k0 + r)*rstride + o;
            *(uint4*)&sKh[r*ASTR + o] = *(const uint4*)&Kh[src];
            *(uint4*)&sKl[r*ASTR + o] = *(const uint4*)&Kl[src];
            *(uint4*)&sVh[r*ASTR + o] = *(const uint4*)&Vh[src];
            *(uint4*)&sVl[r*ASTR + o] = *(const uint4*)&Vl[src];
        }
        __syncthreads();

        float S[8][4];
#pragma unroll
        for (int nt = 0; nt < 8; nt++)
#pragma unroll
            for (int e = 0; e < 4; e++) S[nt][e] = 0.f;

#pragma unroll
        for (int ks = 0; ks < 4; ks++) {
            uint32_t bh[4][4], bl[4][4];
#pragma unroll
            for (int np = 0; np < 4; np++) {
                lm4(&sKh[(np*16 + b_n)*ASTR + ks*16 + b_ko], bh[np]);
                lm4(&sKl[(np*16 + b_n)*ASTR + ks*16 + b_ko], bl[np]);
            }
#pragma unroll
            for (int np = 0; np < 4; np++)
#pragma unroll
                for (int j = 0; j < 2; j++) {
                    int nt = np*2 + j;
                    mma16816(S[nt], qfh[ks], &bh[np][j*2]);
                    mma16816(S[nt], qfh[ks], &bl[np][j*2]);
                    mma16816(S[nt], qfl[ks], &bh[np][j*2]);
                }
        }

#pragma unroll
        for (int nt = 0; nt < 8; nt++)
#pragma unroll
            for (int e = 0; e < 4; e++) {
                S[nt][e] *= 0.125f;
                if (kt == qt) {
                    int col = k0 + nt*8 + t4*2 + (e & 1);
                    int row = q0 + wrow + g + ((e >> 1) << 3);
                    if (col > row) S[nt][e] = -1e30f;
                }
            }

        float P[8][4];
#pragma unroll
        for (int r = 0; r < 2; r++) {
            float mx = -1e30f;
#pragma unroll
            for (int nt = 0; nt < 8; nt++) {
                mx = fmaxf(mx, S[nt][2*r + 0]);
                mx = fmaxf(mx, S[nt][2*r + 1]);
            }
            mx = fmaxf(mx, __shfl_xor_sync(0xffffffffu, mx, 1));
            mx = fmaxf(mx, __shfl_xor_sync(0xffffffffu, mx, 2));
            float mnew  = fmaxf(mrow[r], mx);
            float alpha = __expf(mrow[r] - mnew);
            float rsum = 0.f;
#pragma unroll
            for (int nt = 0; nt < 8; nt++) {
                float p0 = __expf(S[nt][2*r + 0] - mnew);
                float p1 = __expf(S[nt][2*r + 1] - mnew);
                P[nt][2*r + 0] = p0; P[nt][2*r + 1] = p1;
                rsum += p0 + p1;
            }
            rsum += __shfl_xor_sync(0xffffffffu, rsum, 1);
            rsum += __shfl_xor_sync(0xffffffffu, rsum, 2);
            lrow[r] = lrow[r]*alpha + rsum;
            mrow[r] = mnew;
#pragma unroll
            for (int nt = 0; nt < 8; nt++) {
                oacc[nt][2*r + 0] *= alpha;
                oacc[nt][2*r + 1] *= alpha;
            }
        }

        uint32_t pah[4][4], pal[4][4];
#pragma unroll
        for (int ks = 0; ks < 4; ks++) {
            int j0 = 2*ks, j1 = 2*ks + 1;
#pragma unroll
            for (int q = 0; q < 4; q++) {
                int jj = (q < 2) ? j0 : j1;
                int e0 = (q & 1) ? 2 : 0;
                float f0 = P[jj][e0], f1 = P[jj][e0 + 1];
                __half h0 = __float2half(f0), h1 = __float2half(f1);
                __half l0 = __float2half(f0 - __half2float(h0));
                __half l1 = __float2half(f1 - __half2float(h1));
                pah[ks][q] = (uint32_t)__half_as_ushort(h0) |
                             ((uint32_t)__half_as_ushort(h1) << 16);
                pal[ks][q] = (uint32_t)__half_as_ushort(l0) |
                             ((uint32_t)__half_as_ushort(l1) << 16);
            }
        }

#pragma unroll
        for (int ks = 0; ks < 4; ks++) {
            uint32_t vh[4][4], vl[4][4];
#pragma unroll
            for (int np = 0; np < 4; np++) {
                lm4t(&sVh[(ks*16 + v_r)*ASTR + np*16 + v_c], vh[np]);
                lm4t(&sVl[(ks*16 + v_r)*ASTR + np*16 + v_c], vl[np]);
            }
#pragma unroll
            for (int np = 0; np < 4; np++)
#pragma unroll
                for (int j = 0; j < 2; j++) {
                    int nt = np*2 + j;
                    mma16816(oacc[nt], pah[ks], &vh[np][j*2]);
                    mma16816(oacc[nt], pah[ks], &vl[np][j*2]);
                    mma16816(oacc[nt], pal[ks], &vh[np][j*2]);
                }
        }
    }

#pragma unroll
    for (int r = 0; r < 2; r++) {
        float inv = 1.f / lrow[r];
        int row = q0 + wrow + g + r*8;
        long ob = base + (long)(b*T + row)*rstride;
#pragma unroll
        for (int nt = 0; nt < 8; nt++) {
            float v0 = oacc[nt][2*r + 0] * inv;
            float v1 = oacc[nt][2*r + 1] * inv;
            __half h0 = __float2half(v0), h1 = __float2half(v1);
            __half l0 = __float2half(v0 - __half2float(h0));
            __half l1 = __float2half(v1 - __half2float(h1));
            int col = nt*8 + t4*2;
            *(__half2*)&Oh[ob + col] = __halves2half2(h0, h1);
            *(__half2*)&Ol[ob + col] = __halves2half2(l0, l1);
        }
    }
}

// ---------------- weight transpose + fp16 split ----------------
__global__ void splitT4_kernel(const float* p0, const float* p1,
                               const float* p2, const float* p3,
                               __half* __restrict__ oh, __half* __restrict__ ol,
                               int K, int N, int perBatch, int ngroups, int interleave)
{
    __shared__ float tile[32][33];
    const float* ps[4] = {p0, p1, p2, p3};
    int gsel = blockIdx.z / perBatch;
    int bz   = blockIdx.z % perBatch;
    const float* in = ps[gsel] + (long)bz * K * N;
    long ob = (interleave ? (long)(bz*ngroups + gsel) : (long)blockIdx.z) * K * N;
    int n0 = blockIdx.x * 32, k0 = blockIdx.y * 32;
    int tx = threadIdx.x & 31, ty = threadIdx.x >> 5;
#pragma unroll
    for (int j = 0; j < 4; j++) {
        int r = ty*4 + j;
        tile[r][tx] = in[(long)(k0 + r)*N + n0 + tx];
    }
    __syncthreads();
#pragma unroll
    for (int j = 0; j < 4; j++) {
        int nn = ty*4 + j;
        float v = tile[tx][nn];
        __half h = __float2half(v);
        long o = ob + (long)(n0 + nn)*K + k0 + tx;
        oh[o] = h;
        ol[o] = __float2half(v - __half2float(h));
    }
}

__global__ void split1_kernel(const float* __restrict__ in, __half* __restrict__ oh, int n4)
{
    int i = blockIdx.x * blockDim.x + threadIdx.x;
    if (i >= n4) return;
    float4 v = ((const float4*)in)[i];
    oh[4*i + 0] = __float2half(v.x);
    oh[4*i + 1] = __float2half(v.y);
    oh[4*i + 2] = __float2half(v.z);
    oh[4*i + 3] = __float2half(v.w);
}

__global__ void split2_kernel(const float* __restrict__ in, __half* __restrict__ oh,
                              __half* __restrict__ ol, int n4)
{
    int i = blockIdx.x * blockDim.x + threadIdx.x;
    if (i >= n4) return;
    float4 v = ((const float4*)in)[i];
    split_store(oh, ol, 4L*i + 0, v.x);
    split_store(oh, ol, 4L*i + 1, v.y);
    split_store(oh, ol, 4L*i + 2, v.z);
    split_store(oh, ol, 4L*i + 3, v.w);
}

// ---------------- rmsnorm -> fp16 hi/lo ----------------
__global__ void rms_kernel(const float* __restrict__ x, const float* __restrict__ w,
                           __half* __restrict__ oh, __half* __restrict__ ol,
                           int W, int rowsPerChunk, long wStride)
{
    int row = blockIdx.x;
    const float* xr = x + (long)row * W;
    const float* wr = w + (long)(row / rowsPerChunk) * wStride;
    float ss = 0.f;
    for (int i = threadIdx.x; i < W; i += 256) {
        float v = xr[i];
        ss += v * v;
    }
    __shared__ float red[8];
#pragma unroll
    for (int off = 16; off > 0; off >>= 1)
        ss += __shfl_xor_sync(0xffffffffu, ss, off);
    if ((threadIdx.x & 31) == 0) red[threadIdx.x >> 5] = ss;
    __syncthreads();
    float tot = red[0]+red[1]+red[2]+red[3]+red[4]+red[5]+red[6]+red[7];
    float inv = rsqrtf(tot / (float)W + 1e-6f);
    long rb = (long)row * W;
    for (int i = threadIdx.x; i < W; i += 256)
        split_store(oh, ol, rb + i, xr[i] * inv * wr[i]);
}

// ---------------- rope ----------------
__global__ void rope_kernel(const float* __restrict__ q, const float* __restrict__ k,
                            __half* __restrict__ qh, __half* __restrict__ ql,
                            __half* __restrict__ kh, __half* __restrict__ kl,
                            int T, int nh, int rstride, int nrows)
{
    int idx = blockIdx.x * blockDim.x + threadIdx.x;
    if (idx >= nrows * nh * 32) return;
    int i   = idx & 31;
    int h   = (idx >> 5) % nh;
    int row = idx / (32 * nh);
    int t   = row % T;
    float inv = __expf(-(float)(2*i) * (1.f/64.f) * 9.210340371976184f);
    float f = (float)t * inv;
    float s, c;
    sincosf(f, &s, &c);
    long bo = (long)row * rstride + h*64 + i;
    float q1 = q[bo], q2 = q[bo + 32];
    split_store(qh, ql, bo,      q1*c - q2*s);
    split_store(qh, ql, bo + 32, q2*c + q1*s);
    float k1 = k[bo], k2 = k[bo + 32];
    split_store(kh, kl, bo,      k1*c - k2*s);
    split_store(kh, kl, bo + 32, k2*c + k1*s);
}

// ---------------- embedding gather ----------------
__global__ void embed_kernel(float* __restrict__ X, const float* __restrict__ emb,
                             const int* __restrict__ ids)
{
    int row = blockIdx.x;
    int id  = ids[row];
    const float4* src = (const float4*)(emb + (long)id * DD);
    float4* dst = (float4*)(X + (long)row * DD);
    dst[threadIdx.x] = src[threadIdx.x];
}

// ---------------- cross-column merge attention ----------------
__global__ void merge_attn_kernel(const float* __restrict__ Qm, const float* __restrict__ Km,
                                  const float* __restrict__ Vm,
                                  __half* __restrict__ Oh, __half* __restrict__ Ol)
{
    int gid = blockIdx.x * blockDim.x + threadIdx.x;
    int h   = gid & 3;
    int row = (gid >> 2) & (BT - 1);
    int i   = gid >> 13;
    if (i >= CC) return;
    long base  = (long)row * DC + h*64;
    long cstep = (long)BT * DC;

    float4 q[16];
    const float4* qp = (const float4*)(Qm + i*cstep + base);
#pragma unroll
    for (int t = 0; t < 16; t++) q[t] = qp[t];

    float s[CC];
#pragma unroll
    for (int j = 0; j < CC; j++) {
        const float4* kp = (const float4*)(Km + j*cstep + base);
        float acc = 0.f;
#pragma unroll
        for (int t = 0; t < 16; t++) {
            float4 kv = kp[t];
            acc += q[t].x*kv.x + q[t].y*kv.y + q[t].z*kv.z + q[t].w*kv.w;
        }
        s[j] = acc * 0.125f;
    }
    float mm = fmaxf(fmaxf(s[0], s[1]), fmaxf(s[2], s[3]));
    float a[CC], sum = 0.f;
#pragma unroll
    for (int j = 0; j < CC; j++) { a[j] = __expf(s[j] - mm); sum += a[j]; }
    float isum = 1.f / sum;
#pragma unroll
    for (int j = 0; j < CC; j++) a[j] *= isum;

    float o[64];
#pragma unroll
    for (int t = 0; t < 64; t++) o[t] = 0.f;
#pragma unroll
    for (int j = 0; j < CC; j++) {
        const float4* vp = (const float4*)(Vm + j*cstep + base);
        float aj = a[j];
#pragma unroll
        for (int t = 0; t < 16; t++) {
            float4 vv = vp[t];
            o[4*t+0] = fmaf(aj, vv.x, o[4*t+0]);
            o[4*t+1] = fmaf(aj, vv.y, o[4*t+1]);
            o[4*t+2] = fmaf(aj, vv.z, o[4*t+2]);
            o[4*t+3] = fmaf(aj, vv.w, o[4*t+3]);
        }
    }
    long ob = i*cstep + base;
#pragma unroll
    for (int t = 0; t < 64; t++) split_store(Oh, Ol, ob + t, o[t]);
}

// ---------------- concat ----------------
__global__ void comb_kernel(const float* __restrict__ cs, __half* __restrict__ oh,
                            __half* __restrict__ ol)
{
    int gid = blockIdx.x * blockDim.x + threadIdx.x;
    int d4  = gid & (DD/4 - 1);
    int row = gid / (DD/4);
    int d = d4 * 4;
    int c = d >> 8;
    int e = d & 255;
    float4 v = *(const float4*)(cs + (long)c*BT*DC + (long)row*DC + e);
    split_store(oh, ol, 4L*gid + 0, v.x);
    split_store(oh, ol, 4L*gid + 1, v.y);
    split_store(oh, ol, 4L*gid + 2, v.z);
    split_store(oh, ol, 4L*gid + 3, v.w);
}

// ---------------- host side ----------------
static __half *Wh_p, *Wl_p;
#define HG2_SMEM (2*4*GPER*2)
#define HG1_SMEM (2*2*GPER*2)

static inline void hgemm(int mode, int nt, const __half* Ah, const __half* Al, long boff,
                         float* C, __half* Coh, __half* Col,
                         int M, int N, int K, int accum, const float* bias, int batch,
                         long aBS, long bBS, long cBS, long biasBS)
{
    dim3 grid(N/BN, M/BM, batch);
    if (nt == 2) {
        if (mode == 0)
            hgemm_kernel<2,0><<<grid, 256, HG2_SMEM>>>(Ah, Al, Wh_p + boff, Wl_p + boff,
                bias, C, nullptr, nullptr, M, N, K, accum, aBS, bBS, cBS, biasBS,
                nullptr, nullptr);
        else if (mode == 1)
            hgemm_kernel<2,1><<<grid, 256, HG2_SMEM>>>(Ah, Al, Wh_p + boff, Wl_p + boff,
                bias, nullptr, Coh, Col, M, N, K, accum, aBS, bBS, cBS, biasBS,
                nullptr, nullptr);
        else
            hgemm_kernel<2,2><<<grid, 256, HG2_SMEM>>>(Ah, Al, Wh_p + boff, Wl_p + boff,
                bias, nullptr, Coh, Col, M, N, K, accum, aBS, bBS, cBS, biasBS,
                nullptr, nullptr);
    } else {
        hgemm_kernel<1,0><<<grid, 256, HG1_SMEM>>>(Ah, nullptr, Wh_p + boff, nullptr,
            bias, C, nullptr, nullptr, M, N, K, accum, aBS, bBS, cBS, biasBS,
            nullptr, nullptr);
    }
}

static inline void hgemm_qkv(const __half* Ah, const __half* Al, long boff,
                             float* Cq, float* Ck, float* Cv,
                             __half* Voh, __half* Vol,
                             int M, int N, int K, int batch,
                             long aBS, long bBS, long cBS)
{
    dim3 grid(N/BN, M/BM, batch);
    hgemm_kernel<2,3><<<grid, 256, HG2_SMEM>>>(Ah, Al, Wh_p + boff, Wl_p + boff,
        nullptr, Cq, Voh, Vol, M, N, K, 0, aBS, bBS, cBS, 0, Ck, Cv);
}

static inline void splitT4(const float* a, const float* b, const float* c, const float* d,
                           long off, int K, int N, int perBatch, int ngroups, int interleave)
{
    splitT4_kernel<<<dim3(N/32, K/32, ngroups*perBatch), 256>>>(
        a, b, c, d, Wh_p + off, Wl_p + off, K, N, perBatch, ngroups, interleave);
}

extern "C" void kernel_launch(void* const* d_in, const int* in_sizes, int n_in,
                              void* d_out, int out_size)
{
    const int*   ids   = (const int*)d_in[0];
    const float* emb   = (const float*)d_in[1];
    const float* t_wq  = (const float*)d_in[2];
    const float* t_wk  = (const float*)d_in[3];
    const float* t_wv  = (const float*)d_in[4];
    const float* t_wo  = (const float*)d_in[5];
    const float* t_w1  = (const float*)d_in[6];
    const float* t_w2  = (const float*)d_in[7];
    const float* t_n1  = (const float*)d_in[8];
    const float* t_n2  = (const float*)d_in[9];
    const float* cin_w = (const float*)d_in[10];
    const float* cin_b = (const float*)d_in[11];
    const float* c_wq  = (const float*)d_in[12];
    const float* c_wk  = (const float*)d_in[13];
    const float* c_wv  = (const float*)d_in[14];
    const float* c_wo  = (const float*)d_in[15];
    const float* c_w1  = (const float*)d_in[16];
    const float* c_w2  = (const float*)d_in[17];
    const float* c_n1  = (const float*)d_in[18];
    const float* c_n2  = (const float*)d_in[19];
    const float* m_wq  = (const float*)d_in[20];
    const float* m_wk  = (const float*)d_in[21];
    const float* m_wv  = (const float*)d_in[22];
    const float* m_wo  = (const float*)d_in[23];
    const float* m_n   = (const float*)d_in[24];
    const float* oproj = (const float*)d_in[25];
    const float* fnorm = (const float*)d_in[26];
    float* out = (float*)d_out;

    void* p;
    cudaGetSymbolAddress(&p, g_X);   float*  X   = (float*)p;
    cudaGetSymbolAddress(&p, g_Q);   float*  Q   = (float*)p;
    cudaGetSymbolAddress(&p, g_K);   float*  Kb  = (float*)p;
    cudaGetSymbolAddress(&p, g_V);   float*  Vb  = (float*)p;
    cudaGetSymbolAddress(&p, g_CS);  float*  CS  = (float*)p;
    cudaGetSymbolAddress(&p, g_Hh);  __half* Hh  = (__half*)p;
    cudaGetSymbolAddress(&p, g_Hl);  __half* Hl  = (__half*)p;
    cudaGetSymbolAddress(&p, g_M1h); __half* M1h = (__half*)p;
    cudaGetSymbolAddress(&p, g_M1l); __half* M1l = (__half*)p;
    cudaGetSymbolAddress(&p, g_Oh);  __half* Oh  = (__half*)p;
    cudaGetSymbolAddress(&p, g_Ol);  __half* Ol  = (__half*)p;
    cudaGetSymbolAddress(&p, g_Qh);  __half* Qh  = (__half*)p;
    cudaGetSymbolAddress(&p, g_Ql);  __half* Ql  = (__half*)p;
    cudaGetSymbolAddress(&p, g_Kh);  __half* Kh  = (__half*)p;
    cudaGetSymbolAddress(&p, g_Kl);  __half* Kl  = (__half*)p;
    cudaGetSymbolAddress(&p, g_Vh);  __half* Vh  = (__half*)p;
    cudaGetSymbolAddress(&p, g_Vl);  __half* Vl  = (__half*)p;
    cudaGetSymbolAddress(&p, g_Wh);  Wh_p = (__half*)p;
    cudaGetSymbolAddress(&p, g_Wl);  Wl_p = (__half*)p;

    cudaFuncSetAttribute(hgemm_kernel<2,0>, cudaFuncAttributeMaxDynamicSharedMemorySize, HG2_SMEM);
    cudaFuncSetAttribute(hgemm_kernel<2,1>, cudaFuncAttributeMaxDynamicSharedMemorySize, HG2_SMEM);
    cudaFuncSetAttribute(hgemm_kernel<2,2>, cudaFuncAttributeMaxDynamicSharedMemorySize, HG2_SMEM);
    cudaFuncSetAttribute(hgemm_kernel<2,3>, cudaFuncAttributeMaxDynamicSharedMemorySize, HG2_SMEM);
    cudaFuncSetAttribute(hgemm_kernel<1,0>, cudaFuncAttributeMaxDynamicSharedMemorySize, HG1_SMEM);
    cudaFuncSetAttribute(fattn_kernel, cudaFuncAttributeMaxDynamicSharedMemorySize, FATTN_SMEM);

    // ---- weight conversion (batched; QKV interleaved per layer) ----
    splitT4(t_wq, t_wk, t_wv, nullptr, OT_QKV, DD, DD, LT, 3, 1);
    splitT4(t_wo, nullptr, nullptr, nullptr, OT_WO, DD, DD, LT, 1, 0);
    splitT4(t_w1, nullptr, nullptr, nullptr, OT_W1, DD, DFF, LT, 1, 0);
    splitT4(t_w2, nullptr, nullptr, nullptr, OT_W2, DFF, DD, LT, 1, 0);
    splitT4(cin_w, nullptr, nullptr, nullptr, OC_IN, DD, DC, CC, 1, 0);
    splitT4(c_wq, c_wk, c_wv, nullptr, OC_QKV, DC, DC, CC*LC, 3, 1);
    splitT4(c_wo, nullptr, nullptr, nullptr, OC_WO, DC, DC, CC*LC, 1, 0);
    splitT4(c_w1, nullptr, nullptr, nullptr, OC_W1, DC, DFFC, CC*LC, 1, 0);
    splitT4(c_w2, nullptr, nullptr, nullptr, OC_W2, DFFC, DC, CC*LC, 1, 0);
    splitT4(m_wq, m_wk, m_wv, nullptr, OM_QKV, DC, DC, NM, 3, 1);
    splitT4(m_wo, nullptr, nullptr, nullptr, OM_WO, DC, DC, NM, 1, 0);
    splitT4(oproj, nullptr, nullptr, nullptr, O_OP, DD, DD, 1, 1, 0);
    split1_kernel<<<(BV*DD/4 + 255)/256, 256>>>(emb, Wh_p + O_EMB, BV*DD/4);

    embed_kernel<<<BT, 256>>>(X, emb, ids);

    // ---- trunk ----
    for (int l = 0; l < LT; l++) {
        rms_kernel<<<BT, 256>>>(X, t_n1 + (long)l*DD, Hh, Hl, DD, BT, 0);
        hgemm_qkv(Hh, Hl, OT_QKV + (long)l*3*DD*DD, Q, Kb, nullptr, Vh, Vl,
                  BT, 3*DD, DD, 1, 0, 0, 0);
        rope_kernel<<<(BT*HT*32)/256, 256>>>(Q, Kb, Qh, Ql, Kh, Kl, TT, HT, DD, BT);
        fattn_kernel<<<dim3(TT/64, BB*HT, 1), 128, FATTN_SMEM>>>(
            Qh, Ql, Kh, Kl, Vh, Vl, Oh, Ol, TT, HT, DD, 0);
        hgemm(0, 2, Oh, Ol, OT_WO + (long)l*DD*DD, X, 0, 0, BT, DD, DD, 1, nullptr, 1, 0,0,0,0);
        rms_kernel<<<BT, 256>>>(X, t_n2 + (long)l*DD, Hh, Hl, DD, BT, 0);
        hgemm(2, 2, Hh, Hl, OT_W1 + (long)l*DD*DFF, 0, M1h, M1l, BT, DFF, DD, 0, nullptr, 1, 0,0,0,0);
        hgemm(0, 2, M1h, M1l, OT_W2 + (long)l*DFF*DD, X, 0, 0, BT, DD, DFF, 1, nullptr, 1, 0,0,0,0);
    }

    // ---- column projection ----
    split2_kernel<<<(BT*DD/4)/256, 256>>>(X, Hh, Hl, BT*DD/4);
    hgemm(0, 2, Hh, Hl, OC_IN, CS, 0, 0, BT, DC, DD, 0, cin_b, CC, 0, (long)DD*DC, (long)BT*DC, DC);

    // ---- column layers ----
    for (int l = 0; l < LC; l++) {
        rms_kernel<<<CBT, 256>>>(CS, c_n1 + (long)l*DC, Hh, Hl, DC, BT, (long)LC*DC);
        hgemm_qkv(Hh, Hl, OC_QKV + (long)l*3*DC*DC, Q, Kb, nullptr, Vh, Vl,
                  BT, 3*DC, DC, CC, (long)BT*DC, (long)LC*3*DC*DC, (long)BT*DC);
        rope_kernel<<<(CBT*HC*32)/256, 256>>>(Q, Kb, Qh, Ql, Kh, Kl, TT, HC, DC, CBT);
        fattn_kernel<<<dim3(TT/64, BB*HC, CC), 128, FATTN_SMEM>>>(
            Qh, Ql, Kh, Kl, Vh, Vl, Oh, Ol, TT, HC, DC, (long)BT*DC);
        hgemm(0, 2, Oh, Ol, OC_WO + (long)l*DC*DC, CS, 0, 0, BT, DC, DC, 1, nullptr, CC,
              (long)BT*DC, (long)LC*DC*DC, (long)BT*DC, 0);
        rms_kernel<<<CBT, 256>>>(CS, c_n2 + (long)l*DC, Hh, Hl, DC, BT, (long)LC*DC);
        hgemm(2, 2, Hh, Hl, OC_W1 + (long)l*DC*DFFC, 0, M1h, M1l, BT, DFFC, DC, 0, nullptr, CC,
              (long)BT*DC, (long)LC*DC*DFFC, (long)BT*DFFC, 0);
        hgemm(0, 2, M1h, M1l, OC_W2 + (long)l*DFFC*DC, CS, 0, 0, BT, DC, DFFC, 1, nullptr, CC,
              (long)BT*DFFC, (long)LC*DFFC*DC, (long)BT*DC, 0);

        if (((l + 1) & 1) == 0) {
            int m = (l + 1)/2 - 1;
            rms_kernel<<<CBT, 256>>>(CS, m_n + (long)m*DC, Hh, Hl, DC, CBT, 0);
            hgemm_qkv(Hh, Hl, OM_QKV + (long)m*3*DC*DC, Q, Kb, Vb, nullptr, nullptr,
                      CBT, 3*DC, DC, 1, 0, 0, 0);
            merge_attn_kernel<<<(CC*BT*HC)/256, 256>>>(Q, Kb, Vb, Oh, Ol);
            hgemm(0, 2, Oh, Ol, OM_WO + (long)m*DC*DC, CS, 0, 0, CBT, DC, DC, 1, nullptr, 1, 0,0,0,0);
        }
    }

    // ---- output head ----
    comb_kernel<<<(BT*DD/4)/256, 256>>>(CS, Hh, Hl);
    hgemm(0, 2, Hh, Hl, O_OP, Q, 0, 0, BT, DD, DD, 0, nullptr, 1, 0,0,0,0);
    rms_kernel<<<BT, 256>>>(Q, fnorm, Hh, Hl, DD, BT, 0);
    hgemm(0, 1, Hh, nullptr, O_EMB, out, 0, 0, BT, BV, DD, 0, nullptr, 1, 0,0,0,0);
}

// round 11
// speedup vs baseline: 1.2464x; 1.1732x over previous
#include <cuda_runtime.h>
#include <cuda_fp16.h>
#include <math.h>
#include <stdint.h>

// ---------------- model constants ----------------
#define BV   32000
#define DD   1024
#define DFF  4096
#define LT   2
#define HT   16
#define CC   4
#define DC   256
#define DFFC 1024
#define LC   4
#define HC   4
#define NM   2
#define BB   2
#define TT   1024
#define BT   (BB*TT)     // 2048
#define CBT  (CC*BT)     // 8192

// ---------------- weight offsets ([N][K] fp16; QKV interleaved per layer) ----------------
constexpr long OT_QKV = 0;
constexpr long OT_WO  = OT_QKV + (long)LT*3*DD*DD;
constexpr long OT_W1  = OT_WO  + (long)LT*DD*DD;
constexpr long OT_W2  = OT_W1  + (long)LT*DD*DFF;
constexpr long OC_IN  = OT_W2  + (long)LT*DFF*DD;
constexpr long OC_QKV = OC_IN  + (long)CC*DD*DC;
constexpr long OC_WO  = OC_QKV + (long)CC*LC*3*DC*DC;
constexpr long OC_W1  = OC_WO  + (long)CC*LC*DC*DC;
constexpr long OC_W2  = OC_W1  + (long)CC*LC*DC*DFFC;
constexpr long OM_QKV = OC_W2  + (long)CC*LC*DFFC*DC;
constexpr long OM_WO  = OM_QKV + (long)NM*3*DC*DC;
constexpr long O_OP   = OM_WO  + (long)NM*DC*DC;
constexpr long O_EMB  = O_OP   + (long)DD*DD;
constexpr long WTOT   = O_EMB  + (long)BV*DD;

// ---------------- scratch (device globals) ----------------
__device__ float  g_X [BT*DD];
__device__ float  g_Q [BT*DD];
__device__ float  g_K [BT*DD];
__device__ float  g_V [BT*DD];
__device__ float  g_CS[CC*BT*DC];
__device__ __half g_Hh[BT*DD];
__device__ __half g_Hl[BT*DD];
__device__ __half g_M1h[BT*DFF];
__device__ __half g_M1l[BT*DFF];
__device__ __half g_Oh[BT*DD];
__device__ __half g_Ol[BT*DD];
__device__ __half g_Qh[BT*DD];
__device__ __half g_Ql[BT*DD];
__device__ __half g_Kh[BT*DD];
__device__ __half g_Kl[BT*DD];
__device__ __half g_Vh[BT*DD];
__device__ __half g_Vl[BT*DD];
__device__ __half g_Wh[WTOT];
__device__ __half g_Wl[WTOT];

// ---------------- asm helpers ----------------
__device__ __forceinline__ void lm4(const __half* p, uint32_t* r)
{
    uint32_t a = (uint32_t)__cvta_generic_to_shared(p);
    asm volatile("ldmatrix.sync.aligned.m8n8.x4.shared.b16 {%0,%1,%2,%3}, [%4];"
        : "=r"(r[0]), "=r"(r[1]), "=r"(r[2]), "=r"(r[3]) : "r"(a));
}
__device__ __forceinline__ void lm4t(const __half* p, uint32_t* r)
{
    uint32_t a = (uint32_t)__cvta_generic_to_shared(p);
    asm volatile("ldmatrix.sync.aligned.m8n8.x4.trans.shared.b16 {%0,%1,%2,%3}, [%4];"
        : "=r"(r[0]), "=r"(r[1]), "=r"(r[2]), "=r"(r[3]) : "r"(a));
}
__device__ __forceinline__ void mma16816(float* c, const uint32_t* a, const uint32_t* b)
{
    asm volatile("mma.sync.aligned.m16n8k16.row.col.f32.f16.f16.f32 "
        "{%0,%1,%2,%3},{%4,%5,%6,%7},{%8,%9},{%0,%1,%2,%3};"
        : "+f"(c[0]), "+f"(c[1]), "+f"(c[2]), "+f"(c[3])
        : "r"(a[0]), "r"(a[1]), "r"(a[2]), "r"(a[3]), "r"(b[0]), "r"(b[1]));
}
__device__ __forceinline__ void cpasync16(const __half* dst, const __half* src)
{
    uint32_t d = (uint32_t)__cvta_generic_to_shared(dst);
    asm volatile("cp.async.cg.shared.global [%0], [%1], 16;" :: "r"(d), "l"(src));
}
__device__ __forceinline__ void cp_commit() { asm volatile("cp.async.commit_group;"); }
template<int N> __device__ __forceinline__ void cp_wait()
{ asm volatile("cp.async.wait_group %0;" :: "n"(N)); }

__device__ __forceinline__ float gelu1(float v)
{
    return 0.5f * v * (1.f + tanhf(0.7978845608028654f * (v + 0.044715f*v*v*v)));
}
__device__ __forceinline__ void split_store(__half* oh, __half* ol, long idx, float v)
{
    __half h = __float2half(v);
    oh[idx] = h;
    ol[idx] = __float2half(v - __half2float(h));
}

// ---------------- HGEMM (cp.async double-buffered, champion mainloop) ----------------
// NT=2: A single fp16, B two-term (hh + h*lo) -> 2 MMA passes.
// NT=1: plain single-term.
// MODE 0: C fp32 (+accum+bias)  MODE 1: split hi/lo  MODE 2: gelu+split
// MODE 3: fused QKV (N = 3*NW): sel0->C fp32, sel1->Ck fp32, sel2->split or Cv fp32.
#define BM 128
#define BN 128
#define BKH 32
#define SSTR 40
#define GPER (BM*SSTR)

template<int NT, int MODE>
__global__ void __launch_bounds__(256) hgemm_kernel(
    const __half* __restrict__ Ah, const __half* __restrict__ Al,
    const __half* __restrict__ Bh, const __half* __restrict__ Bl,
    const float* __restrict__ bias, float* __restrict__ C,
    __half* __restrict__ Coh, __half* __restrict__ Col,
    int M, int N, int K, int accum,
    long aBS, long bBS, long cBS, long biasBS,
    float* __restrict__ Ck, float* __restrict__ Cv)
{
    extern __shared__ __half smp[];
    const int NARR = (NT == 2) ? 3 : 2;   // Ah, Bh, (Bl)

    Ah += blockIdx.z * aBS;
    Bh += blockIdx.z * bBS;
    if (MODE == 0) C += blockIdx.z * cBS;
    else if (MODE == 3) {
        C += blockIdx.z * cBS;
        if (Ck)  Ck  += blockIdx.z * cBS;
        if (Cv)  Cv  += blockIdx.z * cBS;
        if (Coh) { Coh += blockIdx.z * cBS; Col += blockIdx.z * cBS; }
    } else { Coh += blockIdx.z * cBS; Col += blockIdx.z * cBS; }
    if (NT == 2) Bl += blockIdx.z * bBS;
    if (bias) bias += blockIdx.z * biasBS;

    int row0 = blockIdx.y * BM;
    int col0 = blockIdx.x * BN;
    int tid  = threadIdx.x;
    int lane = tid & 31;
    int wid  = tid >> 5;
    int wm0  = (wid >> 2) * 64;
    int wn0  = (wid & 3) * 32;

    float acc[4][4][4];
#pragma unroll
    for (int mt = 0; mt < 4; mt++)
#pragma unroll
        for (int nt = 0; nt < 4; nt++)
#pragma unroll
            for (int q = 0; q < 4; q++) acc[mt][nt][q] = 0.f;

    int a_r  = lane & 15;
    int a_ko = (lane >> 4) << 3;
    int b_n  = ((lane >> 4) << 3) + (lane & 7);
    int b_ko = ((lane >> 3) & 1) << 3;

    int nk = K / BKH;

    auto loadStage = [&](int st, int k0) {
        __half* dAh = smp + st * NARR * GPER;
        __half* dBh = dAh + GPER;
        __half* dBl = dAh + 2 * GPER;
#pragma unroll
        for (int c = tid; c < 512; c += 256) {
            int r = c >> 2, o = (c & 3) << 3;
            cpasync16(&dAh[r*SSTR + o], &Ah[(long)(row0 + r)*K + k0 + o]);
            cpasync16(&dBh[r*SSTR + o], &Bh[(long)(col0 + r)*K + k0 + o]);
            if (NT == 2)
                cpasync16(&dBl[r*SSTR + o], &Bl[(long)(col0 + r)*K + k0 + o]);
        }
    };

    loadStage(0, 0);
    cp_commit();

    for (int kt = 0; kt < nk; kt++) {
        int cur = kt & 1;
        if (kt + 1 < nk) {
            loadStage(cur ^ 1, (kt + 1) * BKH);
            cp_commit();
            cp_wait<1>();
        } else {
            cp_wait<0>();
        }
        __syncthreads();

        const __half* pAh = smp + cur * NARR * GPER;
        const __half* pBh = pAh + GPER;
        const __half* pBl = pAh + 2 * GPER;

#pragma unroll
        for (int ks = 0; ks < BKH; ks += 16) {
            uint32_t a_hi[4][4], b_hi[2][4];
#pragma unroll
            for (int mt = 0; mt < 4; mt++)
                lm4(&pAh[(wm0 + mt*16 + a_r)*SSTR + ks + a_ko], a_hi[mt]);
#pragma unroll
            for (int np = 0; np < 2; np++)
                lm4(&pBh[(wn0 + np*16 + b_n)*SSTR + ks + b_ko], b_hi[np]);
#pragma unroll
            for (int mt = 0; mt < 4; mt++)
#pragma unroll
                for (int nt = 0; nt < 4; nt++)
                    mma16816(acc[mt][nt], a_hi[mt], &b_hi[nt >> 1][(nt & 1)*2]);

            if (NT == 2) {
                uint32_t b_lo[2][4];
#pragma unroll
                for (int np = 0; np < 2; np++)
                    lm4(&pBl[(wn0 + np*16 + b_n)*SSTR + ks + b_ko], b_lo[np]);
#pragma unroll
                for (int mt = 0; mt < 4; mt++)
#pragma unroll
                    for (int nt = 0; nt < 4; nt++)
                        mma16816(acc[mt][nt], a_hi[mt], &b_lo[nt >> 1][(nt & 1)*2]);
            }
        }
        __syncthreads();
    }

    int g = lane >> 2, t = lane & 3;

    if (MODE == 3) {
        const int NW = N / 3;
        int sel = col0 / NW;
        int colb = col0 - sel*NW;
        float* Cf = (sel == 0) ? C : (sel == 1) ? Ck : Cv;
        bool dosplit = (sel == 2) && (Coh != nullptr);
#pragma unroll
        for (int mt = 0; mt < 4; mt++) {
#pragma unroll
            for (int nt = 0; nt < 4; nt++) {
                int r1  = row0 + wm0 + mt*16 + g;
                int cix = colb + wn0 + nt*8 + 2*t;
                float v00 = acc[mt][nt][0], v01 = acc[mt][nt][1];
                float v10 = acc[mt][nt][2], v11 = acc[mt][nt][3];
                long o0 = (long)r1*NW + cix;
                long o1 = (long)(r1 + 8)*NW + cix;
                if (dosplit) {
                    __half h00 = __float2half(v00), h01 = __float2half(v01);
                    __half h10 = __float2half(v10), h11 = __float2half(v11);
                    *(__half2*)&Coh[o0] = __halves2half2(h00, h01);
                    *(__half2*)&Coh[o1] = __halves2half2(h10, h11);
                    *(__half2*)&Col[o0] = __halves2half2(
                        __float2half(v00 - __half2float(h00)),
                        __float2half(v01 - __half2float(h01)));
                    *(__half2*)&Col[o1] = __halves2half2(
                        __float2half(v10 - __half2float(h10)),
                        __float2half(v11 - __half2float(h11)));
                } else {
                    *(float2*)&Cf[o0] = make_float2(v00, v01);
                    *(float2*)&Cf[o1] = make_float2(v10, v11);
                }
            }
        }
        return;
    }

#pragma unroll
    for (int mt = 0; mt < 4; mt++) {
#pragma unroll
        for (int nt = 0; nt < 4; nt++) {
            int r1  = row0 + wm0 + mt*16 + g;
            int cix = col0 + wn0 + nt*8 + 2*t;
            float bv0 = 0.f, bv1 = 0.f;
            if (bias) { bv0 = bias[cix]; bv1 = bias[cix + 1]; }
            float v00 = acc[mt][nt][0] + bv0, v01 = acc[mt][nt][1] + bv1;
            float v10 = acc[mt][nt][2] + bv0, v11 = acc[mt][nt][3] + bv1;
            long o0 = (long)r1*N + cix;
            long o1 = (long)(r1 + 8)*N + cix;
            if (MODE == 0) {
                if (accum) {
                    float2 p0 = *(float2*)&C[o0];
                    float2 p1 = *(float2*)&C[o1];
                    v00 += p0.x; v01 += p0.y;
                    v10 += p1.x; v11 += p1.y;
                }
                *(float2*)&C[o0] = make_float2(v00, v01);
                *(float2*)&C[o1] = make_float2(v10, v11);
            } else {
                if (MODE == 2) {
                    v00 = gelu1(v00); v01 = gelu1(v01);
                    v10 = gelu1(v10); v11 = gelu1(v11);
                }
                __half h00 = __float2half(v00), h01 = __float2half(v01);
                __half h10 = __float2half(v10), h11 = __float2half(v11);
                *(__half2*)&Coh[o0] = __halves2half2(h00, h01);
                *(__half2*)&Coh[o1] = __halves2half2(h10, h11);
                *(__half2*)&Col[o0] = __halves2half2(
                    __float2half(v00 - __half2float(h00)),
                    __float2half(v01 - __half2float(h01)));
                *(__half2*)&Col[o1] = __halves2half2(
                    __float2half(v10 - __half2float(h10)),
                    __float2half(v11 - __half2float(h11)));
            }
        }
    }
}

// ---------------- tensor-core flash attention (causal, hd=64) ----------------
#define ASTR 72
#define FATTN_SMEM (6*64*ASTR*2)

__global__ void __launch_bounds__(128) fattn_kernel(
    const __half* __restrict__ Qh, const __half* __restrict__ Ql,
    const __half* __restrict__ Kh, const __half* __restrict__ Kl,
    const __half* __restrict__ Vh, const __half* __restrict__ Vl,
    __half* __restrict__ Oh, __half* __restrict__ Ol,
    int T, int nh, int rstride, long colstride)
{
    extern __shared__ __half sm[];
    __half* sQh = sm;
    __half* sQl = sQh + 64*ASTR;
    __half* sKh = sQl + 64*ASTR;
    __half* sKl = sKh + 64*ASTR;
    __half* sVh = sKl + 64*ASTR;
    __half* sVl = sVh + 64*ASTR;

    int qt = blockIdx.x;
    int b  = blockIdx.y / nh;
    int h  = blockIdx.y % nh;
    long base = (long)blockIdx.z * colstride + (long)h * 64;
    int q0  = qt * 64;
    int tid = threadIdx.x;
    int lane = tid & 31;
    int wid  = tid >> 5;
    int wrow = wid * 16;
    int g = lane >> 2, t4 = lane & 3;

#pragma unroll
    for (int c = tid; c < 512; c += 128) {
        int r = c >> 3, o = (c & 7) << 3;
        long src = base + (long)(b*T + q0 + r)*rstride + o;
        *(uint4*)&sQh[r*ASTR + o] = *(const uint4*)&Qh[src];
        *(uint4*)&sQl[r*ASTR + o] = *(const uint4*)&Ql[src];
    }
    __syncthreads();

    int a_r  = lane & 15;
    int a_ko = (lane >> 4) << 3;
    int b_n  = ((lane >> 4) << 3) + (lane & 7);
    int b_ko = ((lane >> 3) & 1) << 3;
    int v_r  = (((lane >> 3) & 1) << 3) + (lane & 7);
    int v_c  = (lane >> 4) << 3;

    uint32_t qfh[4][4], qfl[4][4];
#pragma unroll
    for (int ks = 0; ks < 4; ks++) {
        lm4(&sQh[(wrow + a_r)*ASTR + ks*16 + a_ko], qfh[ks]);
        lm4(&sQl[(wrow + a_r)*ASTR + ks*16 + a_ko], qfl[ks]);
    }

    float mrow[2] = {-1e30f, -1e30f};
    float lrow[2] = {0.f, 0.f};
    float oacc[8][4];
#pragma unroll
    for (int nt = 0; nt < 8; nt++)
#pragma unroll
        for (int e = 0; e < 4; e++) oacc[nt][e] = 0.f;

    for (int kt = 0; kt <= qt; kt++) {
        int k0 = kt * 64;
        __syncthreads();
#pragma unroll
        for (int c = tid; c < 512; c += 128) {
            int r = c >> 3, o = (c & 7) << 3;
            long src = base + (long)(b*T + k0 + r)*rstride + o;
            *(uint4*)&sKh[r*ASTR + o] = *(const uint4*)&Kh[src];
            *(uint4*)&sKl[r*ASTR + o] = *(const uint4*)&Kl[src];
            *(uint4*)&sVh[r*ASTR + o] = *(const uint4*)&Vh[src];
            *(uint4*)&sVl[r*ASTR + o] = *(const uint4*)&Vl[src];
        }
        __syncthreads();

        float S[8][4];
#pragma unroll
        for (int nt = 0; nt < 8; nt++)
#pragma unroll
            for (int e = 0; e < 4; e++) S[nt][e] = 0.f;

#pragma unroll
        for (int ks = 0; ks < 4; ks++) {
            uint32_t bh[4][4], bl[4][4];
#pragma unroll
            for (int np = 0; np < 4; np++) {
                lm4(&sKh[(np*16 + b_n)*ASTR + ks*16 + b_ko], bh[np]);
                lm4(&sKl[(np*16 + b_n)*ASTR + ks*16 + b_ko], bl[np]);
            }
#pragma unroll
            for (int np = 0; np < 4; np++)
#pragma unroll
                for (int j = 0; j < 2; j++) {
                    int nt = np*2 + j;
                    mma16816(S[nt], qfh[ks], &bh[np][j*2]);
                    mma16816(S[nt], qfh[ks], &bl[np][j*2]);
                    mma16816(S[nt], qfl[ks], &bh[np][j*2]);
                }
        }

#pragma unroll
        for (int nt = 0; nt < 8; nt++)
#pragma unroll
            for (int e = 0; e < 4; e++) {
                S[nt][e] *= 0.125f;
                if (kt == qt) {
                    int col = k0 + nt*8 + t4*2 + (e & 1);
                    int row = q0 + wrow + g + ((e >> 1) << 3);
                    if (col > row) S[nt][e] = -1e30f;
                }
            }

        float P[8][4];
#pragma unroll
        for (int r = 0; r < 2; r++) {
            float mx = -1e30f;
#pragma unroll
            for (int nt = 0; nt < 8; nt++) {
                mx = fmaxf(mx, S[nt][2*r + 0]);
                mx = fmaxf(mx, S[nt][2*r + 1]);
            }
            mx = fmaxf(mx, __shfl_xor_sync(0xffffffffu, mx, 1));
            mx = fmaxf(mx, __shfl_xor_sync(0xffffffffu, mx, 2));
            float mnew  = fmaxf(mrow[r], mx);
            float alpha = __expf(mrow[r] - mnew);
            float rsum = 0.f;
#pragma unroll
            for (int nt = 0; nt < 8; nt++) {
                float p0 = __expf(S[nt][2*r + 0] - mnew);
                float p1 = __expf(S[nt][2*r + 1] - mnew);
                P[nt][2*r + 0] = p0; P[nt][2*r + 1] = p1;
                rsum += p0 + p1;
            }
            rsum += __shfl_xor_sync(0xffffffffu, rsum, 1);
            rsum += __shfl_xor_sync(0xffffffffu, rsum, 2);
            lrow[r] = lrow[r]*alpha + rsum;
            mrow[r] = mnew;
#pragma unroll
            for (int nt = 0; nt < 8; nt++) {
                oacc[nt][2*r + 0] *= alpha;
                oacc[nt][2*r + 1] *= alpha;
            }
        }

        uint32_t pah[4][4], pal[4][4];
#pragma unroll
        for (int ks = 0; ks < 4; ks++) {
            int j0 = 2*ks, j1 = 2*ks + 1;
#pragma unroll
            for (int q = 0; q < 4; q++) {
                int jj = (q < 2) ? j0 : j1;
                int e0 = (q & 1) ? 2 : 0;
                float f0 = P[jj][e0], f1 = P[jj][e0 + 1];
                __half h0 = __float2half(f0), h1 = __float2half(f1);
                __half l0 = __float2half(f0 - __half2float(h0));
                __half l1 = __float2half(f1 - __half2float(h1));
                pah[ks][q] = (uint32_t)__half_as_ushort(h0) |
                             ((uint32_t)__half_as_ushort(h1) << 16);
                pal[ks][q] = (uint32_t)__half_as_ushort(l0) |
                             ((uint32_t)__half_as_ushort(l1) << 16);
            }
        }

#pragma unroll
        for (int ks = 0; ks < 4; ks++) {
            uint32_t vh[4][4], vl[4][4];
#pragma unroll
            for (int np = 0; np < 4; np++) {
                lm4t(&sVh[(ks*16 + v_r)*ASTR + np*16 + v_c], vh[np]);
                lm4t(&sVl[(ks*16 + v_r)*ASTR + np*16 + v_c], vl[np]);
            }
#pragma unroll
            for (int np = 0; np < 4; np++)
#pragma unroll
                for (int j = 0; j < 2; j++) {
                    int nt = np*2 + j;
                    mma16816(oacc[nt], pah[ks], &vh[np][j*2]);
                    mma16816(oacc[nt], pah[ks], &vl[np][j*2]);
                    mma16816(oacc[nt], pal[ks], &vh[np][j*2]);
                }
        }
    }

#pragma unroll
    for (int r = 0; r < 2; r++) {
        float inv = 1.f / lrow[r];
        int row = q0 + wrow + g + r*8;
        long ob = base + (long)(b*T + row)*rstride;
#pragma unroll
        for (int nt = 0; nt < 8; nt++) {
            float v0 = oacc[nt][2*r + 0] * inv;
            float v1 = oacc[nt][2*r + 1] * inv;
            __half h0 = __float2half(v0), h1 = __float2half(v1);
            __half l0 = __float2half(v0 - __half2float(h0));
            __half l1 = __float2half(v1 - __half2float(h1));
            int col = nt*8 + t4*2;
            *(__half2*)&Oh[ob + col] = __halves2half2(h0, h1);
            *(__half2*)&Ol[ob + col] = __halves2half2(l0, l1);
        }
    }
}

// ---------------- weight transpose + fp16 split ----------------
__global__ void splitT4_kernel(const float* p0, const float* p1,
                               const float* p2, const float* p3,
                               __half* __restrict__ oh, __half* __restrict__ ol,
                               int K, int N, int perBatch, int ngroups, int interleave)
{
    __shared__ float tile[32][33];
    const float* ps[4] = {p0, p1, p2, p3};
    int gsel = blockIdx.z / perBatch;
    int bz   = blockIdx.z % perBatch;
    const float* in = ps[gsel] + (long)bz * K * N;
    long ob = (interleave ? (long)(bz*ngroups + gsel) : (long)blockIdx.z) * K * N;
    int n0 = blockIdx.x * 32, k0 = blockIdx.y * 32;
    int tx = threadIdx.x & 31, ty = threadIdx.x >> 5;
#pragma unroll
    for (int j = 0; j < 4; j++) {
        int r = ty*4 + j;
        tile[r][tx] = in[(long)(k0 + r)*N + n0 + tx];
    }
    __syncthreads();
#pragma unroll
    for (int j = 0; j < 4; j++) {
        int nn = ty*4 + j;
        float v = tile[tx][nn];
        __half h = __float2half(v);
        long o = ob + (long)(n0 + nn)*K + k0 + tx;
        oh[o] = h;
        ol[o] = __float2half(v - __half2float(h));
    }
}

__global__ void split1_kernel(const float* __restrict__ in, __half* __restrict__ oh, int n4)
{
    int i = blockIdx.x * blockDim.x + threadIdx.x;
    if (i >= n4) return;
    float4 v = ((const float4*)in)[i];
    oh[4*i + 0] = __float2half(v.x);
    oh[4*i + 1] = __float2half(v.y);
    oh[4*i + 2] = __float2half(v.z);
    oh[4*i + 3] = __float2half(v.w);
}

__global__ void split2_kernel(const float* __restrict__ in, __half* __restrict__ oh,
                              __half* __restrict__ ol, int n4)
{
    int i = blockIdx.x * blockDim.x + threadIdx.x;
    if (i >= n4) return;
    float4 v = ((const float4*)in)[i];
    split_store(oh, ol, 4L*i + 0, v.x);
    split_store(oh, ol, 4L*i + 1, v.y);
    split_store(oh, ol, 4L*i + 2, v.z);
    split_store(oh, ol, 4L*i + 3, v.w);
}

// ---------------- rmsnorm -> fp16 hi/lo ----------------
__global__ void rms_kernel(const float* __restrict__ x, const float* __restrict__ w,
                           __half* __restrict__ oh, __half* __restrict__ ol,
                           int W, int rowsPerChunk, long wStride)
{
    int row = blockIdx.x;
    const float* xr = x + (long)row * W;
    const float* wr = w + (long)(row / rowsPerChunk) * wStride;
    float ss = 0.f;
    for (int i = threadIdx.x; i < W; i += 256) {
        float v = xr[i];
        ss += v * v;
    }
    __shared__ float red[8];
#pragma unroll
    for (int off = 16; off > 0; off >>= 1)
        ss += __shfl_xor_sync(0xffffffffu, ss, off);
    if ((threadIdx.x & 31) == 0) red[threadIdx.x >> 5] = ss;
    __syncthreads();
    float tot = red[0]+red[1]+red[2]+red[3]+red[4]+red[5]+red[6]+red[7];
    float inv = rsqrtf(tot / (float)W + 1e-6f);
    long rb = (long)row * W;
    for (int i = threadIdx.x; i < W; i += 256)
        split_store(oh, ol, rb + i, xr[i] * inv * wr[i]);
}

// ---------------- rope ----------------
__global__ void rope_kernel(const float* __restrict__ q, const float* __restrict__ k,
                            __half* __restrict__ qh, __half* __restrict__ ql,
                            __half* __restrict__ kh, __half* __restrict__ kl,
                            int T, int nh, int rstride, int nrows)
{
    int idx = blockIdx.x * blockDim.x + threadIdx.x;
    if (idx >= nrows * nh * 32) return;
    int i   = idx & 31;
    int h   = (idx >> 5) % nh;
    int row = idx / (32 * nh);
    int t   = row % T;
    float inv = __expf(-(float)(2*i) * (1.f/64.f) * 9.210340371976184f);
    float f = (float)t * inv;
    float s, c;
    sincosf(f, &s, &c);
    long bo = (long)row * rstride + h*64 + i;
    float q1 = q[bo], q2 = q[bo + 32];
    split_store(qh, ql, bo,      q1*c - q2*s);
    split_store(qh, ql, bo + 32, q2*c + q1*s);
    float k1 = k[bo], k2 = k[bo + 32];
    split_store(kh, kl, bo,      k1*c - k2*s);
    split_store(kh, kl, bo + 32, k2*c + k1*s);
}

// ---------------- embedding gather ----------------
__global__ void embed_kernel(float* __restrict__ X, const float* __restrict__ emb,
                             const int* __restrict__ ids)
{
    int row = blockIdx.x;
    int id  = ids[row];
    const float4* src = (const float4*)(emb + (long)id * DD);
    float4* dst = (float4*)(X + (long)row * DD);
    dst[threadIdx.x] = src[threadIdx.x];
}

// ---------------- cross-column merge attention ----------------
__global__ void merge_attn_kernel(const float* __restrict__ Qm, const float* __restrict__ Km,
                                  const float* __restrict__ Vm,
                                  __half* __restrict__ Oh, __half* __restrict__ Ol)
{
    int gid = blockIdx.x * blockDim.x + threadIdx.x;
    int h   = gid & 3;
    int row = (gid >> 2) & (BT - 1);
    int i   = gid >> 13;
    if (i >= CC) return;
    long base  = (long)row * DC + h*64;
    long cstep = (long)BT * DC;

    float4 q[16];
    const float4* qp = (const float4*)(Qm + i*cstep + base);
#pragma unroll
    for (int t = 0; t < 16; t++) q[t] = qp[t];

    float s[CC];
#pragma unroll
    for (int j = 0; j < CC; j++) {
        const float4* kp = (const float4*)(Km + j*cstep + base);
        float acc = 0.f;
#pragma unroll
        for (int t = 0; t < 16; t++) {
            float4 kv = kp[t];
            acc += q[t].x*kv.x + q[t].y*kv.y + q[t].z*kv.z + q[t].w*kv.w;
        }
        s[j] = acc * 0.125f;
    }
    float mm = fmaxf(fmaxf(s[0], s[1]), fmaxf(s[2], s[3]));
    float a[CC], sum = 0.f;
#pragma unroll
    for (int j = 0; j < CC; j++) { a[j] = __expf(s[j] - mm); sum += a[j]; }
    float isum = 1.f / sum;
#pragma unroll
    for (int j = 0; j < CC; j++) a[j] *= isum;

    float o[64];
#pragma unroll
    for (int t = 0; t < 64; t++) o[t] = 0.f;
#pragma unroll
    for (int j = 0; j < CC; j++) {
        const float4* vp = (const float4*)(Vm + j*cstep + base);
        float aj = a[j];
#pragma unroll
        for (int t = 0; t < 16; t++) {
            float4 vv = vp[t];
            o[4*t+0] = fmaf(aj, vv.x, o[4*t+0]);
            o[4*t+1] = fmaf(aj, vv.y, o[4*t+1]);
            o[4*t+2] = fmaf(aj, vv.z, o[4*t+2]);
            o[4*t+3] = fmaf(aj, vv.w, o[4*t+3]);
        }
    }
    long ob = i*cstep + base;
#pragma unroll
    for (int t = 0; t < 64; t++) split_store(Oh, Ol, ob + t, o[t]);
}

// ---------------- concat ----------------
__global__ void comb_kernel(const float* __restrict__ cs, __half* __restrict__ oh,
                            __half* __restrict__ ol)
{
    int gid = blockIdx.x * blockDim.x + threadIdx.x;
    int d4  = gid & (DD/4 - 1);
    int row = gid / (DD/4);
    int d = d4 * 4;
    int c = d >> 8;
    int e = d & 255;
    float4 v = *(const float4*)(cs + (long)c*BT*DC + (long)row*DC + e);
    split_store(oh, ol, 4L*gid + 0, v.x);
    split_store(oh, ol, 4L*gid + 1, v.y);
    split_store(oh, ol, 4L*gid + 2, v.z);
    split_store(oh, ol, 4L*gid + 3, v.w);
}

// ---------------- host side ----------------
static __half *Wh_p, *Wl_p;
#define HG2_SMEM (2*3*GPER*2)
#define HG1_SMEM (2*2*GPER*2)

static inline void hgemm(int mode, int nt, const __half* Ah, const __half* Al, long boff,
                         float* C, __half* Coh, __half* Col,
                         int M, int N, int K, int accum, const float* bias, int batch,
                         long aBS, long bBS, long cBS, long biasBS)
{
    dim3 grid(N/BN, M/BM, batch);
    if (nt == 2) {
        if (mode == 0)
            hgemm_kernel<2,0><<<grid, 256, HG2_SMEM>>>(Ah, Al, Wh_p + boff, Wl_p + boff,
                bias, C, nullptr, nullptr, M, N, K, accum, aBS, bBS, cBS, biasBS,
                nullptr, nullptr);
        else if (mode == 1)
            hgemm_kernel<2,1><<<grid, 256, HG2_SMEM>>>(Ah, Al, Wh_p + boff, Wl_p + boff,
                bias, nullptr, Coh, Col, M, N, K, accum, aBS, bBS, cBS, biasBS,
                nullptr, nullptr);
        else
            hgemm_kernel<2,2><<<grid, 256, HG2_SMEM>>>(Ah, Al, Wh_p + boff, Wl_p + boff,
                bias, nullptr, Coh, Col, M, N, K, accum, aBS, bBS, cBS, biasBS,
                nullptr, nullptr);
    } else {
        hgemm_kernel<1,0><<<grid, 256, HG1_SMEM>>>(Ah, nullptr, Wh_p + boff, nullptr,
            bias, C, nullptr, nullptr, M, N, K, accum, aBS, bBS, cBS, biasBS,
            nullptr, nullptr);
    }
}

static inline void hgemm_qkv(const __half* Ah, const __half* Al, long boff,
                             float* Cq, float* Ck, float* Cv,
                             __half* Voh, __half* Vol,
                             int M, int N, int K, int batch,
                             long aBS, long bBS, long cBS)
{
    dim3 grid(N/BN, M/BM, batch);
    hgemm_kernel<2,3><<<grid, 256, HG2_SMEM>>>(Ah, Al, Wh_p + boff, Wl_p + boff,
        nullptr, Cq, Voh, Vol, M, N, K, 0, aBS, bBS, cBS, 0, Ck, Cv);
}

static inline void splitT4(const float* a, const float* b, const float* c, const float* d,
                           long off, int K, int N, int perBatch, int ngroups, int interleave)
{
    splitT4_kernel<<<dim3(N/32, K/32, ngroups*perBatch), 256>>>(
        a, b, c, d, Wh_p + off, Wl_p + off, K, N, perBatch, ngroups, interleave);
}

extern "C" void kernel_launch(void* const* d_in, const int* in_sizes, int n_in,
                              void* d_out, int out_size)
{
    const int*   ids   = (const int*)d_in[0];
    const float* emb   = (const float*)d_in[1];
    const float* t_wq  = (const float*)d_in[2];
    const float* t_wk  = (const float*)d_in[3];
    const float* t_wv  = (const float*)d_in[4];
    const float* t_wo  = (const float*)d_in[5];
    const float* t_w1  = (const float*)d_in[6];
    const float* t_w2  = (const float*)d_in[7];
    const float* t_n1  = (const float*)d_in[8];
    const float* t_n2  = (const float*)d_in[9];
    const float* cin_w = (const float*)d_in[10];
    const float* cin_b = (const float*)d_in[11];
    const float* c_wq  = (const float*)d_in[12];
    const float* c_wk  = (const float*)d_in[13];
    const float* c_wv  = (const float*)d_in[14];
    const float* c_wo  = (const float*)d_in[15];
    const float* c_w1  = (const float*)d_in[16];
    const float* c_w2  = (const float*)d_in[17];
    const float* c_n1  = (const float*)d_in[18];
    const float* c_n2  = (const float*)d_in[19];
    const float* m_wq  = (const float*)d_in[20];
    const float* m_wk  = (const float*)d_in[21];
    const float* m_wv  = (const float*)d_in[22];
    const float* m_wo  = (const float*)d_in[23];
    const float* m_n   = (const float*)d_in[24];
    const float* oproj = (const float*)d_in[25];
    const float* fnorm = (const float*)d_in[26];
    float* out = (float*)d_out;

    void* p;
    cudaGetSymbolAddress(&p, g_X);   float*  X   = (float*)p;
    cudaGetSymbolAddress(&p, g_Q);   float*  Q   = (float*)p;
    cudaGetSymbolAddress(&p, g_K);   float*  Kb  = (float*)p;
    cudaGetSymbolAddress(&p, g_V);   float*  Vb  = (float*)p;
    cudaGetSymbolAddress(&p, g_CS);  float*  CS  = (float*)p;
    cudaGetSymbolAddress(&p, g_Hh);  __half* Hh  = (__half*)p;
    cudaGetSymbolAddress(&p, g_Hl);  __half* Hl  = (__half*)p;
    cudaGetSymbolAddress(&p, g_M1h); __half* M1h = (__half*)p;
    cudaGetSymbolAddress(&p, g_M1l); __half* M1l = (__half*)p;
    cudaGetSymbolAddress(&p, g_Oh);  __half* Oh  = (__half*)p;
    cudaGetSymbolAddress(&p, g_Ol);  __half* Ol  = (__half*)p;
    cudaGetSymbolAddress(&p, g_Qh);  __half* Qh  = (__half*)p;
    cudaGetSymbolAddress(&p, g_Ql);  __half* Ql  = (__half*)p;
    cudaGetSymbolAddress(&p, g_Kh);  __half* Kh  = (__half*)p;
    cudaGetSymbolAddress(&p, g_Kl);  __half* Kl  = (__half*)p;
    cudaGetSymbolAddress(&p, g_Vh);  __half* Vh  = (__half*)p;
    cudaGetSymbolAddress(&p, g_Vl);  __half* Vl  = (__half*)p;
    cudaGetSymbolAddress(&p, g_Wh);  Wh_p = (__half*)p;
    cudaGetSymbolAddress(&p, g_Wl);  Wl_p = (__half*)p;

    cudaFuncSetAttribute(hgemm_kernel<2,0>, cudaFuncAttributeMaxDynamicSharedMemorySize, HG2_SMEM);
    cudaFuncSetAttribute(hgemm_kernel<2,1>, cudaFuncAttributeMaxDynamicSharedMemorySize, HG2_SMEM);
    cudaFuncSetAttribute(hgemm_kernel<2,2>, cudaFuncAttributeMaxDynamicSharedMemorySize, HG2_SMEM);
    cudaFuncSetAttribute(hgemm_kernel<2,3>, cudaFuncAttributeMaxDynamicSharedMemorySize, HG2_SMEM);
    cudaFuncSetAttribute(hgemm_kernel<1,0>, cudaFuncAttributeMaxDynamicSharedMemorySize, HG1_SMEM);
    cudaFuncSetAttribute(fattn_kernel, cudaFuncAttributeMaxDynamicSharedMemorySize, FATTN_SMEM);

    // ---- weight conversion (batched; QKV interleaved per layer) ----
    splitT4(t_wq, t_wk, t_wv, nullptr, OT_QKV, DD, DD, LT, 3, 1);
    splitT4(t_wo, nullptr, nullptr, nullptr, OT_WO, DD, DD, LT, 1, 0);
    splitT4(t_w1, nullptr, nullptr, nullptr, OT_W1, DD, DFF, LT, 1, 0);
    splitT4(t_w2, nullptr, nullptr, nullptr, OT_W2, DFF, DD, LT, 1, 0);
    splitT4(cin_w, nullptr, nullptr, nullptr, OC_IN, DD, DC, CC, 1, 0);
    splitT4(c_wq, c_wk, c_wv, nullptr, OC_QKV, DC, DC, CC*LC, 3, 1);
    splitT4(c_wo, nullptr, nullptr, nullptr, OC_WO, DC, DC, CC*LC, 1, 0);
    splitT4(c_w1, nullptr, nullptr, nullptr, OC_W1, DC, DFFC, CC*LC, 1, 0);
    splitT4(c_w2, nullptr, nullptr, nullptr, OC_W2, DFFC, DC, CC*LC, 1, 0);
    splitT4(m_wq, m_wk, m_wv, nullptr, OM_QKV, DC, DC, NM, 3, 1);
    splitT4(m_wo, nullptr, nullptr, nullptr, OM_WO, DC, DC, NM, 1, 0);
    splitT4(oproj, nullptr, nullptr, nullptr, O_OP, DD, DD, 1, 1, 0);
    split1_kernel<<<(BV*DD/4 + 255)/256, 256>>>(emb, Wh_p + O_EMB, BV*DD/4);

    embed_kernel<<<BT, 256>>>(X, emb, ids);

    // ---- trunk ----
    for (int l = 0; l < LT; l++) {
        rms_kernel<<<BT, 256>>>(X, t_n1 + (long)l*DD, Hh, Hl, DD, BT, 0);
        hgemm_qkv(Hh, Hl, OT_QKV + (long)l*3*DD*DD, Q, Kb, nullptr, Vh, Vl,
                  BT, 3*DD, DD, 1, 0, 0, 0);
        rope_kernel<<<(BT*HT*32)/256, 256>>>(Q, Kb, Qh, Ql, Kh, Kl, TT, HT, DD, BT);
        fattn_kernel<<<dim3(TT/64, BB*HT, 1), 128, FATTN_SMEM>>>(
            Qh, Ql, Kh, Kl, Vh, Vl, Oh, Ol, TT, HT, DD, 0);
        hgemm(0, 2, Oh, Ol, OT_WO + (long)l*DD*DD, X, 0, 0, BT, DD, DD, 1, nullptr, 1, 0,0,0,0);
        rms_kernel<<<BT, 256>>>(X, t_n2 + (long)l*DD, Hh, Hl, DD, BT, 0);
        hgemm(2, 2, Hh, Hl, OT_W1 + (long)l*DD*DFF, 0, M1h, M1l, BT, DFF, DD, 0, nullptr, 1, 0,0,0,0);
        hgemm(0, 2, M1h, M1l, OT_W2 + (long)l*DFF*DD, X, 0, 0, BT, DD, DFF, 1, nullptr, 1, 0,0,0,0);
    }

    // ---- column projection ----
    split2_kernel<<<(BT*DD/4)/256, 256>>>(X, Hh, Hl, BT*DD/4);
    hgemm(0, 2, Hh, Hl, OC_IN, CS, 0, 0, BT, DC, DD, 0, cin_b, CC, 0, (long)DD*DC, (long)BT*DC, DC);

    // ---- column layers ----
    for (int l = 0; l < LC; l++) {
        rms_kernel<<<CBT, 256>>>(CS, c_n1 + (long)l*DC, Hh, Hl, DC, BT, (long)LC*DC);
        hgemm_qkv(Hh, Hl, OC_QKV + (long)l*3*DC*DC, Q, Kb, nullptr, Vh, Vl,
                  BT, 3*DC, DC, CC, (long)BT*DC, (long)LC*3*DC*DC, (long)BT*DC);
        rope_kernel<<<(CBT*HC*32)/256, 256>>>(Q, Kb, Qh, Ql, Kh, Kl, TT, HC, DC, CBT);
        fattn_kernel<<<dim3(TT/64, BB*HC, CC), 128, FATTN_SMEM>>>(
            Qh, Ql, Kh, Kl, Vh, Vl, Oh, Ol, TT, HC, DC, (long)BT*DC);
        hgemm(0, 2, Oh, Ol, OC_WO + (long)l*DC*DC, CS, 0, 0, BT, DC, DC, 1, nullptr, CC,
              (long)BT*DC, (long)LC*DC*DC, (long)BT*DC, 0);
        rms_kernel<<<CBT, 256>>>(CS, c_n2 + (long)l*DC, Hh, Hl, DC, BT, (long)LC*DC);
        hgemm(2, 2, Hh, Hl, OC_W1 + (long)l*DC*DFFC, 0, M1h, M1l, BT, DFFC, DC, 0, nullptr, CC,
              (long)BT*DC, (long)LC*DC*DFFC, (long)BT*DFFC, 0);
        hgemm(0, 2, M1h, M1l, OC_W2 + (long)l*DFFC*DC, CS, 0, 0, BT, DC, DFFC, 1, nullptr, CC,
              (long)BT*DFFC, (long)LC*DFFC*DC, (long)BT*DC, 0);

        if (((l + 1) & 1) == 0) {
            int m = (l + 1)/2 - 1;
            rms_kernel<<<CBT, 256>>>(CS, m_n + (long)m*DC, Hh, Hl, DC, CBT, 0);
            hgemm_qkv(Hh, Hl, OM_QKV + (long)m*3*DC*DC, Q, Kb, Vb, nullptr, nullptr,
                      CBT, 3*DC, DC, 1, 0, 0, 0);
            merge_attn_kernel<<<(CC*BT*HC)/256, 256>>>(Q, Kb, Vb, Oh, Ol);
            hgemm(0, 2, Oh, Ol, OM_WO + (long)m*DC*DC, CS, 0, 0, CBT, DC, DC, 1, nullptr, 1, 0,0,0,0);
        }
    }

    // ---- output head ----
    comb_kernel<<<(BT*DD/4)/256, 256>>>(CS, Hh, Hl);
    hgemm(0, 2, Hh, Hl, O_OP, Q, 0, 0, BT, DD, DD, 0, nullptr, 1, 0,0,0,0);
    rms_kernel<<<BT, 256>>>(Q, fnorm, Hh, Hl, DD, BT, 0);
    hgemm(0, 1, Hh, nullptr, O_EMB, out, 0, 0, BT, BV, DD, 0, nullptr, 1, 0,0,0,0);
}

// round 12
// speedup vs baseline: 1.3181x; 1.0575x over previous
#include <cuda_runtime.h>
#include <cuda_fp16.h>
#include <math.h>
#include <stdint.h>

// ---------------- model constants ----------------
#define BV   32000
#define DD   1024
#define DFF  4096
#define LT   2
#define HT   16
#define CC   4
#define DC   256
#define DFFC 1024
#define LC   4
#define HC   4
#define NM   2
#define BB   2
#define TT   1024
#define BT   (BB*TT)     // 2048
#define CBT  (CC*BT)     // 8192

// ---------------- weight offsets ([N][K] fp16; QKV interleaved per layer) ----------------
constexpr long OT_QKV = 0;
constexpr long OT_WO  = OT_QKV + (long)LT*3*DD*DD;
constexpr long OT_W1  = OT_WO  + (long)LT*DD*DD;
constexpr long OT_W2  = OT_W1  + (long)LT*DD*DFF;
constexpr long OC_IN  = OT_W2  + (long)LT*DFF*DD;
constexpr long OC_QKV = OC_IN  + (long)CC*DD*DC;
constexpr long OC_WO  = OC_QKV + (long)CC*LC*3*DC*DC;
constexpr long OC_W1  = OC_WO  + (long)CC*LC*DC*DC;
constexpr long OC_W2  = OC_W1  + (long)CC*LC*DC*DFFC;
constexpr long OM_QKV = OC_W2  + (long)CC*LC*DFFC*DC;
constexpr long OM_WO  = OM_QKV + (long)NM*3*DC*DC;
constexpr long O_OP   = OM_WO  + (long)NM*DC*DC;
constexpr long O_EMB  = O_OP   + (long)DD*DD;
constexpr long WTOT   = O_EMB  + (long)BV*DD;

// ---------------- scratch (device globals) ----------------
__device__ float  g_X [BT*DD];
__device__ float  g_Q [BT*DD];
__device__ float  g_K [BT*DD];
__device__ float  g_V [BT*DD];
__device__ float  g_CS[CC*BT*DC];
__device__ __half g_Hh[BT*DD];
__device__ __half g_M1h[BT*DFF];
__device__ __half g_Oh[BT*DD];
__device__ __half g_Qh[BT*DD];
__device__ __half g_Kh[BT*DD];
__device__ __half g_Kl[BT*DD];
__device__ __half g_Vh[BT*DD];
__device__ __half g_Vl[BT*DD];
__device__ __half g_Wh[WTOT];
__device__ __half g_Wl[WTOT];

// ---------------- asm helpers ----------------
__device__ __forceinline__ void lm4(const __half* p, uint32_t* r)
{
    uint32_t a = (uint32_t)__cvta_generic_to_shared(p);
    asm volatile("ldmatrix.sync.aligned.m8n8.x4.shared.b16 {%0,%1,%2,%3}, [%4];"
        : "=r"(r[0]), "=r"(r[1]), "=r"(r[2]), "=r"(r[3]) : "r"(a));
}
__device__ __forceinline__ void lm4t(const __half* p, uint32_t* r)
{
    uint32_t a = (uint32_t)__cvta_generic_to_shared(p);
    asm volatile("ldmatrix.sync.aligned.m8n8.x4.trans.shared.b16 {%0,%1,%2,%3}, [%4];"
        : "=r"(r[0]), "=r"(r[1]), "=r"(r[2]), "=r"(r[3]) : "r"(a));
}
__device__ __forceinline__ void mma16816(float* c, const uint32_t* a, const uint32_t* b)
{
    asm volatile("mma.sync.aligned.m16n8k16.row.col.f32.f16.f16.f32 "
        "{%0,%1,%2,%3},{%4,%5,%6,%7},{%8,%9},{%0,%1,%2,%3};"
        : "+f"(c[0]), "+f"(c[1]), "+f"(c[2]), "+f"(c[3])
        : "r"(a[0]), "r"(a[1]), "r"(a[2]), "r"(a[3]), "r"(b[0]), "r"(b[1]));
}
__device__ __forceinline__ void cpasync16(const __half* dst, const __half* src)
{
    uint32_t d = (uint32_t)__cvta_generic_to_shared(dst);
    asm volatile("cp.async.cg.shared.global [%0], [%1], 16;" :: "r"(d), "l"(src));
}
__device__ __forceinline__ void cp_commit() { asm volatile("cp.async.commit_group;"); }
template<int N> __device__ __forceinline__ void cp_wait()
{ asm volatile("cp.async.wait_group %0;" :: "n"(N)); }

__device__ __forceinline__ float gelu1(float v)
{
    return 0.5f * v * (1.f + tanhf(0.7978845608028654f * (v + 0.044715f*v*v*v)));
}
__device__ __forceinline__ void split_store(__half* oh, __half* ol, long idx, float v)
{
    __half h = __float2half(v);
    oh[idx] = h;
    ol[idx] = __float2half(v - __half2float(h));
}

// ---------------- HGEMM (cp.async double-buffered, champion mainloop) ----------------
// NT=2: A single fp16, B two-term (hh + h*lo) -> 2 MMA passes.  NT=1: plain.
// MODE 0: C fp32 (+accum+bias)  MODE 2: gelu + fp16-hi out
// MODE 3: fused QKV (N = 3*NW): sel0->C fp32, sel1->Ck fp32, sel2->hi/lo split
//         (Coh/Col) or fp32 Cv when Coh==null.
#define BM 128
#define BN 128
#define BKH 32
#define SSTR 40
#define GPER (BM*SSTR)

template<int NT, int MODE>
__global__ void __launch_bounds__(256) hgemm_kernel(
    const __half* __restrict__ Ah,
    const __half* __restrict__ Bh, const __half* __restrict__ Bl,
    const float* __restrict__ bias, float* __restrict__ C,
    __half* __restrict__ Coh, __half* __restrict__ Col,
    int M, int N, int K, int accum,
    long aBS, long bBS, long cBS, long biasBS,
    float* __restrict__ Ck, float* __restrict__ Cv)
{
    extern __shared__ __half smp[];
    const int NARR = (NT == 2) ? 3 : 2;   // Ah, Bh, (Bl)

    Ah += blockIdx.z * aBS;
    Bh += blockIdx.z * bBS;
    if (MODE == 0) C += blockIdx.z * cBS;
    else if (MODE == 3) {
        C += blockIdx.z * cBS;
        if (Ck)  Ck  += blockIdx.z * cBS;
        if (Cv)  Cv  += blockIdx.z * cBS;
        if (Coh) { Coh += blockIdx.z * cBS; Col += blockIdx.z * cBS; }
    } else { Coh += blockIdx.z * cBS; }
    if (NT == 2) Bl += blockIdx.z * bBS;
    if (bias) bias += blockIdx.z * biasBS;

    int row0 = blockIdx.y * BM;
    int col0 = blockIdx.x * BN;
    int tid  = threadIdx.x;
    int lane = tid & 31;
    int wid  = tid >> 5;
    int wm0  = (wid >> 2) * 64;
    int wn0  = (wid & 3) * 32;

    float acc[4][4][4];
#pragma unroll
    for (int mt = 0; mt < 4; mt++)
#pragma unroll
        for (int nt = 0; nt < 4; nt++)
#pragma unroll
            for (int q = 0; q < 4; q++) acc[mt][nt][q] = 0.f;

    int a_r  = lane & 15;
    int a_ko = (lane >> 4) << 3;
    int b_n  = ((lane >> 4) << 3) + (lane & 7);
    int b_ko = ((lane >> 3) & 1) << 3;

    int nk = K / BKH;

    auto loadStage = [&](int st, int k0) {
        __half* dAh = smp + st * NARR * GPER;
        __half* dBh = dAh + GPER;
        __half* dBl = dAh + 2 * GPER;
#pragma unroll
        for (int c = tid; c < 512; c += 256) {
            int r = c >> 2, o = (c & 3) << 3;
            cpasync16(&dAh[r*SSTR + o], &Ah[(long)(row0 + r)*K + k0 + o]);
            cpasync16(&dBh[r*SSTR + o], &Bh[(long)(col0 + r)*K + k0 + o]);
            if (NT == 2)
                cpasync16(&dBl[r*SSTR + o], &Bl[(long)(col0 + r)*K + k0 + o]);
        }
    };

    loadStage(0, 0);
    cp_commit();

    for (int kt = 0; kt < nk; kt++) {
        int cur = kt & 1;
        if (kt + 1 < nk) {
            loadStage(cur ^ 1, (kt + 1) * BKH);
            cp_commit();
            cp_wait<1>();
        } else {
            cp_wait<0>();
        }
        __syncthreads();

        const __half* pAh = smp + cur * NARR * GPER;
        const __half* pBh = pAh + GPER;
        const __half* pBl = pAh + 2 * GPER;

#pragma unroll
        for (int ks = 0; ks < BKH; ks += 16) {
            uint32_t a_hi[4][4], b_hi[2][4];
#pragma unroll
            for (int mt = 0; mt < 4; mt++)
                lm4(&pAh[(wm0 + mt*16 + a_r)*SSTR + ks + a_ko], a_hi[mt]);
#pragma unroll
            for (int np = 0; np < 2; np++)
                lm4(&pBh[(wn0 + np*16 + b_n)*SSTR + ks + b_ko], b_hi[np]);
#pragma unroll
            for (int mt = 0; mt < 4; mt++)
#pragma unroll
                for (int nt = 0; nt < 4; nt++)
                    mma16816(acc[mt][nt], a_hi[mt], &b_hi[nt >> 1][(nt & 1)*2]);

            if (NT == 2) {
                uint32_t b_lo[2][4];
#pragma unroll
                for (int np = 0; np < 2; np++)
                    lm4(&pBl[(wn0 + np*16 + b_n)*SSTR + ks + b_ko], b_lo[np]);
#pragma unroll
                for (int mt = 0; mt < 4; mt++)
#pragma unroll
                    for (int nt = 0; nt < 4; nt++)
                        mma16816(acc[mt][nt], a_hi[mt], &b_lo[nt >> 1][(nt & 1)*2]);
            }
        }
        __syncthreads();
    }

    int g = lane >> 2, t = lane & 3;

    if (MODE == 3) {
        const int NW = N / 3;
        int sel = col0 / NW;
        int colb = col0 - sel*NW;
        float* Cf = (sel == 0) ? C : (sel == 1) ? Ck : Cv;
        bool dosplit = (sel == 2) && (Coh != nullptr);
#pragma unroll
        for (int mt = 0; mt < 4; mt++) {
#pragma unroll
            for (int nt = 0; nt < 4; nt++) {
                int r1  = row0 + wm0 + mt*16 + g;
                int cix = colb + wn0 + nt*8 + 2*t;
                float v00 = acc[mt][nt][0], v01 = acc[mt][nt][1];
                float v10 = acc[mt][nt][2], v11 = acc[mt][nt][3];
                long o0 = (long)r1*NW + cix;
                long o1 = (long)(r1 + 8)*NW + cix;
                if (dosplit) {
                    __half h00 = __float2half(v00), h01 = __float2half(v01);
                    __half h10 = __float2half(v10), h11 = __float2half(v11);
                    *(__half2*)&Coh[o0] = __halves2half2(h00, h01);
                    *(__half2*)&Coh[o1] = __halves2half2(h10, h11);
                    *(__half2*)&Col[o0] = __halves2half2(
                        __float2half(v00 - __half2float(h00)),
                        __float2half(v01 - __half2float(h01)));
                    *(__half2*)&Col[o1] = __halves2half2(
                        __float2half(v10 - __half2float(h10)),
                        __float2half(v11 - __half2float(h11)));
                } else {
                    *(float2*)&Cf[o0] = make_float2(v00, v01);
                    *(float2*)&Cf[o1] = make_float2(v10, v11);
                }
            }
        }
        return;
    }

#pragma unroll
    for (int mt = 0; mt < 4; mt++) {
#pragma unroll
        for (int nt = 0; nt < 4; nt++) {
            int r1  = row0 + wm0 + mt*16 + g;
            int cix = col0 + wn0 + nt*8 + 2*t;
            float bv0 = 0.f, bv1 = 0.f;
            if (bias) { bv0 = bias[cix]; bv1 = bias[cix + 1]; }
            float v00 = acc[mt][nt][0] + bv0, v01 = acc[mt][nt][1] + bv1;
            float v10 = acc[mt][nt][2] + bv0, v11 = acc[mt][nt][3] + bv1;
            long o0 = (long)r1*N + cix;
            long o1 = (long)(r1 + 8)*N + cix;
            if (MODE == 0) {
                if (accum) {
                    float2 p0 = *(float2*)&C[o0];
                    float2 p1 = *(float2*)&C[o1];
                    v00 += p0.x; v01 += p0.y;
                    v10 += p1.x; v11 += p1.y;
                }
                *(float2*)&C[o0] = make_float2(v00, v01);
                *(float2*)&C[o1] = make_float2(v10, v11);
            } else {
                if (MODE == 2) {
                    v00 = gelu1(v00); v01 = gelu1(v01);
                    v10 = gelu1(v10); v11 = gelu1(v11);
                }
                *(__half2*)&Coh[o0] = __halves2half2(__float2half(v00), __float2half(v01));
                *(__half2*)&Coh[o1] = __halves2half2(__float2half(v10), __float2half(v11));
            }
        }
    }
}

// ---------------- tensor-core flash attention (causal, hd=64, 2-pass) ----------------
#define ASTR 72
#define FATTN_SMEM (5*64*ASTR*2)

__global__ void __launch_bounds__(128) fattn_kernel(
    const __half* __restrict__ Qh,
    const __half* __restrict__ Kh, const __half* __restrict__ Kl,
    const __half* __restrict__ Vh, const __half* __restrict__ Vl,
    __half* __restrict__ Oh,
    int T, int nh, int rstride, long colstride)
{
    extern __shared__ __half sm[];
    __half* sQh = sm;
    __half* sKh = sQh + 64*ASTR;
    __half* sKl = sKh + 64*ASTR;
    __half* sVh = sKl + 64*ASTR;
    __half* sVl = sVh + 64*ASTR;

    int qt = blockIdx.x;
    int b  = blockIdx.y / nh;
    int h  = blockIdx.y % nh;
    long base = (long)blockIdx.z * colstride + (long)h * 64;
    int q0  = qt * 64;
    int tid = threadIdx.x;
    int lane = tid & 31;
    int wid  = tid >> 5;
    int wrow = wid * 16;
    int g = lane >> 2, t4 = lane & 3;

#pragma unroll
    for (int c = tid; c < 512; c += 128) {
        int r = c >> 3, o = (c & 7) << 3;
        long src = base + (long)(b*T + q0 + r)*rstride + o;
        *(uint4*)&sQh[r*ASTR + o] = *(const uint4*)&Qh[src];
    }
    __syncthreads();

    int a_r  = lane & 15;
    int a_ko = (lane >> 4) << 3;
    int b_n  = ((lane >> 4) << 3) + (lane & 7);
    int b_ko = ((lane >> 3) & 1) << 3;
    int v_r  = (((lane >> 3) & 1) << 3) + (lane & 7);
    int v_c  = (lane >> 4) << 3;

    uint32_t qfh[4][4];
#pragma unroll
    for (int ks = 0; ks < 4; ks++)
        lm4(&sQh[(wrow + a_r)*ASTR + ks*16 + a_ko], qfh[ks]);

    float mrow[2] = {-1e30f, -1e30f};
    float lrow[2] = {0.f, 0.f};
    float oacc[8][4];
#pragma unroll
    for (int nt = 0; nt < 8; nt++)
#pragma unroll
        for (int e = 0; e < 4; e++) oacc[nt][e] = 0.f;

    for (int kt = 0; kt <= qt; kt++) {
        int k0 = kt * 64;
        __syncthreads();
#pragma unroll
        for (int c = tid; c < 512; c += 128) {
            int r = c >> 3, o = (c & 7) << 3;
            long src = base + (long)(b*T + k0 + r)*rstride + o;
            *(uint4*)&sKh[r*ASTR + o] = *(const uint4*)&Kh[src];
            *(uint4*)&sKl[r*ASTR + o] = *(const uint4*)&Kl[src];
            *(uint4*)&sVh[r*ASTR + o] = *(const uint4*)&Vh[src];
            *(uint4*)&sVl[r*ASTR + o] = *(const uint4*)&Vl[src];
        }
        __syncthreads();

        float S[8][4];
#pragma unroll
        for (int nt = 0; nt < 8; nt++)
#pragma unroll
            for (int e = 0; e < 4; e++) S[nt][e] = 0.f;

#pragma unroll
        for (int ks = 0; ks < 4; ks++) {
            uint32_t bh[4][4], bl[4][4];
#pragma unroll
            for (int np = 0; np < 4; np++) {
                lm4(&sKh[(np*16 + b_n)*ASTR + ks*16 + b_ko], bh[np]);
                lm4(&sKl[(np*16 + b_n)*ASTR + ks*16 + b_ko], bl[np]);
            }
#pragma unroll
            for (int np = 0; np < 4; np++)
#pragma unroll
                for (int j = 0; j < 2; j++) {
                    int nt = np*2 + j;
                    mma16816(S[nt], qfh[ks], &bh[np][j*2]);
                    mma16816(S[nt], qfh[ks], &bl[np][j*2]);
                }
        }

#pragma unroll
        for (int nt = 0; nt < 8; nt++)
#pragma unroll
            for (int e = 0; e < 4; e++) {
                S[nt][e] *= 0.125f;
                if (kt == qt) {
                    int col = k0 + nt*8 + t4*2 + (e & 1);
                    int row = q0 + wrow + g + ((e >> 1) << 3);
                    if (col > row) S[nt][e] = -1e30f;
                }
            }

        float P[8][4];
#pragma unroll
        for (int r = 0; r < 2; r++) {
            float mx = -1e30f;
#pragma unroll
            for (int nt = 0; nt < 8; nt++) {
                mx = fmaxf(mx, S[nt][2*r + 0]);
                mx = fmaxf(mx, S[nt][2*r + 1]);
            }
            mx = fmaxf(mx, __shfl_xor_sync(0xffffffffu, mx, 1));
            mx = fmaxf(mx, __shfl_xor_sync(0xffffffffu, mx, 2));
            float mnew  = fmaxf(mrow[r], mx);
            float alpha = __expf(mrow[r] - mnew);
            float rsum = 0.f;
#pragma unroll
            for (int nt = 0; nt < 8; nt++) {
                float p0 = __expf(S[nt][2*r + 0] - mnew);
                float p1 = __expf(S[nt][2*r + 1] - mnew);
                P[nt][2*r + 0] = p0; P[nt][2*r + 1] = p1;
                rsum += p0 + p1;
            }
            rsum += __shfl_xor_sync(0xffffffffu, rsum, 1);
            rsum += __shfl_xor_sync(0xffffffffu, rsum, 2);
            lrow[r] = lrow[r]*alpha + rsum;
            mrow[r] = mnew;
#pragma unroll
            for (int nt = 0; nt < 8; nt++) {
                oacc[nt][2*r + 0] *= alpha;
                oacc[nt][2*r + 1] *= alpha;
            }
        }

        uint32_t pah[4][4];
#pragma unroll
        for (int ks = 0; ks < 4; ks++) {
            int j0 = 2*ks, j1 = 2*ks + 1;
#pragma unroll
            for (int q = 0; q < 4; q++) {
                int jj = (q < 2) ? j0 : j1;
                int e0 = (q & 1) ? 2 : 0;
                __half h0 = __float2half(P[jj][e0]);
                __half h1 = __float2half(P[jj][e0 + 1]);
                pah[ks][q] = (uint32_t)__half_as_ushort(h0) |
                             ((uint32_t)__half_as_ushort(h1) << 16);
            }
        }

#pragma unroll
        for (int ks = 0; ks < 4; ks++) {
            uint32_t vh[4][4], vl[4][4];
#pragma unroll
            for (int np = 0; np < 4; np++) {
                lm4t(&sVh[(ks*16 + v_r)*ASTR + np*16 + v_c], vh[np]);
                lm4t(&sVl[(ks*16 + v_r)*ASTR + np*16 + v_c], vl[np]);
            }
#pragma unroll
            for (int np = 0; np < 4; np++)
#pragma unroll
                for (int j = 0; j < 2; j++) {
                    int nt = np*2 + j;
                    mma16816(oacc[nt], pah[ks], &vh[np][j*2]);
                    mma16816(oacc[nt], pah[ks], &vl[np][j*2]);
                }
        }
    }

#pragma unroll
    for (int r = 0; r < 2; r++) {
        float inv = 1.f / lrow[r];
        int row = q0 + wrow + g + r*8;
        long ob = base + (long)(b*T + row)*rstride;
#pragma unroll
        for (int nt = 0; nt < 8; nt++) {
            float v0 = oacc[nt][2*r + 0] * inv;
            float v1 = oacc[nt][2*r + 1] * inv;
            int col = nt*8 + t4*2;
            *(__half2*)&Oh[ob + col] = __halves2half2(__float2half(v0), __float2half(v1));
        }
    }
}

// ---------------- weight transpose + fp16 split ----------------
__global__ void splitT4_kernel(const float* p0, const float* p1,
                               const float* p2, const float* p3,
                               __half* __restrict__ oh, __half* __restrict__ ol,
                               int K, int N, int perBatch, int ngroups, int interleave)
{
    __shared__ float tile[32][33];
    const float* ps[4] = {p0, p1, p2, p3};
    int gsel = blockIdx.z / perBatch;
    int bz   = blockIdx.z % perBatch;
    const float* in = ps[gsel] + (long)bz * K * N;
    long ob = (interleave ? (long)(bz*ngroups + gsel) : (long)blockIdx.z) * K * N;
    int n0 = blockIdx.x * 32, k0 = blockIdx.y * 32;
    int tx = threadIdx.x & 31, ty = threadIdx.x >> 5;
#pragma unroll
    for (int j = 0; j < 4; j++) {
        int r = ty*4 + j;
        tile[r][tx] = in[(long)(k0 + r)*N + n0 + tx];
    }
    __syncthreads();
#pragma unroll
    for (int j = 0; j < 4; j++) {
        int nn = ty*4 + j;
        float v = tile[tx][nn];
        __half h = __float2half(v);
        long o = ob + (long)(n0 + nn)*K + k0 + tx;
        oh[o] = h;
        ol[o] = __float2half(v - __half2float(h));
    }
}

__global__ void split1_kernel(const float* __restrict__ in, __half* __restrict__ oh, int n4)
{
    int i = blockIdx.x * blockDim.x + threadIdx.x;
    if (i >= n4) return;
    float4 v = ((const float4*)in)[i];
    oh[4*i + 0] = __float2half(v.x);
    oh[4*i + 1] = __float2half(v.y);
    oh[4*i + 2] = __float2half(v.z);
    oh[4*i + 3] = __float2half(v.w);
}

// ---------------- rmsnorm -> fp16 hi ----------------
__global__ void rms_kernel(const float* __restrict__ x, const float* __restrict__ w,
                           __half* __restrict__ oh,
                           int W, int rowsPerChunk, long wStride)
{
    int row = blockIdx.x;
    const float* xr = x + (long)row * W;
    const float* wr = w + (long)(row / rowsPerChunk) * wStride;
    float ss = 0.f;
    for (int i = threadIdx.x; i < W; i += 256) {
        float v = xr[i];
        ss += v * v;
    }
    __shared__ float red[8];
#pragma unroll
    for (int off = 16; off > 0; off >>= 1)
        ss += __shfl_xor_sync(0xffffffffu, ss, off);
    if ((threadIdx.x & 31) == 0) red[threadIdx.x >> 5] = ss;
    __syncthreads();
    float tot = red[0]+red[1]+red[2]+red[3]+red[4]+red[5]+red[6]+red[7];
    float inv = rsqrtf(tot / (float)W + 1e-6f);
    long rb = (long)row * W;
    for (int i = threadIdx.x; i < W; i += 256)
        oh[rb + i] = __float2half(xr[i] * inv * wr[i]);
}

// ---------------- rope: fp32 q,k -> qh (hi) and kh/kl (hi+lo) ----------------
__global__ void rope_kernel(const float* __restrict__ q, const float* __restrict__ k,
                            __half* __restrict__ qh,
                            __half* __restrict__ kh, __half* __restrict__ kl,
                            int T, int nh, int rstride, int nrows)
{
    int idx = blockIdx.x * blockDim.x + threadIdx.x;
    if (idx >= nrows * nh * 32) return;
    int i   = idx & 31;
    int h   = (idx >> 5) % nh;
    int row = idx / (32 * nh);
    int t   = row % T;
    float inv = __expf(-(float)(2*i) * (1.f/64.f) * 9.210340371976184f);
    float f = (float)t * inv;
    float s, c;
    sincosf(f, &s, &c);
    long bo = (long)row * rstride + h*64 + i;
    float q1 = q[bo], q2 = q[bo + 32];
    qh[bo]      = __float2half(q1*c - q2*s);
    qh[bo + 32] = __float2half(q2*c + q1*s);
    float k1 = k[bo], k2 = k[bo + 32];
    split_store(kh, kl, bo,      k1*c - k2*s);
    split_store(kh, kl, bo + 32, k2*c + k1*s);
}

// ---------------- embedding gather ----------------
__global__ void embed_kernel(float* __restrict__ X, const float* __restrict__ emb,
                             const int* __restrict__ ids)
{
    int row = blockIdx.x;
    int id  = ids[row];
    const float4* src = (const float4*)(emb + (long)id * DD);
    float4* dst = (float4*)(X + (long)row * DD);
    dst[threadIdx.x] = src[threadIdx.x];
}

// ---------------- cross-column merge attention ----------------
__global__ void merge_attn_kernel(const float* __restrict__ Qm, const float* __restrict__ Km,
                                  const float* __restrict__ Vm,
                                  __half* __restrict__ Oh)
{
    int gid = blockIdx.x * blockDim.x + threadIdx.x;
    int h   = gid & 3;
    int row = (gid >> 2) & (BT - 1);
    int i   = gid >> 13;
    if (i >= CC) return;
    long base  = (long)row * DC + h*64;
    long cstep = (long)BT * DC;

    float4 q[16];
    const float4* qp = (const float4*)(Qm + i*cstep + base);
#pragma unroll
    for (int t = 0; t < 16; t++) q[t] = qp[t];

    float s[CC];
#pragma unroll
    for (int j = 0; j < CC; j++) {
        const float4* kp = (const float4*)(Km + j*cstep + base);
        float acc = 0.f;
#pragma unroll
        for (int t = 0; t < 16; t++) {
            float4 kv = kp[t];
            acc += q[t].x*kv.x + q[t].y*kv.y + q[t].z*kv.z + q[t].w*kv.w;
        }
        s[j] = acc * 0.125f;
    }
    float mm = fmaxf(fmaxf(s[0], s[1]), fmaxf(s[2], s[3]));
    float a[CC], sum = 0.f;
#pragma unroll
    for (int j = 0; j < CC; j++) { a[j] = __expf(s[j] - mm); sum += a[j]; }
    float isum = 1.f / sum;
#pragma unroll
    for (int j = 0; j < CC; j++) a[j] *= isum;

    float o[64];
#pragma unroll
    for (int t = 0; t < 64; t++) o[t] = 0.f;
#pragma unroll
    for (int j = 0; j < CC; j++) {
        const float4* vp = (const float4*)(Vm + j*cstep + base);
        float aj = a[j];
#pragma unroll
        for (int t = 0; t < 16; t++) {
            float4 vv = vp[t];
            o[4*t+0] = fmaf(aj, vv.x, o[4*t+0]);
            o[4*t+1] = fmaf(aj, vv.y, o[4*t+1]);
            o[4*t+2] = fmaf(aj, vv.z, o[4*t+2]);
            o[4*t+3] = fmaf(aj, vv.w, o[4*t+3]);
        }
    }
    long ob = i*cstep + base;
#pragma unroll
    for (int t = 0; t < 64; t++) Oh[ob + t] = __float2half(o[t]);
}

// ---------------- split fp32 -> fp16 hi (vectorized) ----------------
__global__ void tohalf_kernel(const float* __restrict__ in, __half* __restrict__ oh, int n4)
{
    int i = blockIdx.x * blockDim.x + threadIdx.x;
    if (i >= n4) return;
    float4 v = ((const float4*)in)[i];
    oh[4L*i + 0] = __float2half(v.x);
    oh[4L*i + 1] = __float2half(v.y);
    oh[4L*i + 2] = __float2half(v.z);
    oh[4L*i + 3] = __float2half(v.w);
}

// ---------------- concat -> fp16 hi ----------------
__global__ void comb_kernel(const float* __restrict__ cs, __half* __restrict__ oh)
{
    int gid = blockIdx.x * blockDim.x + threadIdx.x;
    int d4  = gid & (DD/4 - 1);
    int row = gid / (DD/4);
    int d = d4 * 4;
    int c = d >> 8;
    int e = d & 255;
    float4 v = *(const float4*)(cs + (long)c*BT*DC + (long)row*DC + e);
    oh[4L*gid + 0] = __float2half(v.x);
    oh[4L*gid + 1] = __float2half(v.y);
    oh[4L*gid + 2] = __float2half(v.z);
    oh[4L*gid + 3] = __float2half(v.w);
}

// ---------------- host side ----------------
static __half *Wh_p, *Wl_p;
#define HG2_SMEM (2*3*GPER*2)
#define HG1_SMEM (2*2*GPER*2)

static inline void hgemm(int mode, int nt, const __half* Ah, long boff,
                         float* C, __half* Coh,
                         int M, int N, int K, int accum, const float* bias, int batch,
                         long aBS, long bBS, long cBS, long biasBS)
{
    dim3 grid(N/BN, M/BM, batch);
    if (nt == 2) {
        if (mode == 0)
            hgemm_kernel<2,0><<<grid, 256, HG2_SMEM>>>(Ah, Wh_p + boff, Wl_p + boff,
                bias, C, nullptr, nullptr, M, N, K, accum, aBS, bBS, cBS, biasBS,
                nullptr, nullptr);
        else
            hgemm_kernel<2,2><<<grid, 256, HG2_SMEM>>>(Ah, Wh_p + boff, Wl_p + boff,
                bias, nullptr, Coh, nullptr, M, N, K, accum, aBS, bBS, cBS, biasBS,
                nullptr, nullptr);
    } else {
        hgemm_kernel<1,0><<<grid, 256, HG1_SMEM>>>(Ah, Wh_p + boff, nullptr,
            bias, C, nullptr, nullptr, M, N, K, accum, aBS, bBS, cBS, biasBS,
            nullptr, nullptr);
    }
}

static inline void hgemm_qkv(const __half* Ah, long boff,
                             float* Cq, float* Ck, float* Cv,
                             __half* Voh, __half* Vol,
                             int M, int N, int K, int batch,
                             long aBS, long bBS, long cBS)
{
    dim3 grid(N/BN, M/BM, batch);
    hgemm_kernel<2,3><<<grid, 256, HG2_SMEM>>>(Ah, Wh_p + boff, Wl_p + boff,
        nullptr, Cq, Voh, Vol, M, N, K, 0, aBS, bBS, cBS, 0, Ck, Cv);
}

static inline void splitT4(const float* a, const float* b, const float* c, const float* d,
                           long off, int K, int N, int perBatch, int ngroups, int interleave)
{
    splitT4_kernel<<<dim3(N/32, K/32, ngroups*perBatch), 256>>>(
        a, b, c, d, Wh_p + off, Wl_p + off, K, N, perBatch, ngroups, interleave);
}

extern "C" void kernel_launch(void* const* d_in, const int* in_sizes, int n_in,
                              void* d_out, int out_size)
{
    const int*   ids   = (const int*)d_in[0];
    const float* emb   = (const float*)d_in[1];
    const float* t_wq  = (const float*)d_in[2];
    const float* t_wk  = (const float*)d_in[3];
    const float* t_wv  = (const float*)d_in[4];
    const float* t_wo  = (const float*)d_in[5];
    const float* t_w1  = (const float*)d_in[6];
    const float* t_w2  = (const float*)d_in[7];
    const float* t_n1  = (const float*)d_in[8];
    const float* t_n2  = (const float*)d_in[9];
    const float* cin_w = (const float*)d_in[10];
    const float* cin_b = (const float*)d_in[11];
    const float* c_wq  = (const float*)d_in[12];
    const float* c_wk  = (const float*)d_in[13];
    const float* c_wv  = (const float*)d_in[14];
    const float* c_wo  = (const float*)d_in[15];
    const float* c_w1  = (const float*)d_in[16];
    const float* c_w2  = (const float*)d_in[17];
    const float* c_n1  = (const float*)d_in[18];
    const float* c_n2  = (const float*)d_in[19];
    const float* m_wq  = (const float*)d_in[20];
    const float* m_wk  = (const float*)d_in[21];
    const float* m_wv  = (const float*)d_in[22];
    const float* m_wo  = (const float*)d_in[23];
    const float* m_n   = (const float*)d_in[24];
    const float* oproj = (const float*)d_in[25];
    const float* fnorm = (const float*)d_in[26];
    float* out = (float*)d_out;

    void* p;
    cudaGetSymbolAddress(&p, g_X);   float*  X   = (float*)p;
    cudaGetSymbolAddress(&p, g_Q);   float*  Q   = (float*)p;
    cudaGetSymbolAddress(&p, g_K);   float*  Kb  = (float*)p;
    cudaGetSymbolAddress(&p, g_V);   float*  Vb  = (float*)p;
    cudaGetSymbolAddress(&p, g_CS);  float*  CS  = (float*)p;
    cudaGetSymbolAddress(&p, g_Hh);  __half* Hh  = (__half*)p;
    cudaGetSymbolAddress(&p, g_M1h); __half* M1h = (__half*)p;
    cudaGetSymbolAddress(&p, g_Oh);  __half* Oh  = (__half*)p;
    cudaGetSymbolAddress(&p, g_Qh);  __half* Qh  = (__half*)p;
    cudaGetSymbolAddress(&p, g_Kh);  __half* Kh  = (__half*)p;
    cudaGetSymbolAddress(&p, g_Kl);  __half* Kl  = (__half*)p;
    cudaGetSymbolAddress(&p, g_Vh);  __half* Vh  = (__half*)p;
    cudaGetSymbolAddress(&p, g_Vl);  __half* Vl  = (__half*)p;
    cudaGetSymbolAddress(&p, g_Wh);  Wh_p = (__half*)p;
    cudaGetSymbolAddress(&p, g_Wl);  Wl_p = (__half*)p;

    cudaFuncSetAttribute(hgemm_kernel<2,0>, cudaFuncAttributeMaxDynamicSharedMemorySize, HG2_SMEM);
    cudaFuncSetAttribute(hgemm_kernel<2,2>, cudaFuncAttributeMaxDynamicSharedMemorySize, HG2_SMEM);
    cudaFuncSetAttribute(hgemm_kernel<2,3>, cudaFuncAttributeMaxDynamicSharedMemorySize, HG2_SMEM);
    cudaFuncSetAttribute(hgemm_kernel<1,0>, cudaFuncAttributeMaxDynamicSharedMemorySize, HG1_SMEM);
    cudaFuncSetAttribute(fattn_kernel, cudaFuncAttributeMaxDynamicSharedMemorySize, FATTN_SMEM);

    // ---- weight conversion (batched; QKV interleaved per layer) ----
    splitT4(t_wq, t_wk, t_wv, nullptr, OT_QKV, DD, DD, LT, 3, 1);
    splitT4(t_wo, nullptr, nullptr, nullptr, OT_WO, DD, DD, LT, 1, 0);
    splitT4(t_w1, nullptr, nullptr, nullptr, OT_W1, DD, DFF, LT, 1, 0);
    splitT4(t_w2, nullptr, nullptr, nullptr, OT_W2, DFF, DD, LT, 1, 0);
    splitT4(cin_w, nullptr, nullptr, nullptr, OC_IN, DD, DC, CC, 1, 0);
    splitT4(c_wq, c_wk, c_wv, nullptr, OC_QKV, DC, DC, CC*LC, 3, 1);
    splitT4(c_wo, nullptr, nullptr, nullptr, OC_WO, DC, DC, CC*LC, 1, 0);
    splitT4(c_w1, nullptr, nullptr, nullptr, OC_W1, DC, DFFC, CC*LC, 1, 0);
    splitT4(c_w2, nullptr, nullptr, nullptr, OC_W2, DFFC, DC, CC*LC, 1, 0);
    splitT4(m_wq, m_wk, m_wv, nullptr, OM_QKV, DC, DC, NM, 3, 1);
    splitT4(m_wo, nullptr, nullptr, nullptr, OM_WO, DC, DC, NM, 1, 0);
    splitT4(oproj, nullptr, nullptr, nullptr, O_OP, DD, DD, 1, 1, 0);
    split1_kernel<<<(BV*DD/4 + 255)/256, 256>>>(emb, Wh_p + O_EMB, BV*DD/4);

    embed_kernel<<<BT, 256>>>(X, emb, ids);

    // ---- trunk ----
    for (int l = 0; l < LT; l++) {
        rms_kernel<<<BT, 256>>>(X, t_n1 + (long)l*DD, Hh, DD, BT, 0);
        hgemm_qkv(Hh, OT_QKV + (long)l*3*DD*DD, Q, Kb, nullptr, Vh, Vl,
                  BT, 3*DD, DD, 1, 0, 0, 0);
        rope_kernel<<<(BT*HT*32)/256, 256>>>(Q, Kb, Qh, Kh, Kl, TT, HT, DD, BT);
        fattn_kernel<<<dim3(TT/64, BB*HT, 1), 128, FATTN_SMEM>>>(
            Qh, Kh, Kl, Vh, Vl, Oh, TT, HT, DD, 0);
        hgemm(0, 2, Oh, OT_WO + (long)l*DD*DD, X, 0, BT, DD, DD, 1, nullptr, 1, 0,0,0,0);
        rms_kernel<<<BT, 256>>>(X, t_n2 + (long)l*DD, Hh, DD, BT, 0);
        hgemm(2, 2, Hh, OT_W1 + (long)l*DD*DFF, 0, M1h, BT, DFF, DD, 0, nullptr, 1, 0,0,0,0);
        hgemm(0, 2, M1h, OT_W2 + (long)l*DFF*DD, X, 0, BT, DD, DFF, 1, nullptr, 1, 0,0,0,0);
    }

    // ---- column projection ----
    tohalf_kernel<<<(BT*DD/4)/256, 256>>>(X, Hh, BT*DD/4);
    hgemm(0, 2, Hh, OC_IN, CS, 0, BT, DC, DD, 0, cin_b, CC, 0, (long)DD*DC, (long)BT*DC, DC);

    // ---- column layers ----
    for (int l = 0; l < LC; l++) {
        rms_kernel<<<CBT, 256>>>(CS, c_n1 + (long)l*DC, Hh, DC, BT, (long)LC*DC);
        hgemm_qkv(Hh, OC_QKV + (long)l*3*DC*DC, Q, Kb, nullptr, Vh, Vl,
                  BT, 3*DC, DC, CC, (long)BT*DC, (long)LC*3*DC*DC, (long)BT*DC);
        rope_kernel<<<(CBT*HC*32)/256, 256>>>(Q, Kb, Qh, Kh, Kl, TT, HC, DC, CBT);
        fattn_kernel<<<dim3(TT/64, BB*HC, CC), 128, FATTN_SMEM>>>(
            Qh, Kh, Kl, Vh, Vl, Oh, TT, HC, DC, (long)BT*DC);
        hgemm(0, 2, Oh, OC_WO + (long)l*DC*DC, CS, 0, BT, DC, DC, 1, nullptr, CC,
              (long)BT*DC, (long)LC*DC*DC, (long)BT*DC, 0);
        rms_kernel<<<CBT, 256>>>(CS, c_n2 + (long)l*DC, Hh, DC, BT, (long)LC*DC);
        hgemm(2, 2, Hh, OC_W1 + (long)l*DC*DFFC, 0, M1h, BT, DFFC, DC, 0, nullptr, CC,
              (long)BT*DC, (long)LC*DC*DFFC, (long)BT*DFFC, 0);
        hgemm(0, 2, M1h, OC_W2 + (long)l*DFFC*DC, CS, 0, BT, DC, DFFC, 1, nullptr, CC,
              (long)BT*DFFC, (long)LC*DFFC*DC, (long)BT*DC, 0);

        if (((l + 1) & 1) == 0) {
            int m = (l + 1)/2 - 1;
            rms_kernel<<<CBT, 256>>>(CS, m_n + (long)m*DC, Hh, DC, CBT, 0);
            hgemm_qkv(Hh, OM_QKV + (long)m*3*DC*DC, Q, Kb, Vb, nullptr, nullptr,
                      CBT, 3*DC, DC, 1, 0, 0, 0);
            merge_attn_kernel<<<(CC*BT*HC)/256, 256>>>(Q, Kb, Vb, Oh);
            hgemm(0, 2, Oh, OM_WO + (long)m*DC*DC, CS, 0, CBT, DC, DC, 1, nullptr, 1, 0,0,0,0);
        }
    }

    // ---- output head ----
    comb_kernel<<<(BT*DD/4)/256, 256>>>(CS, Hh);
    hgemm(0, 2, Hh, O_OP, Q, 0, BT, DD, DD, 0, nullptr, 1, 0,0,0,0);
    rms_kernel<<<BT, 256>>>(Q, fnorm, Hh, DD, BT, 0);
    hgemm(0, 1, Hh, O_EMB, out, 0, BT, BV, DD, 0, nullptr, 1, 0,0,0,0);
}

// round 14
// speedup vs baseline: 1.3752x; 1.0434x over previous
#include <cuda_runtime.h>
#include <cuda_fp16.h>
#include <math.h>
#include <stdint.h>

// ---------------- model constants ----------------
#define BV   32000
#define DD   1024
#define DFF  4096
#define LT   2
#define HT   16
#define CC   4
#define DC   256
#define DFFC 1024
#define LC   4
#define HC   4
#define NM   2
#define BB   2
#define TT   1024
#define BT   (BB*TT)     // 2048
#define CBT  (CC*BT)     // 8192

// ---------------- weight offsets ([N][K] fp16; QKV interleaved per layer) ----------------
constexpr long OT_QKV = 0;
constexpr long OT_WO  = OT_QKV + (long)LT*3*DD*DD;
constexpr long OT_W1  = OT_WO  + (long)LT*DD*DD;
constexpr long OT_W2  = OT_W1  + (long)LT*DD*DFF;
constexpr long OC_IN  = OT_W2  + (long)LT*DFF*DD;
constexpr long OC_QKV = OC_IN  + (long)CC*DD*DC;
constexpr long OC_WO  = OC_QKV + (long)CC*LC*3*DC*DC;
constexpr long OC_W1  = OC_WO  + (long)CC*LC*DC*DC;
constexpr long OC_W2  = OC_W1  + (long)CC*LC*DC*DFFC;
constexpr long OM_QKV = OC_W2  + (long)CC*LC*DFFC*DC;
constexpr long OM_WO  = OM_QKV + (long)NM*3*DC*DC;
constexpr long O_OP   = OM_WO  + (long)NM*DC*DC;
constexpr long O_EMB  = O_OP   + (long)DD*DD;
constexpr long WTOT   = O_EMB  + (long)BV*DD;

// ---------------- scratch (device globals) ----------------
__device__ float  g_X [BT*DD];
__device__ float  g_Q [BT*DD];
__device__ float  g_K [BT*DD];
__device__ float  g_V [BT*DD];
__device__ float  g_CS[CC*BT*DC];
__device__ __half g_Hh[BT*DD];
__device__ __half g_M1h[BT*DFF];
__device__ __half g_Oh[BT*DD];
__device__ __half g_Qh[BT*DD];
__device__ __half g_Kh[BT*DD];
__device__ __half g_Vh[BT*DD];
__device__ __half g_Wh[WTOT];
__device__ __half g_Wl[WTOT];

// ---------------- asm helpers ----------------
__device__ __forceinline__ void lm4(const __half* p, uint32_t* r)
{
    uint32_t a = (uint32_t)__cvta_generic_to_shared(p);
    asm volatile("ldmatrix.sync.aligned.m8n8.x4.shared.b16 {%0,%1,%2,%3}, [%4];"
        : "=r"(r[0]), "=r"(r[1]), "=r"(r[2]), "=r"(r[3]) : "r"(a));
}
__device__ __forceinline__ void lm4t(const __half* p, uint32_t* r)
{
    uint32_t a = (uint32_t)__cvta_generic_to_shared(p);
    asm volatile("ldmatrix.sync.aligned.m8n8.x4.trans.shared.b16 {%0,%1,%2,%3}, [%4];"
        : "=r"(r[0]), "=r"(r[1]), "=r"(r[2]), "=r"(r[3]) : "r"(a));
}
__device__ __forceinline__ void mma16816(float* c, const uint32_t* a, const uint32_t* b)
{
    asm volatile("mma.sync.aligned.m16n8k16.row.col.f32.f16.f16.f32 "
        "{%0,%1,%2,%3},{%4,%5,%6,%7},{%8,%9},{%0,%1,%2,%3};"
        : "+f"(c[0]), "+f"(c[1]), "+f"(c[2]), "+f"(c[3])
        : "r"(a[0]), "r"(a[1]), "r"(a[2]), "r"(a[3]), "r"(b[0]), "r"(b[1]));
}
__device__ __forceinline__ void cpasync16(const __half* dst, const __half* src)
{
    uint32_t d = (uint32_t)__cvta_generic_to_shared(dst);
    asm volatile("cp.async.cg.shared.global [%0], [%1], 16;" :: "r"(d), "l"(src));
}
__device__ __forceinline__ void cp_commit() { asm volatile("cp.async.commit_group;"); }
template<int N> __device__ __forceinline__ void cp_wait()
{ asm volatile("cp.async.wait_group %0;" :: "n"(N)); }

__device__ __forceinline__ float gelu1(float v)
{
    return 0.5f * v * (1.f + tanhf(0.7978845608028654f * (v + 0.044715f*v*v*v)));
}

// ---------------- HGEMM (cp.async double-buffered, champion mainloop) ----------------
// NT=2: A single fp16, B two-term (hh + h*lo) -> 2 MMA passes.  NT=1: plain.
// MODE 0: C fp32 (+accum+bias)  MODE 2: gelu + fp16-hi out
// MODE 3: fused QKV (N = 3*NW): if Hq != null -> all fp16 (Hq/Hk/Hv by sel),
//         else all fp32 (C/Ck/Cv by sel).
#define BM 128
#define BN 128
#define BKH 32
#define SSTR 40
#define GPER (BM*SSTR)

template<int NT, int MODE>
__global__ void __launch_bounds__(256) hgemm_kernel(
    const __half* __restrict__ Ah,
    const __half* __restrict__ Bh, const __half* __restrict__ Bl,
    const float* __restrict__ bias, float* __restrict__ C,
    __half* __restrict__ Coh,
    int M, int N, int K, int accum,
    long aBS, long bBS, long cBS, long biasBS,
    float* __restrict__ Ck, float* __restrict__ Cv,
    __half* __restrict__ Hq, __half* __restrict__ Hk, __half* __restrict__ Hv)
{
    extern __shared__ __half smp[];
    const int NARR = (NT == 2) ? 3 : 2;   // Ah, Bh, (Bl)

    Ah += blockIdx.z * aBS;
    Bh += blockIdx.z * bBS;
    if (MODE == 0) C += blockIdx.z * cBS;
    else if (MODE == 3) {
        if (Hq) { Hq += blockIdx.z * cBS; Hk += blockIdx.z * cBS; Hv += blockIdx.z * cBS; }
        else    { C += blockIdx.z * cBS; Ck += blockIdx.z * cBS; Cv += blockIdx.z * cBS; }
    } else { Coh += blockIdx.z * cBS; }
    if (NT == 2) Bl += blockIdx.z * bBS;
    if (bias) bias += blockIdx.z * biasBS;

    int row0 = blockIdx.y * BM;
    int col0 = blockIdx.x * BN;
    int tid  = threadIdx.x;
    int lane = tid & 31;
    int wid  = tid >> 5;
    int wm0  = (wid >> 2) * 64;
    int wn0  = (wid & 3) * 32;

    float acc[4][4][4];
#pragma unroll
    for (int mt = 0; mt < 4; mt++)
#pragma unroll
        for (int nt = 0; nt < 4; nt++)
#pragma unroll
            for (int q = 0; q < 4; q++) acc[mt][nt][q] = 0.f;

    int a_r  = lane & 15;
    int a_ko = (lane >> 4) << 3;
    int b_n  = ((lane >> 4) << 3) + (lane & 7);
    int b_ko = ((lane >> 3) & 1) << 3;

    int nk = K / BKH;

    auto loadStage = [&](int st, int k0) {
        __half* dAh = smp + st * NARR * GPER;
        __half* dBh = dAh + GPER;
        __half* dBl = dAh + 2 * GPER;
#pragma unroll
        for (int c = tid; c < 512; c += 256) {
            int r = c >> 2, o = (c & 3) << 3;
            cpasync16(&dAh[r*SSTR + o], &Ah[(long)(row0 + r)*K + k0 + o]);
            cpasync16(&dBh[r*SSTR + o], &Bh[(long)(col0 + r)*K + k0 + o]);
            if (NT == 2)
                cpasync16(&dBl[r*SSTR + o], &Bl[(long)(col0 + r)*K + k0 + o]);
        }
    };

    loadStage(0, 0);
    cp_commit();

    for (int kt = 0; kt < nk; kt++) {
        int cur = kt & 1;
        if (kt + 1 < nk) {
            loadStage(cur ^ 1, (kt + 1) * BKH);
            cp_commit();
            cp_wait<1>();
        } else {
            cp_wait<0>();
        }
        __syncthreads();

        const __half* pAh = smp + cur * NARR * GPER;
        const __half* pBh = pAh + GPER;
        const __half* pBl = pAh + 2 * GPER;

#pragma unroll
        for (int ks = 0; ks < BKH; ks += 16) {
            uint32_t a_hi[4][4], b_hi[2][4];
#pragma unroll
            for (int mt = 0; mt < 4; mt++)
                lm4(&pAh[(wm0 + mt*16 + a_r)*SSTR + ks + a_ko], a_hi[mt]);
#pragma unroll
            for (int np = 0; np < 2; np++)
                lm4(&pBh[(wn0 + np*16 + b_n)*SSTR + ks + b_ko], b_hi[np]);
#pragma unroll
            for (int mt = 0; mt < 4; mt++)
#pragma unroll
                for (int nt = 0; nt < 4; nt++)
                    mma16816(acc[mt][nt], a_hi[mt], &b_hi[nt >> 1][(nt & 1)*2]);

            if (NT == 2) {
                uint32_t b_lo[2][4];
#pragma unroll
                for (int np = 0; np < 2; np++)
                    lm4(&pBl[(wn0 + np*16 + b_n)*SSTR + ks + b_ko], b_lo[np]);
#pragma unroll
                for (int mt = 0; mt < 4; mt++)
#pragma unroll
                    for (int nt = 0; nt < 4; nt++)
                        mma16816(acc[mt][nt], a_hi[mt], &b_lo[nt >> 1][(nt & 1)*2]);
            }
        }
        __syncthreads();
    }

    int g = lane >> 2, t = lane & 3;

    if (MODE == 3) {
        const int NW = N / 3;
        int sel = col0 / NW;
        int colb = col0 - sel*NW;
        if (Hq) {
            __half* Hf = (sel == 0) ? Hq : (sel == 1) ? Hk : Hv;
#pragma unroll
            for (int mt = 0; mt < 4; mt++) {
#pragma unroll
                for (int nt = 0; nt < 4; nt++) {
                    int r1  = row0 + wm0 + mt*16 + g;
                    int cix = colb + wn0 + nt*8 + 2*t;
                    long o0 = (long)r1*NW + cix;
                    long o1 = (long)(r1 + 8)*NW + cix;
                    *(__half2*)&Hf[o0] = __halves2half2(
                        __float2half(acc[mt][nt][0]), __float2half(acc[mt][nt][1]));
                    *(__half2*)&Hf[o1] = __halves2half2(
                        __float2half(acc[mt][nt][2]), __float2half(acc[mt][nt][3]));
                }
            }
        } else {
            float* Cf = (sel == 0) ? C : (sel == 1) ? Ck : Cv;
#pragma unroll
            for (int mt = 0; mt < 4; mt++) {
#pragma unroll
                for (int nt = 0; nt < 4; nt++) {
                    int r1  = row0 + wm0 + mt*16 + g;
                    int cix = colb + wn0 + nt*8 + 2*t;
                    long o0 = (long)r1*NW + cix;
                    long o1 = (long)(r1 + 8)*NW + cix;
                    *(float2*)&Cf[o0] = make_float2(acc[mt][nt][0], acc[mt][nt][1]);
                    *(float2*)&Cf[o1] = make_float2(acc[mt][nt][2], acc[mt][nt][3]);
                }
            }
        }
        return;
    }

#pragma unroll
    for (int mt = 0; mt < 4; mt++) {
#pragma unroll
        for (int nt = 0; nt < 4; nt++) {
            int r1  = row0 + wm0 + mt*16 + g;
            int cix = col0 + wn0 + nt*8 + 2*t;
            float bv0 = 0.f, bv1 = 0.f;
            if (bias) { bv0 = bias[cix]; bv1 = bias[cix + 1]; }
            float v00 = acc[mt][nt][0] + bv0, v01 = acc[mt][nt][1] + bv1;
            float v10 = acc[mt][nt][2] + bv0, v11 = acc[mt][nt][3] + bv1;
            long o0 = (long)r1*N + cix;
            long o1 = (long)(r1 + 8)*N + cix;
            if (MODE == 0) {
                if (accum) {
                    float2 p0 = *(float2*)&C[o0];
                    float2 p1 = *(float2*)&C[o1];
                    v00 += p0.x; v01 += p0.y;
                    v10 += p1.x; v11 += p1.y;
                }
                *(float2*)&C[o0] = make_float2(v00, v01);
                *(float2*)&C[o1] = make_float2(v10, v11);
            } else {
                if (MODE == 2) {
                    v00 = gelu1(v00); v01 = gelu1(v01);
                    v10 = gelu1(v10); v11 = gelu1(v11);
                }
                *(__half2*)&Coh[o0] = __halves2half2(__float2half(v00), __float2half(v01));
                *(__half2*)&Coh[o1] = __halves2half2(__float2half(v10), __float2half(v11));
            }
        }
    }
}

// ---------------- tensor-core flash attention (causal, hd=64, single fp16) ----------------
#define ASTR 72
#define FATTN_SMEM (3*64*ASTR*2)

__global__ void __launch_bounds__(128) fattn_kernel(
    const __half* __restrict__ Qh,
    const __half* __restrict__ Kh,
    const __half* __restrict__ Vh,
    __half* __restrict__ Oh,
    int T, int nh, int rstride, long colstride)
{
    extern __shared__ __half sm[];
    __half* sQh = sm;
    __half* sKh = sQh + 64*ASTR;
    __half* sVh = sKh + 64*ASTR;

    int qt = blockIdx.x;
    int b  = blockIdx.y / nh;
    int h  = blockIdx.y % nh;
    long base = (long)blockIdx.z * colstride + (long)h * 64;
    int q0  = qt * 64;
    int tid = threadIdx.x;
    int lane = tid & 31;
    int wid  = tid >> 5;
    int wrow = wid * 16;
    int g = lane >> 2, t4 = lane & 3;

#pragma unroll
    for (int c = tid; c < 512; c += 128) {
        int r = c >> 3, o = (c & 7) << 3;
        long src = base + (long)(b*T + q0 + r)*rstride + o;
        *(uint4*)&sQh[r*ASTR + o] = *(const uint4*)&Qh[src];
    }
    __syncthreads();

    int a_r  = lane & 15;
    int a_ko = (lane >> 4) << 3;
    int b_n  = ((lane >> 4) << 3) + (lane & 7);
    int b_ko = ((lane >> 3) & 1) << 3;
    int v_r  = (((lane >> 3) & 1) << 3) + (lane & 7);
    int v_c  = (lane >> 4) << 3;

    uint32_t qfh[4][4];
#pragma unroll
    for (int ks = 0; ks < 4; ks++)
        lm4(&sQh[(wrow + a_r)*ASTR + ks*16 + a_ko], qfh[ks]);

    float mrow[2] = {-1e30f, -1e30f};
    float lrow[2] = {0.f, 0.f};
    float oacc[8][4];
#pragma unroll
    for (int nt = 0; nt < 8; nt++)
#pragma unroll
        for (int e = 0; e < 4; e++) oacc[nt][e] = 0.f;

    for (int kt = 0; kt <= qt; kt++) {
        int k0 = kt * 64;
        __syncthreads();
#pragma unroll
        for (int c = tid; c < 512; c += 128) {
            int r = c >> 3, o = (c & 7) << 3;
            long src = base + (long)(b*T + k0 + r)*rstride + o;
            *(uint4*)&sKh[r*ASTR + o] = *(const uint4*)&Kh[src];
            *(uint4*)&sVh[r*ASTR + o] = *(const uint4*)&Vh[src];
        }
        __syncthreads();

        float S[8][4];
#pragma unroll
        for (int nt = 0; nt < 8; nt++)
#pragma unroll
            for (int e = 0; e < 4; e++) S[nt][e] = 0.f;

#pragma unroll
        for (int ks = 0; ks < 4; ks++) {
            uint32_t bh[4][4];
#pragma unroll
            for (int np = 0; np < 4; np++)
                lm4(&sKh[(np*16 + b_n)*ASTR + ks*16 + b_ko], bh[np]);
#pragma unroll
            for (int np = 0; np < 4; np++)
#pragma unroll
                for (int j = 0; j < 2; j++)
                    mma16816(S[np*2 + j], qfh[ks], &bh[np][j*2]);
        }

#pragma unroll
        for (int nt = 0; nt < 8; nt++)
#pragma unroll
            for (int e = 0; e < 4; e++) {
                S[nt][e] *= 0.125f;
                if (kt == qt) {
                    int col = k0 + nt*8 + t4*2 + (e & 1);
                    int row = q0 + wrow + g + ((e >> 1) << 3);
                    if (col > row) S[nt][e] = -1e30f;
                }
            }

        float P[8][4];
#pragma unroll
        for (int r = 0; r < 2; r++) {
            float mx = -1e30f;
#pragma unroll
            for (int nt = 0; nt < 8; nt++) {
                mx = fmaxf(mx, S[nt][2*r + 0]);
                mx = fmaxf(mx, S[nt][2*r + 1]);
            }
            mx = fmaxf(mx, __shfl_xor_sync(0xffffffffu, mx, 1));
            mx = fmaxf(mx, __shfl_xor_sync(0xffffffffu, mx, 2));
            float mnew  = fmaxf(mrow[r], mx);
            float alpha = __expf(mrow[r] - mnew);
            float rsum = 0.f;
#pragma unroll
            for (int nt = 0; nt < 8; nt++) {
                float p0 = __expf(S[nt][2*r + 0] - mnew);
                float p1 = __expf(S[nt][2*r + 1] - mnew);
                P[nt][2*r + 0] = p0; P[nt][2*r + 1] = p1;
                rsum += p0 + p1;
            }
            rsum += __shfl_xor_sync(0xffffffffu, rsum, 1);
            rsum += __shfl_xor_sync(0xffffffffu, rsum, 2);
            lrow[r] = lrow[r]*alpha + rsum;
            mrow[r] = mnew;
#pragma unroll
            for (int nt = 0; nt < 8; nt++) {
                oacc[nt][2*r + 0] *= alpha;
                oacc[nt][2*r + 1] *= alpha;
            }
        }

        uint32_t pah[4][4];
#pragma unroll
        for (int ks = 0; ks < 4; ks++) {
            int j0 = 2*ks, j1 = 2*ks + 1;
#pragma unroll
            for (int q = 0; q < 4; q++) {
                int jj = (q < 2) ? j0 : j1;
                int e0 = (q & 1) ? 2 : 0;
                __half h0 = __float2half(P[jj][e0]);
                __half h1 = __float2half(P[jj][e0 + 1]);
                pah[ks][q] = (uint32_t)__half_as_ushort(h0) |
                             ((uint32_t)__half_as_ushort(h1) << 16);
            }
        }

#pragma unroll
        for (int ks = 0; ks < 4; ks++) {
            uint32_t vh[4][4];
#pragma unroll
            for (int np = 0; np < 4; np++)
                lm4t(&sVh[(ks*16 + v_r)*ASTR + np*16 + v_c], vh[np]);
#pragma unroll
            for (int np = 0; np < 4; np++)
#pragma unroll
                for (int j = 0; j < 2; j++)
                    mma16816(oacc[np*2 + j], pah[ks], &vh[np][j*2]);
        }
    }

#pragma unroll
    for (int r = 0; r < 2; r++) {
        float inv = 1.f / lrow[r];
        int row = q0 + wrow + g + r*8;
        long ob = base + (long)(b*T + row)*rstride;
#pragma unroll
        for (int nt = 0; nt < 8; nt++) {
            float v0 = oacc[nt][2*r + 0] * inv;
            float v1 = oacc[nt][2*r + 1] * inv;
            int col = nt*8 + t4*2;
            *(__half2*)&Oh[ob + col] = __halves2half2(__float2half(v0), __float2half(v1));
        }
    }
}

// ---------------- weight transpose + fp16 split ----------------
__global__ void splitT4_kernel(const float* p0, const float* p1,
                               const float* p2, const float* p3,
                               __half* __restrict__ oh, __half* __restrict__ ol,
                               int K, int N, int perBatch, int ngroups, int interleave)
{
    __shared__ float tile[32][33];
    const float* ps[4] = {p0, p1, p2, p3};
    int gsel = blockIdx.z / perBatch;
    int bz   = blockIdx.z % perBatch;
    const float* in = ps[gsel] + (long)bz * K * N;
    long ob = (interleave ? (long)(bz*ngroups + gsel) : (long)blockIdx.z) * K * N;
    int n0 = blockIdx.x * 32, k0 = blockIdx.y * 32;
    int tx = threadIdx.x & 31, ty = threadIdx.x >> 5;
#pragma unroll
    for (int j = 0; j < 4; j++) {
        int r = ty*4 + j;
        tile[r][tx] = in[(long)(k0 + r)*N + n0 + tx];
    }
    __syncthreads();
#pragma unroll
    for (int j = 0; j < 4; j++) {
        int nn = ty*4 + j;
        float v = tile[tx][nn];
        __half h = __float2half(v);
        long o = ob + (long)(n0 + nn)*K + k0 + tx;
        oh[o] = h;
        ol[o] = __float2half(v - __half2float(h));
    }
}

__global__ void split1_kernel(const float* __restrict__ in, __half* __restrict__ oh, int n4)
{
    int i = blockIdx.x * blockDim.x + threadIdx.x;
    if (i >= n4) return;
    float4 v = ((const float4*)in)[i];
    oh[4*i + 0] = __float2half(v.x);
    oh[4*i + 1] = __float2half(v.y);
    oh[4*i + 2] = __float2half(v.z);
    oh[4*i + 3] = __float2half(v.w);
}

// ---------------- rmsnorm -> fp16 hi ----------------
__global__ void rms_kernel(const float* __restrict__ x, const float* __restrict__ w,
                           __half* __restrict__ oh,
                           int W, int rowsPerChunk, long wStride)
{
    int row = blockIdx.x;
    const float* xr = x + (long)row * W;
    const float* wr = w + (long)(row / rowsPerChunk) * wStride;
    float ss = 0.f;
    for (int i = threadIdx.x; i < W; i += 256) {
        float v = xr[i];
        ss += v * v;
    }
    __shared__ float red[8];
#pragma unroll
    for (int off = 16; off > 0; off >>= 1)
        ss += __shfl_xor_sync(0xffffffffu, ss, off);
    if ((threadIdx.x & 31) == 0) red[threadIdx.x >> 5] = ss;
    __syncthreads();
    float tot = red[0]+red[1]+red[2]+red[3]+red[4]+red[5]+red[6]+red[7];
    float inv = rsqrtf(tot / (float)W + 1e-6f);
    long rb = (long)row * W;
    for (int i = threadIdx.x; i < W; i += 256)
        oh[rb + i] = __float2half(xr[i] * inv * wr[i]);
}

// ---------------- rope: in-place rotate on fp16 q,k ----------------
__global__ void rope_kernel(__half* __restrict__ qh, __half* __restrict__ kh,
                            int T, int nh, int rstride, int nrows)
{
    int idx = blockIdx.x * blockDim.x + threadIdx.x;
    if (idx >= nrows * nh * 32) return;
    int i   = idx & 31;
    int h   = (idx >> 5) % nh;
    int row = idx / (32 * nh);
    int t   = row % T;
    float inv = __expf(-(float)(2*i) * (1.f/64.f) * 9.210340371976184f);
    float f = (float)t * inv;
    float s, c;
    sincosf(f, &s, &c);
    long bo = (long)row * rstride + h*64 + i;
    float q1 = __half2float(qh[bo]), q2 = __half2float(qh[bo + 32]);
    qh[bo]      = __float2half(q1*c - q2*s);
    qh[bo + 32] = __float2half(q2*c + q1*s);
    float k1 = __half2float(kh[bo]), k2 = __half2float(kh[bo + 32]);
    kh[bo]      = __float2half(k1*c - k2*s);
    kh[bo + 32] = __float2half(k2*c + k1*s);
}

// ---------------- embedding gather ----------------
__global__ void embed_kernel(float* __restrict__ X, const float* __restrict__ emb,
                             const int* __restrict__ ids)
{
    int row = blockIdx.x;
    int id  = ids[row];
    const float4* src = (const float4*)(emb + (long)id * DD);
    float4* dst = (float4*)(X + (long)row * DD);
    dst[threadIdx.x] = src[threadIdx.x];
}

// ---------------- cross-column merge attention (fp32 in, fp16 out) ----------------
__global__ void merge_attn_kernel(const float* __restrict__ Qm, const float* __restrict__ Km,
                                  const float* __restrict__ Vm,
                                  __half* __restrict__ Oh)
{
    int gid = blockIdx.x * blockDim.x + threadIdx.x;
    int h   = gid & 3;
    int row = (gid >> 2) & (BT - 1);
    int i   = gid >> 13;
    if (i >= CC) return;
    long base  = (long)row * DC + h*64;
    long cstep = (long)BT * DC;

    float4 q[16];
    const float4* qp = (const float4*)(Qm + i*cstep + base);
#pragma unroll
    for (int t = 0; t < 16; t++) q[t] = qp[t];

    float s[CC];
#pragma unroll
    for (int j = 0; j < CC; j++) {
        const float4* kp = (const float4*)(Km + j*cstep + base);
        float acc = 0.f;
#pragma unroll
        for (int t = 0; t < 16; t++) {
            float4 kv = kp[t];
            acc += q[t].x*kv.x + q[t].y*kv.y + q[t].z*kv.z + q[t].w*kv.w;
        }
        s[j] = acc * 0.125f;
    }
    float mm = fmaxf(fmaxf(s[0], s[1]), fmaxf(s[2], s[3]));
    float a[CC], sum = 0.f;
#pragma unroll
    for (int j = 0; j < CC; j++) { a[j] = __expf(s[j] - mm); sum += a[j]; }
    float isum = 1.f / sum;
#pragma unroll
    for (int j = 0; j < CC; j++) a[j] *= isum;

    float o[64];
#pragma unroll
    for (int t = 0; t < 64; t++) o[t] = 0.f;
#pragma unroll
    for (int j = 0; j < CC; j++) {
        const float4* vp = (const float4*)(Vm + j*cstep + base);
        float aj = a[j];
#pragma unroll
        for (int t = 0; t < 16; t++) {
            float4 vv = vp[t];
            o[4*t+0] = fmaf(aj, vv.x, o[4*t+0]);
            o[4*t+1] = fmaf(aj, vv.y, o[4*t+1]);
            o[4*t+2] = fmaf(aj, vv.z, o[4*t+2]);
            o[4*t+3] = fmaf(aj, vv.w, o[4*t+3]);
        }
    }
    long ob = i*cstep + base;
#pragma unroll
    for (int t = 0; t < 64; t++) Oh[ob + t] = __float2half(o[t]);
}

// ---------------- fp32 -> fp16 (vectorized) ----------------
__global__ void tohalf_kernel(const float* __restrict__ in, __half* __restrict__ oh, int n4)
{
    int i = blockIdx.x * blockDim.x + threadIdx.x;
    if (i >= n4) return;
    float4 v = ((const float4*)in)[i];
    oh[4L*i + 0] = __float2half(v.x);
    oh[4L*i + 1] = __float2half(v.y);
    oh[4L*i + 2] = __float2half(v.z);
    oh[4L*i + 3] = __float2half(v.w);
}

// ---------------- concat -> fp16 ----------------
__global__ void comb_kernel(const float* __restrict__ cs, __half* __restrict__ oh)
{
    int gid = blockIdx.x * blockDim.x + threadIdx.x;
    int d4  = gid & (DD/4 - 1);
    int row = gid / (DD/4);
    int d = d4 * 4;
    int c = d >> 8;
    int e = d & 255;
    float4 v = *(const float4*)(cs + (long)c*BT*DC + (long)row*DC + e);
    oh[4L*gid + 0] = __float2half(v.x);
    oh[4L*gid + 1] = __float2half(v.y);
    oh[4L*gid + 2] = __float2half(v.z);
    oh[4L*gid + 3] = __float2half(v.w);
}

// ---------------- host side ----------------
static __half *Wh_p, *Wl_p;
#define HG2_SMEM (2*3*GPER*2)
#define HG1_SMEM (2*2*GPER*2)

static inline void hgemm(int mode, int nt, const __half* Ah, long boff,
                         float* C, __half* Coh,
                         int M, int N, int K, int accum, const float* bias, int batch,
                         long aBS, long bBS, long cBS, long biasBS)
{
    dim3 grid(N/BN, M/BM, batch);
    if (nt == 2) {
        if (mode == 0)
            hgemm_kernel<2,0><<<grid, 256, HG2_SMEM>>>(Ah, Wh_p + boff, Wl_p + boff,
                bias, C, nullptr, M, N, K, accum, aBS, bBS, cBS, biasBS,
                nullptr, nullptr, nullptr, nullptr, nullptr);
        else
            hgemm_kernel<2,2><<<grid, 256, HG2_SMEM>>>(Ah, Wh_p + boff, Wl_p + boff,
                bias, nullptr, Coh, M, N, K, accum, aBS, bBS, cBS, biasBS,
                nullptr, nullptr, nullptr, nullptr, nullptr);
    } else {
        hgemm_kernel<1,0><<<grid, 256, HG1_SMEM>>>(Ah, Wh_p + boff, nullptr,
            bias, C, nullptr, M, N, K, accum, aBS, bBS, cBS, biasBS,
            nullptr, nullptr, nullptr, nullptr, nullptr);
    }
}

// fused QKV: all-half (Hq/Hk/Hv) when Hq != null, else all-fp32 (Cq/Ck/Cv)
static inline void hgemm_qkv(const __half* Ah, long boff,
                             float* Cq, float* Ck, float* Cv,
                             __half* Hq, __half* Hk, __half* Hv,
                             int M, int N, int K, int batch,
                             long aBS, long bBS, long cBS)
{
    dim3 grid(N/BN, M/BM, batch);
    hgemm_kernel<2,3><<<grid, 256, HG2_SMEM>>>(Ah, Wh_p + boff, Wl_p + boff,
        nullptr, Cq, nullptr, M, N, K, 0, aBS, bBS, cBS, 0, Ck, Cv, Hq, Hk, Hv);
}

static inline void splitT4(const float* a, const float* b, const float* c, const float* d,
                           long off, int K, int N, int perBatch, int ngroups, int interleave)
{
    splitT4_kernel<<<dim3(N/32, K/32, ngroups*perBatch), 256>>>(
        a, b, c, d, Wh_p + off, Wl_p + off, K, N, perBatch, ngroups, interleave);
}

extern "C" void kernel_launch(void* const* d_in, const int* in_sizes, int n_in,
                              void* d_out, int out_size)
{
    const int*   ids   = (const int*)d_in[0];
    const float* emb   = (const float*)d_in[1];
    const float* t_wq  = (const float*)d_in[2];
    const float* t_wk  = (const float*)d_in[3];
    const float* t_wv  = (const float*)d_in[4];
    const float* t_wo  = (const float*)d_in[5];
    const float* t_w1  = (const float*)d_in[6];
    const float* t_w2  = (const float*)d_in[7];
    const float* t_n1  = (const float*)d_in[8];
    const float* t_n2  = (const float*)d_in[9];
    const float* cin_w = (const float*)d_in[10];
    const float* cin_b = (const float*)d_in[11];
    const float* c_wq  = (const float*)d_in[12];
    const float* c_wk  = (const float*)d_in[13];
    const float* c_wv  = (const float*)d_in[14];
    const float* c_wo  = (const float*)d_in[15];
    const float* c_w1  = (const float*)d_in[16];
    const float* c_w2  = (const float*)d_in[17];
    const float* c_n1  = (const float*)d_in[18];
    const float* c_n2  = (const float*)d_in[19];
    const float* m_wq  = (const float*)d_in[20];
    const float* m_wk  = (const float*)d_in[21];
    const float* m_wv  = (const float*)d_in[22];
    const float* m_wo  = (const float*)d_in[23];
    const float* m_n   = (const float*)d_in[24];
    const float* oproj = (const float*)d_in[25];
    const float* fnorm = (const float*)d_in[26];
    float* out = (float*)d_out;

    void* p;
    cudaGetSymbolAddress(&p, g_X);   float*  X   = (float*)p;
    cudaGetSymbolAddress(&p, g_Q);   float*  Q   = (float*)p;
    cudaGetSymbolAddress(&p, g_K);   float*  Kb  = (float*)p;
    cudaGetSymbolAddress(&p, g_V);   float*  Vb  = (float*)p;
    cudaGetSymbolAddress(&p, g_CS);  float*  CS  = (float*)p;
    cudaGetSymbolAddress(&p, g_Hh);  __half* Hh  = (__half*)p;
    cudaGetSymbolAddress(&p, g_M1h); __half* M1h = (__half*)p;
    cudaGetSymbolAddress(&p, g_Oh);  __half* Oh  = (__half*)p;
    cudaGetSymbolAddress(&p, g_Qh);  __half* Qh  = (__half*)p;
    cudaGetSymbolAddress(&p, g_Kh);  __half* Kh  = (__half*)p;
    cudaGetSymbolAddress(&p, g_Vh);  __half* Vh  = (__half*)p;
    cudaGetSymbolAddress(&p, g_Wh);  Wh_p = (__half*)p;
    cudaGetSymbolAddress(&p, g_Wl);  Wl_p = (__half*)p;

    cudaFuncSetAttribute(hgemm_kernel<2,0>, cudaFuncAttributeMaxDynamicSharedMemorySize, HG2_SMEM);
    cudaFuncSetAttribute(hgemm_kernel<2,2>, cudaFuncAttributeMaxDynamicSharedMemorySize, HG2_SMEM);
    cudaFuncSetAttribute(hgemm_kernel<2,3>, cudaFuncAttributeMaxDynamicSharedMemorySize, HG2_SMEM);
    cudaFuncSetAttribute(hgemm_kernel<1,0>, cudaFuncAttributeMaxDynamicSharedMemorySize, HG1_SMEM);
    cudaFuncSetAttribute(fattn_kernel, cudaFuncAttributeMaxDynamicSharedMemorySize, FATTN_SMEM);

    // ---- weight conversion (batched; QKV interleaved per layer) ----
    splitT4(t_wq, t_wk, t_wv, nullptr, OT_QKV, DD, DD, LT, 3, 1);
    splitT4(t_wo, nullptr, nullptr, nullptr, OT_WO, DD, DD, LT, 1, 0);
    splitT4(t_w1, nullptr, nullptr, nullptr, OT_W1, DD, DFF, LT, 1, 0);
    splitT4(t_w2, nullptr, nullptr, nullptr, OT_W2, DFF, DD, LT, 1, 0);
    splitT4(cin_w, nullptr, nullptr, nullptr, OC_IN, DD, DC, CC, 1, 0);
    splitT4(c_wq, c_wk, c_wv, nullptr, OC_QKV, DC, DC, CC*LC, 3, 1);
    splitT4(c_wo, nullptr, nullptr, nullptr, OC_WO, DC, DC, CC*LC, 1, 0);
    splitT4(c_w1, nullptr, nullptr, nullptr, OC_W1, DC, DFFC, CC*LC, 1, 0);
    splitT4(c_w2, nullptr, nullptr, nullptr, OC_W2, DFFC, DC, CC*LC, 1, 0);
    splitT4(m_wq, m_wk, m_wv, nullptr, OM_QKV, DC, DC, NM, 3, 1);
    splitT4(m_wo, nullptr, nullptr, nullptr, OM_WO, DC, DC, NM, 1, 0);
    splitT4(oproj, nullptr, nullptr, nullptr, O_OP, DD, DD, 1, 1, 0);
    split1_kernel<<<(BV*DD/4 + 255)/256, 256>>>(emb, Wh_p + O_EMB, BV*DD/4);

    embed_kernel<<<BT, 256>>>(X, emb, ids);

    // ---- trunk ----
    for (int l = 0; l < LT; l++) {
        rms_kernel<<<BT, 256>>>(X, t_n1 + (long)l*DD, Hh, DD, BT, 0);
        hgemm_qkv(Hh, OT_QKV + (long)l*3*DD*DD, nullptr, nullptr, nullptr,
                  Qh, Kh, Vh, BT, 3*DD, DD, 1, 0, 0, 0);
        rope_kernel<<<(BT*HT*32)/256, 256>>>(Qh, Kh, TT, HT, DD, BT);
        fattn_kernel<<<dim3(TT/64, BB*HT, 1), 128, FATTN_SMEM>>>(
            Qh, Kh, Vh, Oh, TT, HT, DD, 0);
        hgemm(0, 2, Oh, OT_WO + (long)l*DD*DD, X, 0, BT, DD, DD, 1, nullptr, 1, 0,0,0,0);
        rms_kernel<<<BT, 256>>>(X, t_n2 + (long)l*DD, Hh, DD, BT, 0);
        hgemm(2, 2, Hh, OT_W1 + (long)l*DD*DFF, 0, M1h, BT, DFF, DD, 0, nullptr, 1, 0,0,0,0);
        hgemm(0, 2, M1h, OT_W2 + (long)l*DFF*DD, X, 0, BT, DD, DFF, 1, nullptr, 1, 0,0,0,0);
    }

    // ---- column projection ----
    tohalf_kernel<<<(BT*DD/4)/256, 256>>>(X, Hh, BT*DD/4);
    hgemm(0, 2, Hh, OC_IN, CS, 0, BT, DC, DD, 0, cin_b, CC, 0, (long)DD*DC, (long)BT*DC, DC);

    // ---- column layers ----
    for (int l = 0; l < LC; l++) {
        rms_kernel<<<CBT, 256>>>(CS, c_n1 + (long)l*DC, Hh, DC, BT, (long)LC*DC);
        hgemm_qkv(Hh, OC_QKV + (long)l*3*DC*DC, nullptr, nullptr, nullptr,
                  Qh, Kh, Vh, BT, 3*DC, DC, CC,
                  (long)BT*DC, (long)LC*3*DC*DC, (long)BT*DC);
        rope_kernel<<<(CBT*HC*32)/256, 256>>>(Qh, Kh, TT, HC, DC, CBT);
        fattn_kernel<<<dim3(TT/64, BB*HC, CC), 128, FATTN_SMEM>>>(
            Qh, Kh, Vh, Oh, TT, HC, DC, (long)BT*DC);
        hgemm(0, 2, Oh, OC_WO + (long)l*DC*DC, CS, 0, BT, DC, DC, 1, nullptr, CC,
              (long)BT*DC, (long)LC*DC*DC, (long)BT*DC, 0);
        rms_kernel<<<CBT, 256>>>(CS, c_n2 + (long)l*DC, Hh, DC, BT, (long)LC*DC);
        hgemm(2, 2, Hh, OC_W1 + (long)l*DC*DFFC, 0, M1h, BT, DFFC, DC, 0, nullptr, CC,
              (long)BT*DC, (long)LC*DC*DFFC, (long)BT*DFFC, 0);
        hgemm(0, 2, M1h, OC_W2 + (long)l*DFFC*DC, CS, 0, BT, DC, DFFC, 1, nullptr, CC,
              (long)BT*DFFC, (long)LC*DFFC*DC, (long)BT*DC, 0);

        if (((l + 1) & 1) == 0) {
            int m = (l + 1)/2 - 1;
            rms_kernel<<<CBT, 256>>>(CS, m_n + (long)m*DC, Hh, DC, CBT, 0);
            hgemm_qkv(Hh, OM_QKV + (long)m*3*DC*DC, Q, Kb, Vb,
                      nullptr, nullptr, nullptr, CBT, 3*DC, DC, 1, 0, 0, 0);
            merge_attn_kernel<<<(CC*BT*HC)/256, 256>>>(Q, Kb, Vb, Oh);
            hgemm(0, 2, Oh, OM_WO + (long)m*DC*DC, CS, 0, CBT, DC, DC, 1, nullptr, 1, 0,0,0,0);
        }
    }

    // ---- output head ----
    comb_kernel<<<(BT*DD/4)/256, 256>>>(CS, Hh);
    hgemm(0, 2, Hh, O_OP, Q, 0, BT, DD, DD, 0, nullptr, 1, 0,0,0,0);
    rms_kernel<<<BT, 256>>>(Q, fnorm, Hh, DD, BT, 0);
    hgemm(0, 1, Hh, O_EMB, out, 0, BT, BV, DD, 0, nullptr, 1, 0,0,0,0);
}

// round 15
// speedup vs baseline: 1.4318x; 1.0411x over previous
#include <cuda_runtime.h>
#include <cuda_fp16.h>
#include <math.h>
#include <stdint.h>

// ---------------- model constants ----------------
#define BV   32000
#define DD   1024
#define DFF  4096
#define LT   2
#define HT   16
#define CC   4
#define DC   256
#define DFFC 1024
#define LC   4
#define HC   4
#define NM   2
#define BB   2
#define TT   1024
#define BT   (BB*TT)     // 2048
#define CBT  (CC*BT)     // 8192

// ---------------- weight offsets ([N][K] fp16; QKV interleaved per layer) ----------------
constexpr long OT_QKV = 0;
constexpr long OT_WO  = OT_QKV + (long)LT*3*DD*DD;
constexpr long OT_W1  = OT_WO  + (long)LT*DD*DD;
constexpr long OT_W2  = OT_W1  + (long)LT*DD*DFF;
constexpr long OC_IN  = OT_W2  + (long)LT*DFF*DD;
constexpr long OC_QKV = OC_IN  + (long)CC*DD*DC;
constexpr long OC_WO  = OC_QKV + (long)CC*LC*3*DC*DC;
constexpr long OC_W1  = OC_WO  + (long)CC*LC*DC*DC;
constexpr long OC_W2  = OC_W1  + (long)CC*LC*DC*DFFC;
constexpr long OM_QKV = OC_W2  + (long)CC*LC*DFFC*DC;
constexpr long OM_WO  = OM_QKV + (long)NM*3*DC*DC;
constexpr long O_OP   = OM_WO  + (long)NM*DC*DC;
constexpr long O_EMB  = O_OP   + (long)DD*DD;
constexpr long WTOT   = O_EMB  + (long)BV*DD;

// ---------------- scratch (device globals) ----------------
__device__ float  g_X [BT*DD];
__device__ float  g_Q [BT*DD];
__device__ float  g_K [BT*DD];
__device__ float  g_V [BT*DD];
__device__ float  g_CS[CC*BT*DC];
__device__ __half g_Hh[BT*DD];
__device__ __half g_M1h[BT*DFF];
__device__ __half g_Oh[BT*DD];
__device__ __half g_Qh[BT*DD];
__device__ __half g_Kh[BT*DD];
__device__ __half g_Vh[BT*DD];
__device__ __half g_Wh[WTOT];
__device__ __half g_Wl[WTOT];

// ---------------- asm helpers ----------------
__device__ __forceinline__ void lm4(const __half* p, uint32_t* r)
{
    uint32_t a = (uint32_t)__cvta_generic_to_shared(p);
    asm volatile("ldmatrix.sync.aligned.m8n8.x4.shared.b16 {%0,%1,%2,%3}, [%4];"
        : "=r"(r[0]), "=r"(r[1]), "=r"(r[2]), "=r"(r[3]) : "r"(a));
}
__device__ __forceinline__ void lm4t(const __half* p, uint32_t* r)
{
    uint32_t a = (uint32_t)__cvta_generic_to_shared(p);
    asm volatile("ldmatrix.sync.aligned.m8n8.x4.trans.shared.b16 {%0,%1,%2,%3}, [%4];"
        : "=r"(r[0]), "=r"(r[1]), "=r"(r[2]), "=r"(r[3]) : "r"(a));
}
__device__ __forceinline__ void mma16816(float* c, const uint32_t* a, const uint32_t* b)
{
    asm volatile("mma.sync.aligned.m16n8k16.row.col.f32.f16.f16.f32 "
        "{%0,%1,%2,%3},{%4,%5,%6,%7},{%8,%9},{%0,%1,%2,%3};"
        : "+f"(c[0]), "+f"(c[1]), "+f"(c[2]), "+f"(c[3])
        : "r"(a[0]), "r"(a[1]), "r"(a[2]), "r"(a[3]), "r"(b[0]), "r"(b[1]));
}
__device__ __forceinline__ void cpasync16(const __half* dst, const __half* src)
{
    uint32_t d = (uint32_t)__cvta_generic_to_shared(dst);
    asm volatile("cp.async.cg.shared.global [%0], [%1], 16;" :: "r"(d), "l"(src));
}
__device__ __forceinline__ void cp_commit() { asm volatile("cp.async.commit_group;"); }
template<int N> __device__ __forceinline__ void cp_wait()
{ asm volatile("cp.async.wait_group %0;" :: "n"(N)); }

__device__ __forceinline__ float gelu1(float v)
{
    return 0.5f * v * (1.f + tanhf(0.7978845608028654f * (v + 0.044715f*v*v*v)));
}

// ---------------- HGEMM (cp.async double-buffered, champion mainloop) ----------------
// NT=2: A single fp16, B two-term (hh + h*lo) -> 2 MMA passes.  NT=1: plain.
// MODE 0: C fp32 (+accum+bias)  MODE 2: gelu + fp16-hi out
// MODE 3: fused QKV (N = 3*NW): if Hq != null -> all fp16 (Hq/Hk/Hv by sel),
//         else all fp32 (C/Ck/Cv by sel).
#define BM 128
#define BN 128
#define BKH 32
#define SSTR 40
#define GPER (BM*SSTR)

template<int NT, int MODE>
__global__ void __launch_bounds__(256) hgemm_kernel(
    const __half* __restrict__ Ah,
    const __half* __restrict__ Bh, const __half* __restrict__ Bl,
    const float* __restrict__ bias, float* __restrict__ C,
    __half* __restrict__ Coh,
    int M, int N, int K, int accum,
    long aBS, long bBS, long cBS, long biasBS,
    float* __restrict__ Ck, float* __restrict__ Cv,
    __half* __restrict__ Hq, __half* __restrict__ Hk, __half* __restrict__ Hv)
{
    extern __shared__ __half smp[];
    const int NARR = (NT == 2) ? 3 : 2;   // Ah, Bh, (Bl)

    Ah += blockIdx.z * aBS;
    Bh += blockIdx.z * bBS;
    if (MODE == 0) C += blockIdx.z * cBS;
    else if (MODE == 3) {
        if (Hq) { Hq += blockIdx.z * cBS; Hk += blockIdx.z * cBS; Hv += blockIdx.z * cBS; }
        else    { C += blockIdx.z * cBS; Ck += blockIdx.z * cBS; Cv += blockIdx.z * cBS; }
    } else { Coh += blockIdx.z * cBS; }
    if (NT == 2) Bl += blockIdx.z * bBS;
    if (bias) bias += blockIdx.z * biasBS;

    int row0 = blockIdx.y * BM;
    int col0 = blockIdx.x * BN;
    int tid  = threadIdx.x;
    int lane = tid & 31;
    int wid  = tid >> 5;
    int wm0  = (wid >> 2) * 64;
    int wn0  = (wid & 3) * 32;

    float acc[4][4][4];
#pragma unroll
    for (int mt = 0; mt < 4; mt++)
#pragma unroll
        for (int nt = 0; nt < 4; nt++)
#pragma unroll
            for (int q = 0; q < 4; q++) acc[mt][nt][q] = 0.f;

    int a_r  = lane & 15;
    int a_ko = (lane >> 4) << 3;
    int b_n  = ((lane >> 4) << 3) + (lane & 7);
    int b_ko = ((lane >> 3) & 1) << 3;

    int nk = K / BKH;

    auto loadStage = [&](int st, int k0) {
        __half* dAh = smp + st * NARR * GPER;
        __half* dBh = dAh + GPER;
        __half* dBl = dAh + 2 * GPER;
#pragma unroll
        for (int c = tid; c < 512; c += 256) {
            int r = c >> 2, o = (c & 3) << 3;
            cpasync16(&dAh[r*SSTR + o], &Ah[(long)(row0 + r)*K + k0 + o]);
            cpasync16(&dBh[r*SSTR + o], &Bh[(long)(col0 + r)*K + k0 + o]);
            if (NT == 2)
                cpasync16(&dBl[r*SSTR + o], &Bl[(long)(col0 + r)*K + k0 + o]);
        }
    };

    loadStage(0, 0);
    cp_commit();

    for (int kt = 0; kt < nk; kt++) {
        int cur = kt & 1;
        if (kt + 1 < nk) {
            loadStage(cur ^ 1, (kt + 1) * BKH);
            cp_commit();
            cp_wait<1>();
        } else {
            cp_wait<0>();
        }
        __syncthreads();

        const __half* pAh = smp + cur * NARR * GPER;
        const __half* pBh = pAh + GPER;
        const __half* pBl = pAh + 2 * GPER;

#pragma unroll
        for (int ks = 0; ks < BKH; ks += 16) {
            uint32_t a_hi[4][4], b_hi[2][4];
#pragma unroll
            for (int mt = 0; mt < 4; mt++)
                lm4(&pAh[(wm0 + mt*16 + a_r)*SSTR + ks + a_ko], a_hi[mt]);
#pragma unroll
            for (int np = 0; np < 2; np++)
                lm4(&pBh[(wn0 + np*16 + b_n)*SSTR + ks + b_ko], b_hi[np]);
#pragma unroll
            for (int mt = 0; mt < 4; mt++)
#pragma unroll
                for (int nt = 0; nt < 4; nt++)
                    mma16816(acc[mt][nt], a_hi[mt], &b_hi[nt >> 1][(nt & 1)*2]);

            if (NT == 2) {
                uint32_t b_lo[2][4];
#pragma unroll
                for (int np = 0; np < 2; np++)
                    lm4(&pBl[(wn0 + np*16 + b_n)*SSTR + ks + b_ko], b_lo[np]);
#pragma unroll
                for (int mt = 0; mt < 4; mt++)
#pragma unroll
                    for (int nt = 0; nt < 4; nt++)
                        mma16816(acc[mt][nt], a_hi[mt], &b_lo[nt >> 1][(nt & 1)*2]);
            }
        }
        __syncthreads();
    }

    int g = lane >> 2, t = lane & 3;

    if (MODE == 3) {
        const int NW = N / 3;
        int sel = col0 / NW;
        int colb = col0 - sel*NW;
        if (Hq) {
            __half* Hf = (sel == 0) ? Hq : (sel == 1) ? Hk : Hv;
#pragma unroll
            for (int mt = 0; mt < 4; mt++) {
#pragma unroll
                for (int nt = 0; nt < 4; nt++) {
                    int r1  = row0 + wm0 + mt*16 + g;
                    int cix = colb + wn0 + nt*8 + 2*t;
                    long o0 = (long)r1*NW + cix;
                    long o1 = (long)(r1 + 8)*NW + cix;
                    *(__half2*)&Hf[o0] = __halves2half2(
                        __float2half(acc[mt][nt][0]), __float2half(acc[mt][nt][1]));
                    *(__half2*)&Hf[o1] = __halves2half2(
                        __float2half(acc[mt][nt][2]), __float2half(acc[mt][nt][3]));
                }
            }
        } else {
            float* Cf = (sel == 0) ? C : (sel == 1) ? Ck : Cv;
#pragma unroll
            for (int mt = 0; mt < 4; mt++) {
#pragma unroll
                for (int nt = 0; nt < 4; nt++) {
                    int r1  = row0 + wm0 + mt*16 + g;
                    int cix = colb + wn0 + nt*8 + 2*t;
                    long o0 = (long)r1*NW + cix;
                    long o1 = (long)(r1 + 8)*NW + cix;
                    *(float2*)&Cf[o0] = make_float2(acc[mt][nt][0], acc[mt][nt][1]);
                    *(float2*)&Cf[o1] = make_float2(acc[mt][nt][2], acc[mt][nt][3]);
                }
            }
        }
        return;
    }

#pragma unroll
    for (int mt = 0; mt < 4; mt++) {
#pragma unroll
        for (int nt = 0; nt < 4; nt++) {
            int r1  = row0 + wm0 + mt*16 + g;
            int cix = col0 + wn0 + nt*8 + 2*t;
            float bv0 = 0.f, bv1 = 0.f;
            if (bias) { bv0 = bias[cix]; bv1 = bias[cix + 1]; }
            float v00 = acc[mt][nt][0] + bv0, v01 = acc[mt][nt][1] + bv1;
            float v10 = acc[mt][nt][2] + bv0, v11 = acc[mt][nt][3] + bv1;
            long o0 = (long)r1*N + cix;
            long o1 = (long)(r1 + 8)*N + cix;
            if (MODE == 0) {
                if (accum) {
                    float2 p0 = *(float2*)&C[o0];
                    float2 p1 = *(float2*)&C[o1];
                    v00 += p0.x; v01 += p0.y;
                    v10 += p1.x; v11 += p1.y;
                }
                *(float2*)&C[o0] = make_float2(v00, v01);
                *(float2*)&C[o1] = make_float2(v10, v11);
            } else {
                if (MODE == 2) {
                    v00 = gelu1(v00); v01 = gelu1(v01);
                    v10 = gelu1(v10); v11 = gelu1(v11);
                }
                *(__half2*)&Coh[o0] = __halves2half2(__float2half(v00), __float2half(v01));
                *(__half2*)&Coh[o1] = __halves2half2(__float2half(v10), __float2half(v11));
            }
        }
    }
}

// ---------------- tensor-core flash attention (causal, hd=64, single fp16) ----------------
#define ASTR 72
#define FATTN_SMEM (3*64*ASTR*2)

__global__ void __launch_bounds__(128) fattn_kernel(
    const __half* __restrict__ Qh,
    const __half* __restrict__ Kh,
    const __half* __restrict__ Vh,
    __half* __restrict__ Oh,
    int T, int nh, int rstride, long colstride)
{
    extern __shared__ __half sm[];
    __half* sQh = sm;
    __half* sKh = sQh + 64*ASTR;
    __half* sVh = sKh + 64*ASTR;

    int qt = blockIdx.x;
    int b  = blockIdx.y / nh;
    int h  = blockIdx.y % nh;
    long base = (long)blockIdx.z * colstride + (long)h * 64;
    int q0  = qt * 64;
    int tid = threadIdx.x;
    int lane = tid & 31;
    int wid  = tid >> 5;
    int wrow = wid * 16;
    int g = lane >> 2, t4 = lane & 3;

#pragma unroll
    for (int c = tid; c < 512; c += 128) {
        int r = c >> 3, o = (c & 7) << 3;
        long src = base + (long)(b*T + q0 + r)*rstride + o;
        *(uint4*)&sQh[r*ASTR + o] = *(const uint4*)&Qh[src];
    }
    __syncthreads();

    int a_r  = lane & 15;
    int a_ko = (lane >> 4) << 3;
    int b_n  = ((lane >> 4) << 3) + (lane & 7);
    int b_ko = ((lane >> 3) & 1) << 3;
    int v_r  = (((lane >> 3) & 1) << 3) + (lane & 7);
    int v_c  = (lane >> 4) << 3;

    uint32_t qfh[4][4];
#pragma unroll
    for (int ks = 0; ks < 4; ks++)
        lm4(&sQh[(wrow + a_r)*ASTR + ks*16 + a_ko], qfh[ks]);

    float mrow[2] = {-1e30f, -1e30f};
    float lrow[2] = {0.f, 0.f};
    float oacc[8][4];
#pragma unroll
    for (int nt = 0; nt < 8; nt++)
#pragma unroll
        for (int e = 0; e < 4; e++) oacc[nt][e] = 0.f;

    for (int kt = 0; kt <= qt; kt++) {
        int k0 = kt * 64;
        __syncthreads();
#pragma unroll
        for (int c = tid; c < 512; c += 128) {
            int r = c >> 3, o = (c & 7) << 3;
            long src = base + (long)(b*T + k0 + r)*rstride + o;
            *(uint4*)&sKh[r*ASTR + o] = *(const uint4*)&Kh[src];
            *(uint4*)&sVh[r*ASTR + o] = *(const uint4*)&Vh[src];
        }
        __syncthreads();

        float S[8][4];
#pragma unroll
        for (int nt = 0; nt < 8; nt++)
#pragma unroll
            for (int e = 0; e < 4; e++) S[nt][e] = 0.f;

#pragma unroll
        for (int ks = 0; ks < 4; ks++) {
            uint32_t bh[4][4];
#pragma unroll
            for (int np = 0; np < 4; np++)
                lm4(&sKh[(np*16 + b_n)*ASTR + ks*16 + b_ko], bh[np]);
#pragma unroll
            for (int np = 0; np < 4; np++)
#pragma unroll
                for (int j = 0; j < 2; j++)
                    mma16816(S[np*2 + j], qfh[ks], &bh[np][j*2]);
        }

#pragma unroll
        for (int nt = 0; nt < 8; nt++)
#pragma unroll
            for (int e = 0; e < 4; e++) {
                S[nt][e] *= 0.125f;
                if (kt == qt) {
                    int col = k0 + nt*8 + t4*2 + (e & 1);
                    int row = q0 + wrow + g + ((e >> 1) << 3);
                    if (col > row) S[nt][e] = -1e30f;
                }
            }

        float P[8][4];
#pragma unroll
        for (int r = 0; r < 2; r++) {
            float mx = -1e30f;
#pragma unroll
            for (int nt = 0; nt < 8; nt++) {
                mx = fmaxf(mx, S[nt][2*r + 0]);
                mx = fmaxf(mx, S[nt][2*r + 1]);
            }
            mx = fmaxf(mx, __shfl_xor_sync(0xffffffffu, mx, 1));
            mx = fmaxf(mx, __shfl_xor_sync(0xffffffffu, mx, 2));
            float mnew  = fmaxf(mrow[r], mx);
            float alpha = __expf(mrow[r] - mnew);
            float rsum = 0.f;
#pragma unroll
            for (int nt = 0; nt < 8; nt++) {
                float p0 = __expf(S[nt][2*r + 0] - mnew);
                float p1 = __expf(S[nt][2*r + 1] - mnew);
                P[nt][2*r + 0] = p0; P[nt][2*r + 1] = p1;
                rsum += p0 + p1;
            }
            rsum += __shfl_xor_sync(0xffffffffu, rsum, 1);
            rsum += __shfl_xor_sync(0xffffffffu, rsum, 2);
            lrow[r] = lrow[r]*alpha + rsum;
            mrow[r] = mnew;
#pragma unroll
            for (int nt = 0; nt < 8; nt++) {
                oacc[nt][2*r + 0] *= alpha;
                oacc[nt][2*r + 1] *= alpha;
            }
        }

        uint32_t pah[4][4];
#pragma unroll
        for (int ks = 0; ks < 4; ks++) {
            int j0 = 2*ks, j1 = 2*ks + 1;
#pragma unroll
            for (int q = 0; q < 4; q++) {
                int jj = (q < 2) ? j0 : j1;
                int e0 = (q & 1) ? 2 : 0;
                __half h0 = __float2half(P[jj][e0]);
                __half h1 = __float2half(P[jj][e0 + 1]);
                pah[ks][q] = (uint32_t)__half_as_ushort(h0) |
                             ((uint32_t)__half_as_ushort(h1) << 16);
            }
        }

#pragma unroll
        for (int ks = 0; ks < 4; ks++) {
            uint32_t vh[4][4];
#pragma unroll
            for (int np = 0; np < 4; np++)
                lm4t(&sVh[(ks*16 + v_r)*ASTR + np*16 + v_c], vh[np]);
#pragma unroll
            for (int np = 0; np < 4; np++)
#pragma unroll
                for (int j = 0; j < 2; j++)
                    mma16816(oacc[np*2 + j], pah[ks], &vh[np][j*2]);
        }
    }

#pragma unroll
    for (int r = 0; r < 2; r++) {
        float inv = 1.f / lrow[r];
        int row = q0 + wrow + g + r*8;
        long ob = base + (long)(b*T + row)*rstride;
#pragma unroll
        for (int nt = 0; nt < 8; nt++) {
            float v0 = oacc[nt][2*r + 0] * inv;
            float v1 = oacc[nt][2*r + 1] * inv;
            int col = nt*8 + t4*2;
            *(__half2*)&Oh[ob + col] = __halves2half2(__float2half(v0), __float2half(v1));
        }
    }
}

// ---------------- weight transpose + fp16 split ----------------
__global__ void splitT4_kernel(const float* p0, const float* p1,
                               const float* p2, const float* p3,
                               __half* __restrict__ oh, __half* __restrict__ ol,
                               int K, int N, int perBatch, int ngroups, int interleave)
{
    __shared__ float tile[32][33];
    const float* ps[4] = {p0, p1, p2, p3};
    int gsel = blockIdx.z / perBatch;
    int bz   = blockIdx.z % perBatch;
    const float* in = ps[gsel] + (long)bz * K * N;
    long ob = (interleave ? (long)(bz*ngroups + gsel) : (long)blockIdx.z) * K * N;
    int n0 = blockIdx.x * 32, k0 = blockIdx.y * 32;
    int tx = threadIdx.x & 31, ty = threadIdx.x >> 5;
#pragma unroll
    for (int j = 0; j < 4; j++) {
        int r = ty*4 + j;
        tile[r][tx] = in[(long)(k0 + r)*N + n0 + tx];
    }
    __syncthreads();
#pragma unroll
    for (int j = 0; j < 4; j++) {
        int nn = ty*4 + j;
        float v = tile[tx][nn];
        __half h = __float2half(v);
        long o = ob + (long)(n0 + nn)*K + k0 + tx;
        oh[o] = h;
        ol[o] = __float2half(v - __half2float(h));
    }
}

__global__ void split1_kernel(const float* __restrict__ in, __half* __restrict__ oh, int n4)
{
    int i = blockIdx.x * blockDim.x + threadIdx.x;
    if (i >= n4) return;
    float4 v = ((const float4*)in)[i];
    oh[4*i + 0] = __float2half(v.x);
    oh[4*i + 1] = __float2half(v.y);
    oh[4*i + 2] = __float2half(v.z);
    oh[4*i + 3] = __float2half(v.w);
}

// ---------------- rmsnorm -> fp16 hi ----------------
__global__ void rms_kernel(const float* __restrict__ x, const float* __restrict__ w,
                           __half* __restrict__ oh,
                           int W, int rowsPerChunk, long wStride)
{
    int row = blockIdx.x;
    const float* xr = x + (long)row * W;
    const float* wr = w + (long)(row / rowsPerChunk) * wStride;
    float ss = 0.f;
    for (int i = threadIdx.x; i < W; i += 256) {
        float v = xr[i];
        ss += v * v;
    }
    __shared__ float red[8];
#pragma unroll
    for (int off = 16; off > 0; off >>= 1)
        ss += __shfl_xor_sync(0xffffffffu, ss, off);
    if ((threadIdx.x & 31) == 0) red[threadIdx.x >> 5] = ss;
    __syncthreads();
    float tot = red[0]+red[1]+red[2]+red[3]+red[4]+red[5]+red[6]+red[7];
    float inv = rsqrtf(tot / (float)W + 1e-6f);
    long rb = (long)row * W;
    for (int i = threadIdx.x; i < W; i += 256)
        oh[rb + i] = __float2half(xr[i] * inv * wr[i]);
}

// ---------------- rope: in-place rotate on fp16 q,k ----------------
__global__ void rope_kernel(__half* __restrict__ qh, __half* __restrict__ kh,
                            int T, int nh, int rstride, int nrows)
{
    int idx = blockIdx.x * blockDim.x + threadIdx.x;
    if (idx >= nrows * nh * 32) return;
    int i   = idx & 31;
    int h   = (idx >> 5) % nh;
    int row = idx / (32 * nh);
    int t   = row % T;
    float inv = __expf(-(float)(2*i) * (1.f/64.f) * 9.210340371976184f);
    float f = (float)t * inv;
    float s, c;
    sincosf(f, &s, &c);
    long bo = (long)row * rstride + h*64 + i;
    float q1 = __half2float(qh[bo]), q2 = __half2float(qh[bo + 32]);
    qh[bo]      = __float2half(q1*c - q2*s);
    qh[bo + 32] = __float2half(q2*c + q1*s);
    float k1 = __half2float(kh[bo]), k2 = __half2float(kh[bo + 32]);
    kh[bo]      = __float2half(k1*c - k2*s);
    kh[bo + 32] = __float2half(k2*c + k1*s);
}

// ---------------- embedding gather ----------------
__global__ void embed_kernel(float* __restrict__ X, const float* __restrict__ emb,
                             const int* __restrict__ ids)
{
    int row = blockIdx.x;
    int id  = ids[row];
    const float4* src = (const float4*)(emb + (long)id * DD);
    float4* dst = (float4*)(X + (long)row * DD);
    dst[threadIdx.x] = src[threadIdx.x];
}

// ---------------- cross-column merge attention (fp32 in, fp16 out) ----------------
__global__ void merge_attn_kernel(const float* __restrict__ Qm, const float* __restrict__ Km,
                                  const float* __restrict__ Vm,
                                  __half* __restrict__ Oh)
{
    int gid = blockIdx.x * blockDim.x + threadIdx.x;
    int h   = gid & 3;
    int row = (gid >> 2) & (BT - 1);
    int i   = gid >> 13;
    if (i >= CC) return;
    long base  = (long)row * DC + h*64;
    long cstep = (long)BT * DC;

    float4 q[16];
    const float4* qp = (const float4*)(Qm + i*cstep + base);
#pragma unroll
    for (int t = 0; t < 16; t++) q[t] = qp[t];

    float s[CC];
#pragma unroll
    for (int j = 0; j < CC; j++) {
        const float4* kp = (const float4*)(Km + j*cstep + base);
        float acc = 0.f;
#pragma unroll
        for (int t = 0; t < 16; t++) {
            float4 kv = kp[t];
            acc += q[t].x*kv.x + q[t].y*kv.y + q[t].z*kv.z + q[t].w*kv.w;
        }
        s[j] = acc * 0.125f;
    }
    float mm = fmaxf(fmaxf(s[0], s[1]), fmaxf(s[2], s[3]));
    float a[CC], sum = 0.f;
#pragma unroll
    for (int j = 0; j < CC; j++) { a[j] = __expf(s[j] - mm); sum += a[j]; }
    float isum = 1.f / sum;
#pragma unroll
    for (int j = 0; j < CC; j++) a[j] *= isum;

    float o[64];
#pragma unroll
    for (int t = 0; t < 64; t++) o[t] = 0.f;
#pragma unroll
    for (int j = 0; j < CC; j++) {
        const float4* vp = (const float4*)(Vm + j*cstep + base);
        float aj = a[j];
#pragma unroll
        for (int t = 0; t < 16; t++) {
            float4 vv = vp[t];
            o[4*t+0] = fmaf(aj, vv.x, o[4*t+0]);
            o[4*t+1] = fmaf(aj, vv.y, o[4*t+1]);
            o[4*t+2] = fmaf(aj, vv.z, o[4*t+2]);
            o[4*t+3] = fmaf(aj, vv.w, o[4*t+3]);
        }
    }
    long ob = i*cstep + base;
#pragma unroll
    for (int t = 0; t < 64; t++) Oh[ob + t] = __float2half(o[t]);
}

// ---------------- fp32 -> fp16 (vectorized) ----------------
__global__ void tohalf_kernel(const float* __restrict__ in, __half* __restrict__ oh, int n4)
{
    int i = blockIdx.x * blockDim.x + threadIdx.x;
    if (i >= n4) return;
    float4 v = ((const float4*)in)[i];
    oh[4L*i + 0] = __float2half(v.x);
    oh[4L*i + 1] = __float2half(v.y);
    oh[4L*i + 2] = __float2half(v.z);
    oh[4L*i + 3] = __float2half(v.w);
}

// ---------------- concat -> fp16 ----------------
__global__ void comb_kernel(const float* __restrict__ cs, __half* __restrict__ oh)
{
    int gid = blockIdx.x * blockDim.x + threadIdx.x;
    int d4  = gid & (DD/4 - 1);
    int row = gid / (DD/4);
    int d = d4 * 4;
    int c = d >> 8;
    int e = d & 255;
    float4 v = *(const float4*)(cs + (long)c*BT*DC + (long)row*DC + e);
    oh[4L*gid + 0] = __float2half(v.x);
    oh[4L*gid + 1] = __float2half(v.y);
    oh[4L*gid + 2] = __float2half(v.z);
    oh[4L*gid + 3] = __float2half(v.w);
}

// ---------------- host side ----------------
static __half *Wh_p, *Wl_p;
#define HG2_SMEM (2*3*GPER*2)
#define HG1_SMEM (2*2*GPER*2)

static inline void hgemm(int mode, int nt, const __half* Ah, long boff,
                         float* C, __half* Coh,
                         int M, int N, int K, int accum, const float* bias, int batch,
                         long aBS, long bBS, long cBS, long biasBS)
{
    dim3 grid(N/BN, M/BM, batch);
    if (nt == 2) {
        if (mode == 0)
            hgemm_kernel<2,0><<<grid, 256, HG2_SMEM>>>(Ah, Wh_p + boff, Wl_p + boff,
                bias, C, nullptr, M, N, K, accum, aBS, bBS, cBS, biasBS,
                nullptr, nullptr, nullptr, nullptr, nullptr);
        else
            hgemm_kernel<2,2><<<grid, 256, HG2_SMEM>>>(Ah, Wh_p + boff, Wl_p + boff,
                bias, nullptr, Coh, M, N, K, accum, aBS, bBS, cBS, biasBS,
                nullptr, nullptr, nullptr, nullptr, nullptr);
    } else {
        hgemm_kernel<1,0><<<grid, 256, HG1_SMEM>>>(Ah, Wh_p + boff, nullptr,
            bias, C, nullptr, M, N, K, accum, aBS, bBS, cBS, biasBS,
            nullptr, nullptr, nullptr, nullptr, nullptr);
    }
}

// fused QKV: all-half (Hq/Hk/Hv) when Hq != null (single-term weights),
// else all-fp32 (Cq/Ck/Cv, 2-term weights, merge path)
static inline void hgemm_qkv(const __half* Ah, long boff,
                             float* Cq, float* Ck, float* Cv,
                             __half* Hq, __half* Hk, __half* Hv,
                             int M, int N, int K, int batch,
                             long aBS, long bBS, long cBS)
{
    dim3 grid(N/BN, M/BM, batch);
    if (Hq)
        hgemm_kernel<1,3><<<grid, 256, HG1_SMEM>>>(Ah, Wh_p + boff, nullptr,
            nullptr, nullptr, nullptr, M, N, K, 0, aBS, bBS, cBS, 0,
            nullptr, nullptr, Hq, Hk, Hv);
    else
        hgemm_kernel<2,3><<<grid, 256, HG2_SMEM>>>(Ah, Wh_p + boff, Wl_p + boff,
            nullptr, Cq, nullptr, M, N, K, 0, aBS, bBS, cBS, 0, Ck, Cv,
            nullptr, nullptr, nullptr);
}

static inline void splitT4(const float* a, const float* b, const float* c, const float* d,
                           long off, int K, int N, int perBatch, int ngroups, int interleave)
{
    splitT4_kernel<<<dim3(N/32, K/32, ngroups*perBatch), 256>>>(
        a, b, c, d, Wh_p + off, Wl_p + off, K, N, perBatch, ngroups, interleave);
}

extern "C" void kernel_launch(void* const* d_in, const int* in_sizes, int n_in,
                              void* d_out, int out_size)
{
    const int*   ids   = (const int*)d_in[0];
    const float* emb   = (const float*)d_in[1];
    const float* t_wq  = (const float*)d_in[2];
    const float* t_wk  = (const float*)d_in[3];
    const float* t_wv  = (const float*)d_in[4];
    const float* t_wo  = (const float*)d_in[5];
    const float* t_w1  = (const float*)d_in[6];
    const float* t_w2  = (const float*)d_in[7];
    const float* t_n1  = (const float*)d_in[8];
    const float* t_n2  = (const float*)d_in[9];
    const float* cin_w = (const float*)d_in[10];
    const float* cin_b = (const float*)d_in[11];
    const float* c_wq  = (const float*)d_in[12];
    const float* c_wk  = (const float*)d_in[13];
    const float* c_wv  = (const float*)d_in[14];
    const float* c_wo  = (const float*)d_in[15];
    const float* c_w1  = (const float*)d_in[16];
    const float* c_w2  = (const float*)d_in[17];
    const float* c_n1  = (const float*)d_in[18];
    const float* c_n2  = (const float*)d_in[19];
    const float* m_wq  = (const float*)d_in[20];
    const float* m_wk  = (const float*)d_in[21];
    const float* m_wv  = (const float*)d_in[22];
    const float* m_wo  = (const float*)d_in[23];
    const float* m_n   = (const float*)d_in[24];
    const float* oproj = (const float*)d_in[25];
    const float* fnorm = (const float*)d_in[26];
    float* out = (float*)d_out;

    void* p;
    cudaGetSymbolAddress(&p, g_X);   float*  X   = (float*)p;
    cudaGetSymbolAddress(&p, g_Q);   float*  Q   = (float*)p;
    cudaGetSymbolAddress(&p, g_K);   float*  Kb  = (float*)p;
    cudaGetSymbolAddress(&p, g_V);   float*  Vb  = (float*)p;
    cudaGetSymbolAddress(&p, g_CS);  float*  CS  = (float*)p;
    cudaGetSymbolAddress(&p, g_Hh);  __half* Hh  = (__half*)p;
    cudaGetSymbolAddress(&p, g_M1h); __half* M1h = (__half*)p;
    cudaGetSymbolAddress(&p, g_Oh);  __half* Oh  = (__half*)p;
    cudaGetSymbolAddress(&p, g_Qh);  __half* Qh  = (__half*)p;
    cudaGetSymbolAddress(&p, g_Kh);  __half* Kh  = (__half*)p;
    cudaGetSymbolAddress(&p, g_Vh);  __half* Vh  = (__half*)p;
    cudaGetSymbolAddress(&p, g_Wh);  Wh_p = (__half*)p;
    cudaGetSymbolAddress(&p, g_Wl);  Wl_p = (__half*)p;

    cudaFuncSetAttribute(hgemm_kernel<2,0>, cudaFuncAttributeMaxDynamicSharedMemorySize, HG2_SMEM);
    cudaFuncSetAttribute(hgemm_kernel<2,2>, cudaFuncAttributeMaxDynamicSharedMemorySize, HG2_SMEM);
    cudaFuncSetAttribute(hgemm_kernel<2,3>, cudaFuncAttributeMaxDynamicSharedMemorySize, HG2_SMEM);
    cudaFuncSetAttribute(hgemm_kernel<1,3>, cudaFuncAttributeMaxDynamicSharedMemorySize, HG1_SMEM);
    cudaFuncSetAttribute(hgemm_kernel<1,0>, cudaFuncAttributeMaxDynamicSharedMemorySize, HG1_SMEM);
    cudaFuncSetAttribute(fattn_kernel, cudaFuncAttributeMaxDynamicSharedMemorySize, FATTN_SMEM);

    // ---- weight conversion (batched; QKV interleaved per layer) ----
    splitT4(t_wq, t_wk, t_wv, nullptr, OT_QKV, DD, DD, LT, 3, 1);
    splitT4(t_wo, nullptr, nullptr, nullptr, OT_WO, DD, DD, LT, 1, 0);
    splitT4(t_w1, nullptr, nullptr, nullptr, OT_W1, DD, DFF, LT, 1, 0);
    splitT4(t_w2, nullptr, nullptr, nullptr, OT_W2, DFF, DD, LT, 1, 0);
    splitT4(cin_w, nullptr, nullptr, nullptr, OC_IN, DD, DC, CC, 1, 0);
    splitT4(c_wq, c_wk, c_wv, nullptr, OC_QKV, DC, DC, CC*LC, 3, 1);
    splitT4(c_wo, nullptr, nullptr, nullptr, OC_WO, DC, DC, CC*LC, 1, 0);
    splitT4(c_w1, nullptr, nullptr, nullptr, OC_W1, DC, DFFC, CC*LC, 1, 0);
    splitT4(c_w2, nullptr, nullptr, nullptr, OC_W2, DFFC, DC, CC*LC, 1, 0);
    splitT4(m_wq, m_wk, m_wv, nullptr, OM_QKV, DC, DC, NM, 3, 1);
    splitT4(m_wo, nullptr, nullptr, nullptr, OM_WO, DC, DC, NM, 1, 0);
    splitT4(oproj, nullptr, nullptr, nullptr, O_OP, DD, DD, 1, 1, 0);
    split1_kernel<<<(BV*DD/4 + 255)/256, 256>>>(emb, Wh_p + O_EMB, BV*DD/4);

    embed_kernel<<<BT, 256>>>(X, emb, ids);

    // ---- trunk ----
    for (int l = 0; l < LT; l++) {
        rms_kernel<<<BT, 256>>>(X, t_n1 + (long)l*DD, Hh, DD, BT, 0);
        hgemm_qkv(Hh, OT_QKV + (long)l*3*DD*DD, nullptr, nullptr, nullptr,
                  Qh, Kh, Vh, BT, 3*DD, DD, 1, 0, 0, 0);
        rope_kernel<<<(BT*HT*32)/256, 256>>>(Qh, Kh, TT, HT, DD, BT);
        fattn_kernel<<<dim3(TT/64, BB*HT, 1), 128, FATTN_SMEM>>>(
            Qh, Kh, Vh, Oh, TT, HT, DD, 0);
        hgemm(0, 2, Oh, OT_WO + (long)l*DD*DD, X, 0, BT, DD, DD, 1, nullptr, 1, 0,0,0,0);
        rms_kernel<<<BT, 256>>>(X, t_n2 + (long)l*DD, Hh, DD, BT, 0);
        hgemm(2, 2, Hh, OT_W1 + (long)l*DD*DFF, 0, M1h, BT, DFF, DD, 0, nullptr, 1, 0,0,0,0);
        hgemm(0, 2, M1h, OT_W2 + (long)l*DFF*DD, X, 0, BT, DD, DFF, 1, nullptr, 1, 0,0,0,0);
    }

    // ---- column projection ----
    tohalf_kernel<<<(BT*DD/4)/256, 256>>>(X, Hh, BT*DD/4);
    hgemm(0, 2, Hh, OC_IN, CS, 0, BT, DC, DD, 0, cin_b, CC, 0, (long)DD*DC, (long)BT*DC, DC);

    // ---- column layers ----
    for (int l = 0; l < LC; l++) {
        rms_kernel<<<CBT, 256>>>(CS, c_n1 + (long)l*DC, Hh, DC, BT, (long)LC*DC);
        hgemm_qkv(Hh, OC_QKV + (long)l*3*DC*DC, nullptr, nullptr, nullptr,
                  Qh, Kh, Vh, BT, 3*DC, DC, CC,
                  (long)BT*DC, (long)LC*3*DC*DC, (long)BT*DC);
        rope_kernel<<<(CBT*HC*32)/256, 256>>>(Qh, Kh, TT, HC, DC, CBT);
        fattn_kernel<<<dim3(TT/64, BB*HC, CC), 128, FATTN_SMEM>>>(
            Qh, Kh, Vh, Oh, TT, HC, DC, (long)BT*DC);
        hgemm(0, 2, Oh, OC_WO + (long)l*DC*DC, CS, 0, BT, DC, DC, 1, nullptr, CC,
              (long)BT*DC, (long)LC*DC*DC, (long)BT*DC, 0);
        rms_kernel<<<CBT, 256>>>(CS, c_n2 + (long)l*DC, Hh, DC, BT, (long)LC*DC);
        hgemm(2, 2, Hh, OC_W1 + (long)l*DC*DFFC, 0, M1h, BT, DFFC, DC, 0, nullptr, CC,
              (long)BT*DC, (long)LC*DC*DFFC, (long)BT*DFFC, 0);
        hgemm(0, 2, M1h, OC_W2 + (long)l*DFFC*DC, CS, 0, BT, DC, DFFC, 1, nullptr, CC,
              (long)BT*DFFC, (long)LC*DFFC*DC, (long)BT*DC, 0);

        if (((l + 1) & 1) == 0) {
            int m = (l + 1)/2 - 1;
            rms_kernel<<<CBT, 256>>>(CS, m_n + (long)m*DC, Hh, DC, CBT, 0);
            hgemm_qkv(Hh, OM_QKV + (long)m*3*DC*DC, Q, Kb, Vb,
                      nullptr, nullptr, nullptr, CBT, 3*DC, DC, 1, 0, 0, 0);
            merge_attn_kernel<<<(CC*BT*HC)/256, 256>>>(Q, Kb, Vb, Oh);
            hgemm(0, 2, Oh, OM_WO + (long)m*DC*DC, CS, 0, CBT, DC, DC, 1, nullptr, 1, 0,0,0,0);
        }
    }

    // ---- output head ----
    comb_kernel<<<(BT*DD/4)/256, 256>>>(CS, Hh);
    hgemm(0, 2, Hh, O_OP, Q, 0, BT, DD, DD, 0, nullptr, 1, 0,0,0,0);
    rms_kernel<<<BT, 256>>>(Q, fnorm, Hh, DD, BT, 0);
    hgemm(0, 1, Hh, O_EMB, out, 0, BT, BV, DD, 0, nullptr, 1, 0,0,0,0);
}

// round 17
// speedup vs baseline: 1.5177x; 1.0600x over previous
#include <cuda_runtime.h>
#include <cuda_fp16.h>
#include <math.h>
#include <stdint.h>

// ---------------- model constants ----------------
#define BV   32000
#define DD   1024
#define DFF  4096
#define LT   2
#define HT   16
#define CC   4
#define DC   256
#define DFFC 1024
#define LC   4
#define HC   4
#define NM   2
#define BB   2
#define TT   1024
#define BT   (BB*TT)     // 2048
#define CBT  (CC*BT)     // 8192

// ---------------- weight offsets ([N][K] fp16; QKV interleaved per layer) ----------------
constexpr long OT_QKV = 0;
constexpr long OT_WO  = OT_QKV + (long)LT*3*DD*DD;
constexpr long OT_W1  = OT_WO  + (long)LT*DD*DD;
constexpr long OT_W2  = OT_W1  + (long)LT*DD*DFF;
constexpr long OC_IN  = OT_W2  + (long)LT*DFF*DD;
constexpr long OC_QKV = OC_IN  + (long)CC*DD*DC;
constexpr long OC_WO  = OC_QKV + (long)CC*LC*3*DC*DC;
constexpr long OC_W1  = OC_WO  + (long)CC*LC*DC*DC;
constexpr long OC_W2  = OC_W1  + (long)CC*LC*DC*DFFC;
constexpr long OM_QKV = OC_W2  + (long)CC*LC*DFFC*DC;
constexpr long OM_WO  = OM_QKV + (long)NM*3*DC*DC;
constexpr long O_OP   = OM_WO  + (long)NM*DC*DC;
constexpr long O_EMB  = O_OP   + (long)DD*DD;
constexpr long WTOT   = O_EMB  + (long)BV*DD;

// ---------------- scratch (device globals) ----------------
__device__ float  g_X [BT*DD];
__device__ float  g_Q [BT*DD];
__device__ float  g_K [BT*DD];
__device__ float  g_V [BT*DD];
__device__ float  g_CS[CC*BT*DC];
__device__ __half g_Hh[BT*DD];
__device__ __half g_M1h[BT*DFF];
__device__ __half g_Oh[BT*DD];
__device__ __half g_Qh[BT*DD];
__device__ __half g_Kh[BT*DD];
__device__ __half g_Vh[BT*DD];
__device__ __half g_Wh[WTOT];
__device__ __half g_Wl[WTOT];

// ---------------- asm helpers ----------------
__device__ __forceinline__ void lm4(const __half* p, uint32_t* r)
{
    uint32_t a = (uint32_t)__cvta_generic_to_shared(p);
    asm volatile("ldmatrix.sync.aligned.m8n8.x4.shared.b16 {%0,%1,%2,%3}, [%4];"
        : "=r"(r[0]), "=r"(r[1]), "=r"(r[2]), "=r"(r[3]) : "r"(a));
}
__device__ __forceinline__ void lm4t(const __half* p, uint32_t* r)
{
    uint32_t a = (uint32_t)__cvta_generic_to_shared(p);
    asm volatile("ldmatrix.sync.aligned.m8n8.x4.trans.shared.b16 {%0,%1,%2,%3}, [%4];"
        : "=r"(r[0]), "=r"(r[1]), "=r"(r[2]), "=r"(r[3]) : "r"(a));
}
__device__ __forceinline__ void mma16816(float* c, const uint32_t* a, const uint32_t* b)
{
    asm volatile("mma.sync.aligned.m16n8k16.row.col.f32.f16.f16.f32 "
        "{%0,%1,%2,%3},{%4,%5,%6,%7},{%8,%9},{%0,%1,%2,%3};"
        : "+f"(c[0]), "+f"(c[1]), "+f"(c[2]), "+f"(c[3])
        : "r"(a[0]), "r"(a[1]), "r"(a[2]), "r"(a[3]), "r"(b[0]), "r"(b[1]));
}
__device__ __forceinline__ void cpasync16(const __half* dst, const __half* src)
{
    uint32_t d = (uint32_t)__cvta_generic_to_shared(dst);
    asm volatile("cp.async.cg.shared.global [%0], [%1], 16;" :: "r"(d), "l"(src));
}
__device__ __forceinline__ void cp_commit() { asm volatile("cp.async.commit_group;"); }
template<int N> __device__ __forceinline__ void cp_wait()
{ asm volatile("cp.async.wait_group %0;" :: "n"(N)); }

__device__ __forceinline__ float gelu1(float v)
{
    return 0.5f * v * (1.f + tanhf(0.7978845608028654f * (v + 0.044715f*v*v*v)));
}

// ---------------- HGEMM (cp.async double-buffered, champion mainloop) ----------------
// NT=2: A single fp16, B two-term (hh + h*lo) -> 2 MMA passes.  NT=1: plain.
// MODE 0: C fp32 (+accum+bias)  MODE 2: gelu + fp16-hi out
// MODE 3: fused QKV (N = 3*NW): if Hq != null -> all fp16 (Hq/Hk/Hv by sel),
//         else all fp32 (C/Ck/Cv by sel).
#define BM 128
#define BN 128
#define BKH 32
#define SSTR 40
#define GPER (BM*SSTR)

template<int NT, int MODE>
__global__ void __launch_bounds__(256) hgemm_kernel(
    const __half* __restrict__ Ah,
    const __half* __restrict__ Bh, const __half* __restrict__ Bl,
    const float* __restrict__ bias, float* __restrict__ C,
    __half* __restrict__ Coh,
    int M, int N, int K, int accum,
    long aBS, long bBS, long cBS, long biasBS,
    float* __restrict__ Ck, float* __restrict__ Cv,
    __half* __restrict__ Hq, __half* __restrict__ Hk, __half* __restrict__ Hv)
{
    extern __shared__ __half smp[];
    const int NARR = (NT == 2) ? 3 : 2;   // Ah, Bh, (Bl)

    Ah += blockIdx.z * aBS;
    Bh += blockIdx.z * bBS;
    if (MODE == 0) C += blockIdx.z * cBS;
    else if (MODE == 3) {
        if (Hq) { Hq += blockIdx.z * cBS; Hk += blockIdx.z * cBS; Hv += blockIdx.z * cBS; }
        else    { C += blockIdx.z * cBS; Ck += blockIdx.z * cBS; Cv += blockIdx.z * cBS; }
    } else { Coh += blockIdx.z * cBS; }
    if (NT == 2) Bl += blockIdx.z * bBS;
    if (bias) bias += blockIdx.z * biasBS;

    int row0 = blockIdx.y * BM;
    int col0 = blockIdx.x * BN;
    int tid  = threadIdx.x;
    int lane = tid & 31;
    int wid  = tid >> 5;
    int wm0  = (wid >> 2) * 64;
    int wn0  = (wid & 3) * 32;

    float acc[4][4][4];
#pragma unroll
    for (int mt = 0; mt < 4; mt++)
#pragma unroll
        for (int nt = 0; nt < 4; nt++)
#pragma unroll
            for (int q = 0; q < 4; q++) acc[mt][nt][q] = 0.f;

    int a_r  = lane & 15;
    int a_ko = (lane >> 4) << 3;
    int b_n  = ((lane >> 4) << 3) + (lane & 7);
    int b_ko = ((lane >> 3) & 1) << 3;

    int nk = K / BKH;

    auto loadStage = [&](int st, int k0) {
        __half* dAh = smp + st * NARR * GPER;
        __half* dBh = dAh + GPER;
        __half* dBl = dAh + 2 * GPER;
#pragma unroll
        for (int c = tid; c < 512; c += 256) {
            int r = c >> 2, o = (c & 3) << 3;
            cpasync16(&dAh[r*SSTR + o], &Ah[(long)(row0 + r)*K + k0 + o]);
            cpasync16(&dBh[r*SSTR + o], &Bh[(long)(col0 + r)*K + k0 + o]);
            if (NT == 2)
                cpasync16(&dBl[r*SSTR + o], &Bl[(long)(col0 + r)*K + k0 + o]);
        }
    };

    loadStage(0, 0);
    cp_commit();

    for (int kt = 0; kt < nk; kt++) {
        int cur = kt & 1;
        if (kt + 1 < nk) {
            loadStage(cur ^ 1, (kt + 1) * BKH);
            cp_commit();
            cp_wait<1>();
        } else {
            cp_wait<0>();
        }
        __syncthreads();

        const __half* pAh = smp + cur * NARR * GPER;
        const __half* pBh = pAh + GPER;
        const __half* pBl = pAh + 2 * GPER;

#pragma unroll
        for (int ks = 0; ks < BKH; ks += 16) {
            uint32_t a_hi[4][4], b_hi[2][4];
#pragma unroll
            for (int mt = 0; mt < 4; mt++)
                lm4(&pAh[(wm0 + mt*16 + a_r)*SSTR + ks + a_ko], a_hi[mt]);
#pragma unroll
            for (int np = 0; np < 2; np++)
                lm4(&pBh[(wn0 + np*16 + b_n)*SSTR + ks + b_ko], b_hi[np]);
#pragma unroll
            for (int mt = 0; mt < 4; mt++)
#pragma unroll
                for (int nt = 0; nt < 4; nt++)
                    mma16816(acc[mt][nt], a_hi[mt], &b_hi[nt >> 1][(nt & 1)*2]);

            if (NT == 2) {
                uint32_t b_lo[2][4];
#pragma unroll
                for (int np = 0; np < 2; np++)
                    lm4(&pBl[(wn0 + np*16 + b_n)*SSTR + ks + b_ko], b_lo[np]);
#pragma unroll
                for (int mt = 0; mt < 4; mt++)
#pragma unroll
                    for (int nt = 0; nt < 4; nt++)
                        mma16816(acc[mt][nt], a_hi[mt], &b_lo[nt >> 1][(nt & 1)*2]);
            }
        }
        __syncthreads();
    }

    int g = lane >> 2, t = lane & 3;

    if (MODE == 3) {
        const int NW = N / 3;
        int sel = col0 / NW;
        int colb = col0 - sel*NW;
        if (Hq) {
            __half* Hf = (sel == 0) ? Hq : (sel == 1) ? Hk : Hv;
#pragma unroll
            for (int mt = 0; mt < 4; mt++) {
#pragma unroll
                for (int nt = 0; nt < 4; nt++) {
                    int r1  = row0 + wm0 + mt*16 + g;
                    int cix = colb + wn0 + nt*8 + 2*t;
                    long o0 = (long)r1*NW + cix;
                    long o1 = (long)(r1 + 8)*NW + cix;
                    *(__half2*)&Hf[o0] = __halves2half2(
                        __float2half(acc[mt][nt][0]), __float2half(acc[mt][nt][1]));
                    *(__half2*)&Hf[o1] = __halves2half2(
                        __float2half(acc[mt][nt][2]), __float2half(acc[mt][nt][3]));
                }
            }
        } else {
            float* Cf = (sel == 0) ? C : (sel == 1) ? Ck : Cv;
#pragma unroll
            for (int mt = 0; mt < 4; mt++) {
#pragma unroll
                for (int nt = 0; nt < 4; nt++) {
                    int r1  = row0 + wm0 + mt*16 + g;
                    int cix = colb + wn0 + nt*8 + 2*t;
                    long o0 = (long)r1*NW + cix;
                    long o1 = (long)(r1 + 8)*NW + cix;
                    *(float2*)&Cf[o0] = make_float2(acc[mt][nt][0], acc[mt][nt][1]);
                    *(float2*)&Cf[o1] = make_float2(acc[mt][nt][2], acc[mt][nt][3]);
                }
            }
        }
        return;
    }

#pragma unroll
    for (int mt = 0; mt < 4; mt++) {
#pragma unroll
        for (int nt = 0; nt < 4; nt++) {
            int r1  = row0 + wm0 + mt*16 + g;
            int cix = col0 + wn0 + nt*8 + 2*t;
            float bv0 = 0.f, bv1 = 0.f;
            if (bias) { bv0 = bias[cix]; bv1 = bias[cix + 1]; }
            float v00 = acc[mt][nt][0] + bv0, v01 = acc[mt][nt][1] + bv1;
            float v10 = acc[mt][nt][2] + bv0, v11 = acc[mt][nt][3] + bv1;
            long o0 = (long)r1*N + cix;
            long o1 = (long)(r1 + 8)*N + cix;
            if (MODE == 0) {
                if (accum) {
                    float2 p0 = *(float2*)&C[o0];
                    float2 p1 = *(float2*)&C[o1];
                    v00 += p0.x; v01 += p0.y;
                    v10 += p1.x; v11 += p1.y;
                }
                *(float2*)&C[o0] = make_float2(v00, v01);
                *(float2*)&C[o1] = make_float2(v10, v11);
            } else {
                if (MODE == 2) {
                    v00 = gelu1(v00); v01 = gelu1(v01);
                    v10 = gelu1(v10); v11 = gelu1(v11);
                }
                *(__half2*)&Coh[o0] = __halves2half2(__float2half(v00), __float2half(v01));
                *(__half2*)&Coh[o1] = __halves2half2(__float2half(v10), __float2half(v11));
            }
        }
    }
}

// ---------------- tensor-core flash attention (causal, hd=64, single fp16) ----------------
#define ASTR 72
#define FATTN_SMEM (3*64*ASTR*2)

__global__ void __launch_bounds__(128) fattn_kernel(
    const __half* __restrict__ Qh,
    const __half* __restrict__ Kh,
    const __half* __restrict__ Vh,
    __half* __restrict__ Oh,
    int T, int nh, int rstride, long colstride)
{
    extern __shared__ __half sm[];
    __half* sQh = sm;
    __half* sKh = sQh + 64*ASTR;
    __half* sVh = sKh + 64*ASTR;

    int qt = blockIdx.x;
    int b  = blockIdx.y / nh;
    int h  = blockIdx.y % nh;
    long base = (long)blockIdx.z * colstride + (long)h * 64;
    int q0  = qt * 64;
    int tid = threadIdx.x;
    int lane = tid & 31;
    int wid  = tid >> 5;
    int wrow = wid * 16;
    int g = lane >> 2, t4 = lane & 3;

#pragma unroll
    for (int c = tid; c < 512; c += 128) {
        int r = c >> 3, o = (c & 7) << 3;
        long src = base + (long)(b*T + q0 + r)*rstride + o;
        *(uint4*)&sQh[r*ASTR + o] = *(const uint4*)&Qh[src];
    }
    __syncthreads();

    int a_r  = lane & 15;
    int a_ko = (lane >> 4) << 3;
    int b_n  = ((lane >> 4) << 3) + (lane & 7);
    int b_ko = ((lane >> 3) & 1) << 3;
    int v_r  = (((lane >> 3) & 1) << 3) + (lane & 7);
    int v_c  = (lane >> 4) << 3;

    uint32_t qfh[4][4];
#pragma unroll
    for (int ks = 0; ks < 4; ks++)
        lm4(&sQh[(wrow + a_r)*ASTR + ks*16 + a_ko], qfh[ks]);

    float mrow[2] = {-1e30f, -1e30f};
    float lrow[2] = {0.f, 0.f};
    float oacc[8][4];
#pragma unroll
    for (int nt = 0; nt < 8; nt++)
#pragma unroll
        for (int e = 0; e < 4; e++) oacc[nt][e] = 0.f;

    for (int kt = 0; kt <= qt; kt++) {
        int k0 = kt * 64;
        __syncthreads();
#pragma unroll
        for (int c = tid; c < 512; c += 128) {
            int r = c >> 3, o = (c & 7) << 3;
            long src = base + (long)(b*T + k0 + r)*rstride + o;
            *(uint4*)&sKh[r*ASTR + o] = *(const uint4*)&Kh[src];
            *(uint4*)&sVh[r*ASTR + o] = *(const uint4*)&Vh[src];
        }
        __syncthreads();

        float S[8][4];
#pragma unroll
        for (int nt = 0; nt < 8; nt++)
#pragma unroll
            for (int e = 0; e < 4; e++) S[nt][e] = 0.f;

#pragma unroll
        for (int ks = 0; ks < 4; ks++) {
            uint32_t bh[4][4];
#pragma unroll
            for (int np = 0; np < 4; np++)
                lm4(&sKh[(np*16 + b_n)*ASTR + ks*16 + b_ko], bh[np]);
#pragma unroll
            for (int np = 0; np < 4; np++)
#pragma unroll
                for (int j = 0; j < 2; j++)
                    mma16816(S[np*2 + j], qfh[ks], &bh[np][j*2]);
        }

#pragma unroll
        for (int nt = 0; nt < 8; nt++)
#pragma unroll
            for (int e = 0; e < 4; e++) {
                S[nt][e] *= 0.125f;
                if (kt == qt) {
                    int col = k0 + nt*8 + t4*2 + (e & 1);
                    int row = q0 + wrow + g + ((e >> 1) << 3);
                    if (col > row) S[nt][e] = -1e30f;
                }
            }

        float P[8][4];
#pragma unroll
        for (int r = 0; r < 2; r++) {
            float mx = -1e30f;
#pragma unroll
            for (int nt = 0; nt < 8; nt++) {
                mx = fmaxf(mx, S[nt][2*r + 0]);
                mx = fmaxf(mx, S[nt][2*r + 1]);
            }
            mx = fmaxf(mx, __shfl_xor_sync(0xffffffffu, mx, 1));
            mx = fmaxf(mx, __shfl_xor_sync(0xffffffffu, mx, 2));
            float mnew  = fmaxf(mrow[r], mx);
            float alpha = __expf(mrow[r] - mnew);
            float rsum = 0.f;
#pragma unroll
            for (int nt = 0; nt < 8; nt++) {
                float p0 = __expf(S[nt][2*r + 0] - mnew);
                float p1 = __expf(S[nt][2*r + 1] - mnew);
                P[nt][2*r + 0] = p0; P[nt][2*r + 1] = p1;
                rsum += p0 + p1;
            }
            rsum += __shfl_xor_sync(0xffffffffu, rsum, 1);
            rsum += __shfl_xor_sync(0xffffffffu, rsum, 2);
            lrow[r] = lrow[r]*alpha + rsum;
            mrow[r] = mnew;
#pragma unroll
            for (int nt = 0; nt < 8; nt++) {
                oacc[nt][2*r + 0] *= alpha;
                oacc[nt][2*r + 1] *= alpha;
            }
        }

        uint32_t pah[4][4];
#pragma unroll
        for (int ks = 0; ks < 4; ks++) {
            int j0 = 2*ks, j1 = 2*ks + 1;
#pragma unroll
            for (int q = 0; q < 4; q++) {
                int jj = (q < 2) ? j0 : j1;
                int e0 = (q & 1) ? 2 : 0;
                __half h0 = __float2half(P[jj][e0]);
                __half h1 = __float2half(P[jj][e0 + 1]);
                pah[ks][q] = (uint32_t)__half_as_ushort(h0) |
                             ((uint32_t)__half_as_ushort(h1) << 16);
            }
        }

#pragma unroll
        for (int ks = 0; ks < 4; ks++) {
            uint32_t vh[4][4];
#pragma unroll
            for (int np = 0; np < 4; np++)
                lm4t(&sVh[(ks*16 + v_r)*ASTR + np*16 + v_c], vh[np]);
#pragma unroll
            for (int np = 0; np < 4; np++)
#pragma unroll
                for (int j = 0; j < 2; j++)
                    mma16816(oacc[np*2 + j], pah[ks], &vh[np][j*2]);
        }
    }

#pragma unroll
    for (int r = 0; r < 2; r++) {
        float inv = 1.f / lrow[r];
        int row = q0 + wrow + g + r*8;
        long ob = base + (long)(b*T + row)*rstride;
#pragma unroll
        for (int nt = 0; nt < 8; nt++) {
            float v0 = oacc[nt][2*r + 0] * inv;
            float v1 = oacc[nt][2*r + 1] * inv;
            int col = nt*8 + t4*2;
            *(__half2*)&Oh[ob + col] = __halves2half2(__float2half(v0), __float2half(v1));
        }
    }
}

// ---------------- weight transpose + fp16 split ----------------
__global__ void splitT4_kernel(const float* p0, const float* p1,
                               const float* p2, const float* p3,
                               __half* __restrict__ oh, __half* __restrict__ ol,
                               int K, int N, int perBatch, int ngroups, int interleave)
{
    __shared__ float tile[32][33];
    const float* ps[4] = {p0, p1, p2, p3};
    int gsel = blockIdx.z / perBatch;
    int bz   = blockIdx.z % perBatch;
    const float* in = ps[gsel] + (long)bz * K * N;
    long ob = (interleave ? (long)(bz*ngroups + gsel) : (long)blockIdx.z) * K * N;
    int n0 = blockIdx.x * 32, k0 = blockIdx.y * 32;
    int tx = threadIdx.x & 31, ty = threadIdx.x >> 5;
#pragma unroll
    for (int j = 0; j < 4; j++) {
        int r = ty*4 + j;
        tile[r][tx] = in[(long)(k0 + r)*N + n0 + tx];
    }
    __syncthreads();
#pragma unroll
    for (int j = 0; j < 4; j++) {
        int nn = ty*4 + j;
        float v = tile[tx][nn];
        __half h = __float2half(v);
        long o = ob + (long)(n0 + nn)*K + k0 + tx;
        oh[o] = h;
        ol[o] = __float2half(v - __half2float(h));
    }
}

__global__ void split1_kernel(const float* __restrict__ in, __half* __restrict__ oh, int n4)
{
    int i = blockIdx.x * blockDim.x + threadIdx.x;
    if (i >= n4) return;
    float4 v = ((const float4*)in)[i];
    oh[4*i + 0] = __float2half(v.x);
    oh[4*i + 1] = __float2half(v.y);
    oh[4*i + 2] = __float2half(v.z);
    oh[4*i + 3] = __float2half(v.w);
}

// ---------------- rmsnorm -> fp16 hi ----------------
__global__ void rms_kernel(const float* __restrict__ x, const float* __restrict__ w,
                           __half* __restrict__ oh,
                           int W, int rowsPerChunk, long wStride)
{
    int row = blockIdx.x;
    const float* xr = x + (long)row * W;
    const float* wr = w + (long)(row / rowsPerChunk) * wStride;
    float ss = 0.f;
    for (int i = threadIdx.x; i < W; i += 256) {
        float v = xr[i];
        ss += v * v;
    }
    __shared__ float red[8];
#pragma unroll
    for (int off = 16; off > 0; off >>= 1)
        ss += __shfl_xor_sync(0xffffffffu, ss, off);
    if ((threadIdx.x & 31) == 0) red[threadIdx.x >> 5] = ss;
    __syncthreads();
    float tot = red[0]+red[1]+red[2]+red[3]+red[4]+red[5]+red[6]+red[7];
    float inv = rsqrtf(tot / (float)W + 1e-6f);
    long rb = (long)row * W;
    for (int i = threadIdx.x; i < W; i += 256)
        oh[rb + i] = __float2half(xr[i] * inv * wr[i]);
}

// ---------------- rope: in-place rotate on fp16 q,k ----------------
__global__ void rope_kernel(__half* __restrict__ qh, __half* __restrict__ kh,
                            int T, int nh, int rstride, int nrows)
{
    int idx = blockIdx.x * blockDim.x + threadIdx.x;
    if (idx >= nrows * nh * 32) return;
    int i   = idx & 31;
    int h   = (idx >> 5) % nh;
    int row = idx / (32 * nh);
    int t   = row % T;
    float inv = __expf(-(float)(2*i) * (1.f/64.f) * 9.210340371976184f);
    float f = (float)t * inv;
    float s, c;
    sincosf(f, &s, &c);
    long bo = (long)row * rstride + h*64 + i;
    float q1 = __half2float(qh[bo]), q2 = __half2float(qh[bo + 32]);
    qh[bo]      = __float2half(q1*c - q2*s);
    qh[bo + 32] = __float2half(q2*c + q1*s);
    float k1 = __half2float(kh[bo]), k2 = __half2float(kh[bo + 32]);
    kh[bo]      = __float2half(k1*c - k2*s);
    kh[bo + 32] = __float2half(k2*c + k1*s);
}

// ---------------- embedding gather ----------------
__global__ void embed_kernel(float* __restrict__ X, const float* __restrict__ emb,
                             const int* __restrict__ ids)
{
    int row = blockIdx.x;
    int id  = ids[row];
    const float4* src = (const float4*)(emb + (long)id * DD);
    float4* dst = (float4*)(X + (long)row * DD);
    dst[threadIdx.x] = src[threadIdx.x];
}

// ---------------- cross-column merge attention (fp32 in, fp16 out) ----------------
__global__ void merge_attn_kernel(const float* __restrict__ Qm, const float* __restrict__ Km,
                                  const float* __restrict__ Vm,
                                  __half* __restrict__ Oh)
{
    int gid = blockIdx.x * blockDim.x + threadIdx.x;
    int h   = gid & 3;
    int row = (gid >> 2) & (BT - 1);
    int i   = gid >> 13;
    if (i >= CC) return;
    long base  = (long)row * DC + h*64;
    long cstep = (long)BT * DC;

    float4 q[16];
    const float4* qp = (const float4*)(Qm + i*cstep + base);
#pragma unroll
    for (int t = 0; t < 16; t++) q[t] = qp[t];

    float s[CC];
#pragma unroll
    for (int j = 0; j < CC; j++) {
        const float4* kp = (const float4*)(Km + j*cstep + base);
        float acc = 0.f;
#pragma unroll
        for (int t = 0; t < 16; t++) {
            float4 kv = kp[t];
            acc += q[t].x*kv.x + q[t].y*kv.y + q[t].z*kv.z + q[t].w*kv.w;
        }
        s[j] = acc * 0.125f;
    }
    float mm = fmaxf(fmaxf(s[0], s[1]), fmaxf(s[2], s[3]));
    float a[CC], sum = 0.f;
#pragma unroll
    for (int j = 0; j < CC; j++) { a[j] = __expf(s[j] - mm); sum += a[j]; }
    float isum = 1.f / sum;
#pragma unroll
    for (int j = 0; j < CC; j++) a[j] *= isum;

    float o[64];
#pragma unroll
    for (int t = 0; t < 64; t++) o[t] = 0.f;
#pragma unroll
    for (int j = 0; j < CC; j++) {
        const float4* vp = (const float4*)(Vm + j*cstep + base);
        float aj = a[j];
#pragma unroll
        for (int t = 0; t < 16; t++) {
            float4 vv = vp[t];
            o[4*t+0] = fmaf(aj, vv.x, o[4*t+0]);
            o[4*t+1] = fmaf(aj, vv.y, o[4*t+1]);
            o[4*t+2] = fmaf(aj, vv.z, o[4*t+2]);
            o[4*t+3] = fmaf(aj, vv.w, o[4*t+3]);
        }
    }
    long ob = i*cstep + base;
#pragma unroll
    for (int t = 0; t < 64; t++) Oh[ob + t] = __float2half(o[t]);
}

// ---------------- fp32 -> fp16 (vectorized) ----------------
__global__ void tohalf_kernel(const float* __restrict__ in, __half* __restrict__ oh, int n4)
{
    int i = blockIdx.x * blockDim.x + threadIdx.x;
    if (i >= n4) return;
    float4 v = ((const float4*)in)[i];
    oh[4L*i + 0] = __float2half(v.x);
    oh[4L*i + 1] = __float2half(v.y);
    oh[4L*i + 2] = __float2half(v.z);
    oh[4L*i + 3] = __float2half(v.w);
}

// ---------------- concat -> fp16 ----------------
__global__ void comb_kernel(const float* __restrict__ cs, __half* __restrict__ oh)
{
    int gid = blockIdx.x * blockDim.x + threadIdx.x;
    int d4  = gid & (DD/4 - 1);
    int row = gid / (DD/4);
    int d = d4 * 4;
    int c = d >> 8;
    int e = d & 255;
    float4 v = *(const float4*)(cs + (long)c*BT*DC + (long)row*DC + e);
    oh[4L*gid + 0] = __float2half(v.x);
    oh[4L*gid + 1] = __float2half(v.y);
    oh[4L*gid + 2] = __float2half(v.z);
    oh[4L*gid + 3] = __float2half(v.w);
}

// ---------------- host side ----------------
static __half *Wh_p, *Wl_p;
#define HG2_SMEM (2*3*GPER*2)
#define HG1_SMEM (2*2*GPER*2)

static inline void hgemm(int mode, int nt, const __half* Ah, long boff,
                         float* C, __half* Coh,
                         int M, int N, int K, int accum, const float* bias, int batch,
                         long aBS, long bBS, long cBS, long biasBS)
{
    dim3 grid(N/BN, M/BM, batch);
    if (nt == 2) {
        if (mode == 0)
            hgemm_kernel<2,0><<<grid, 256, HG2_SMEM>>>(Ah, Wh_p + boff, Wl_p + boff,
                bias, C, nullptr, M, N, K, accum, aBS, bBS, cBS, biasBS,
                nullptr, nullptr, nullptr, nullptr, nullptr);
        else
            hgemm_kernel<2,2><<<grid, 256, HG2_SMEM>>>(Ah, Wh_p + boff, Wl_p + boff,
                bias, nullptr, Coh, M, N, K, accum, aBS, bBS, cBS, biasBS,
                nullptr, nullptr, nullptr, nullptr, nullptr);
    } else {
        if (mode == 0)
            hgemm_kernel<1,0><<<grid, 256, HG1_SMEM>>>(Ah, Wh_p + boff, nullptr,
                bias, C, nullptr, M, N, K, accum, aBS, bBS, cBS, biasBS,
                nullptr, nullptr, nullptr, nullptr, nullptr);
        else
            hgemm_kernel<1,2><<<grid, 256, HG1_SMEM>>>(Ah, Wh_p + boff, nullptr,
                bias, nullptr, Coh, M, N, K, accum, aBS, bBS, cBS, biasBS,
                nullptr, nullptr, nullptr, nullptr, nullptr);
    }
}

// fused QKV: all-half (Hq/Hk/Hv) when Hq != null (single-term weights),
// else all-fp32 (Cq/Ck/Cv, 2-term weights, merge path)
static inline void hgemm_qkv(const __half* Ah, long boff,
                             float* Cq, float* Ck, float* Cv,
                             __half* Hq, __half* Hk, __half* Hv,
                             int M, int N, int K, int batch,
                             long aBS, long bBS, long cBS)
{
    dim3 grid(N/BN, M/BM, batch);
    if (Hq)
        hgemm_kernel<1,3><<<grid, 256, HG1_SMEM>>>(Ah, Wh_p + boff, nullptr,
            nullptr, nullptr, nullptr, M, N, K, 0, aBS, bBS, cBS, 0,
            nullptr, nullptr, Hq, Hk, Hv);
    else
        hgemm_kernel<2,3><<<grid, 256, HG2_SMEM>>>(Ah, Wh_p + boff, Wl_p + boff,
            nullptr, Cq, nullptr, M, N, K, 0, aBS, bBS, cBS, 0, Ck, Cv,
            nullptr, nullptr, nullptr);
}

static inline void splitT4(const float* a, const float* b, const float* c, const float* d,
                           long off, int K, int N, int perBatch, int ngroups, int interleave)
{
    splitT4_kernel<<<dim3(N/32, K/32, ngroups*perBatch), 256>>>(
        a, b, c, d, Wh_p + off, Wl_p + off, K, N, perBatch, ngroups, interleave);
}

extern "C" void kernel_launch(void* const* d_in, const int* in_sizes, int n_in,
                              void* d_out, int out_size)
{
    const int*   ids   = (const int*)d_in[0];
    const float* emb   = (const float*)d_in[1];
    const float* t_wq  = (const float*)d_in[2];
    const float* t_wk  = (const float*)d_in[3];
    const float* t_wv  = (const float*)d_in[4];
    const float* t_wo  = (const float*)d_in[5];
    const float* t_w1  = (const float*)d_in[6];
    const float* t_w2  = (const float*)d_in[7];
    const float* t_n1  = (const float*)d_in[8];
    const float* t_n2  = (const float*)d_in[9];
    const float* cin_w = (const float*)d_in[10];
    const float* cin_b = (const float*)d_in[11];
    const float* c_wq  = (const float*)d_in[12];
    const float* c_wk  = (const float*)d_in[13];
    const float* c_wv  = (const float*)d_in[14];
    const float* c_wo  = (const float*)d_in[15];
    const float* c_w1  = (const float*)d_in[16];
    const float* c_w2  = (const float*)d_in[17];
    const float* c_n1  = (const float*)d_in[18];
    const float* c_n2  = (const float*)d_in[19];
    const float* m_wq  = (const float*)d_in[20];
    const float* m_wk  = (const float*)d_in[21];
    const float* m_wv  = (const float*)d_in[22];
    const float* m_wo  = (const float*)d_in[23];
    const float* m_n   = (const float*)d_in[24];
    const float* oproj = (const float*)d_in[25];
    const float* fnorm = (const float*)d_in[26];
    float* out = (float*)d_out;

    void* p;
    cudaGetSymbolAddress(&p, g_X);   float*  X   = (float*)p;
    cudaGetSymbolAddress(&p, g_Q);   float*  Q   = (float*)p;
    cudaGetSymbolAddress(&p, g_K);   float*  Kb  = (float*)p;
    cudaGetSymbolAddress(&p, g_V);   float*  Vb  = (float*)p;
    cudaGetSymbolAddress(&p, g_CS);  float*  CS  = (float*)p;
    cudaGetSymbolAddress(&p, g_Hh);  __half* Hh  = (__half*)p;
    cudaGetSymbolAddress(&p, g_M1h); __half* M1h = (__half*)p;
    cudaGetSymbolAddress(&p, g_Oh);  __half* Oh  = (__half*)p;
    cudaGetSymbolAddress(&p, g_Qh);  __half* Qh  = (__half*)p;
    cudaGetSymbolAddress(&p, g_Kh);  __half* Kh  = (__half*)p;
    cudaGetSymbolAddress(&p, g_Vh);  __half* Vh  = (__half*)p;
    cudaGetSymbolAddress(&p, g_Wh);  Wh_p = (__half*)p;
    cudaGetSymbolAddress(&p, g_Wl);  Wl_p = (__half*)p;

    cudaFuncSetAttribute(hgemm_kernel<2,0>, cudaFuncAttributeMaxDynamicSharedMemorySize, HG2_SMEM);
    cudaFuncSetAttribute(hgemm_kernel<2,2>, cudaFuncAttributeMaxDynamicSharedMemorySize, HG2_SMEM);
    cudaFuncSetAttribute(hgemm_kernel<2,3>, cudaFuncAttributeMaxDynamicSharedMemorySize, HG2_SMEM);
    cudaFuncSetAttribute(hgemm_kernel<1,3>, cudaFuncAttributeMaxDynamicSharedMemorySize, HG1_SMEM);
    cudaFuncSetAttribute(hgemm_kernel<1,2>, cudaFuncAttributeMaxDynamicSharedMemorySize, HG1_SMEM);
    cudaFuncSetAttribute(hgemm_kernel<1,0>, cudaFuncAttributeMaxDynamicSharedMemorySize, HG1_SMEM);
    cudaFuncSetAttribute(fattn_kernel, cudaFuncAttributeMaxDynamicSharedMemorySize, FATTN_SMEM);

    // ---- weight conversion (batched; QKV interleaved per layer) ----
    splitT4(t_wq, t_wk, t_wv, nullptr, OT_QKV, DD, DD, LT, 3, 1);
    splitT4(t_wo, nullptr, nullptr, nullptr, OT_WO, DD, DD, LT, 1, 0);
    splitT4(t_w1, nullptr, nullptr, nullptr, OT_W1, DD, DFF, LT, 1, 0);
    splitT4(t_w2, nullptr, nullptr, nullptr, OT_W2, DFF, DD, LT, 1, 0);
    splitT4(cin_w, nullptr, nullptr, nullptr, OC_IN, DD, DC, CC, 1, 0);
    splitT4(c_wq, c_wk, c_wv, nullptr, OC_QKV, DC, DC, CC*LC, 3, 1);
    splitT4(c_wo, nullptr, nullptr, nullptr, OC_WO, DC, DC, CC*LC, 1, 0);
    splitT4(c_w1, nullptr, nullptr, nullptr, OC_W1, DC, DFFC, CC*LC, 1, 0);
    splitT4(c_w2, nullptr, nullptr, nullptr, OC_W2, DFFC, DC, CC*LC, 1, 0);
    splitT4(m_wq, m_wk, m_wv, nullptr, OM_QKV, DC, DC, NM, 3, 1);
    splitT4(m_wo, nullptr, nullptr, nullptr, OM_WO, DC, DC, NM, 1, 0);
    splitT4(oproj, nullptr, nullptr, nullptr, O_OP, DD, DD, 1, 1, 0);
    split1_kernel<<<(BV*DD/4 + 255)/256, 256>>>(emb, Wh_p + O_EMB, BV*DD/4);

    embed_kernel<<<BT, 256>>>(X, emb, ids);

    // ---- trunk ----
    for (int l = 0; l < LT; l++) {
        rms_kernel<<<BT, 256>>>(X, t_n1 + (long)l*DD, Hh, DD, BT, 0);
        hgemm_qkv(Hh, OT_QKV + (long)l*3*DD*DD, nullptr, nullptr, nullptr,
                  Qh, Kh, Vh, BT, 3*DD, DD, 1, 0, 0, 0);
        rope_kernel<<<(BT*HT*32)/256, 256>>>(Qh, Kh, TT, HT, DD, BT);
        fattn_kernel<<<dim3(TT/64, BB*HT, 1), 128, FATTN_SMEM>>>(
            Qh, Kh, Vh, Oh, TT, HT, DD, 0);
        hgemm(0, 2, Oh, OT_WO + (long)l*DD*DD, X, 0, BT, DD, DD, 1, nullptr, 1, 0,0,0,0);
        rms_kernel<<<BT, 256>>>(X, t_n2 + (long)l*DD, Hh, DD, BT, 0);
        hgemm(2, 1, Hh, OT_W1 + (long)l*DD*DFF, 0, M1h, BT, DFF, DD, 0, nullptr, 1, 0,0,0,0);
        hgemm(0, 2, M1h, OT_W2 + (long)l*DFF*DD, X, 0, BT, DD, DFF, 1, nullptr, 1, 0,0,0,0);
    }

    // ---- column projection ----
    tohalf_kernel<<<(BT*DD/4)/256, 256>>>(X, Hh, BT*DD/4);
    hgemm(0, 2, Hh, OC_IN, CS, 0, BT, DC, DD, 0, cin_b, CC, 0, (long)DD*DC, (long)BT*DC, DC);

    // ---- column layers ----
    for (int l = 0; l < LC; l++) {
        rms_kernel<<<CBT, 256>>>(CS, c_n1 + (long)l*DC, Hh, DC, BT, (long)LC*DC);
        hgemm_qkv(Hh, OC_QKV + (long)l*3*DC*DC, nullptr, nullptr, nullptr,
                  Qh, Kh, Vh, BT, 3*DC, DC, CC,
                  (long)BT*DC, (long)LC*3*DC*DC, (long)BT*DC);
        rope_kernel<<<(CBT*HC*32)/256, 256>>>(Qh, Kh, TT, HC, DC, CBT);
        fattn_kernel<<<dim3(TT/64, BB*HC, CC), 128, FATTN_SMEM>>>(
            Qh, Kh, Vh, Oh, TT, HC, DC, (long)BT*DC);
        hgemm(0, 2, Oh, OC_WO + (long)l*DC*DC, CS, 0, BT, DC, DC, 1, nullptr, CC,
              (long)BT*DC, (long)LC*DC*DC, (long)BT*DC, 0);
        rms_kernel<<<CBT, 256>>>(CS, c_n2 + (long)l*DC, Hh, DC, BT, (long)LC*DC);
        hgemm(2, 1, Hh, OC_W1 + (long)l*DC*DFFC, 0, M1h, BT, DFFC, DC, 0, nullptr, CC,
              (long)BT*DC, (long)LC*DC*DFFC, (long)BT*DFFC, 0);
        hgemm(0, 2, M1h, OC_W2 + (long)l*DFFC*DC, CS, 0, BT, DC, DFFC, 1, nullptr, CC,
              (long)BT*DFFC, (long)LC*DFFC*DC, (long)BT*DC, 0);

        if (((l + 1) & 1) == 0) {
            int m = (l + 1)/2 - 1;
            rms_kernel<<<CBT, 256>>>(CS, m_n + (long)m*DC, Hh, DC, CBT, 0);
            hgemm_qkv(Hh, OM_QKV + (long)m*3*DC*DC, Q, Kb, Vb,
                      nullptr, nullptr, nullptr, CBT, 3*DC, DC, 1, 0, 0, 0);
            merge_attn_kernel<<<(CC*BT*HC)/256, 256>>>(Q, Kb, Vb, Oh);
            hgemm(0, 2, Oh, OM_WO + (long)m*DC*DC, CS, 0, CBT, DC, DC, 1, nullptr, 1, 0,0,0,0);
        }
    }

    // ---- output head ----
    comb_kernel<<<(BT*DD/4)/256, 256>>>(CS, Hh);
    hgemm(0, 2, Hh, O_OP, Q, 0, BT, DD, DD, 0, nullptr, 1, 0,0,0,0);
    rms_kernel<<<BT, 256>>>(Q, fnorm, Hh, DD, BT, 0);
    hgemm(0, 1, Hh, O_EMB, out, 0, BT, BV, DD, 0, nullptr, 1, 0,0,0,0);
}